// round 6
// baseline (speedup 1.0000x reference)
#include <cuda_runtime.h>
#include <cstdint>
#include <math.h>

#define S_LEN   2048
#define BATCH   2
#define DMODEL  1024
#define NHEADS  16
#define DHEAD   64
#define MROWS   (BATCH * S_LEN)   // 4096
#define IGNORE_VAL (-100000.0f)

// ---------------- scratch (no allocations allowed) ----------------
__device__ float g_q[MROWS * DMODEL];
__device__ float g_k[MROWS * DMODEL];
__device__ float g_v[MROWS * DMODEL];
__device__ float g_z[MROWS * DMODEL];

// ---------------- helpers ----------------
__device__ __forceinline__ uint32_t smem_u32(const void* p) {
    uint32_t a;
    asm("{ .reg .u64 t; cvta.to.shared.u64 t, %1; cvt.u32.u64 %0, t; }" : "=r"(a) : "l"(p));
    return a;
}
__device__ __forceinline__ uint32_t f2tf32(float f) {
    uint32_t r;
    asm("cvt.rna.tf32.f32 %0, %1;" : "=r"(r) : "f"(f));
    return r;
}
__device__ __forceinline__ void cp_async16(uint32_t dst, const void* src) {
    asm volatile("cp.async.ca.shared.global [%0], [%1], 16;" :: "r"(dst), "l"(src));
}
__device__ __forceinline__ void cp_async4(uint32_t dst, const void* src) {
    asm volatile("cp.async.ca.shared.global [%0], [%1], 4;" :: "r"(dst), "l"(src));
}
__device__ __forceinline__ void cp_commit() {
    asm volatile("cp.async.commit_group;" ::: "memory");
}
template <int N>
__device__ __forceinline__ void cp_wait() {
    asm volatile("cp.async.wait_group %0;" :: "n"(N) : "memory");
}

__device__ __forceinline__ void mma_tf32_16x8x8(
    float* d, const uint32_t* a, const uint32_t* b, const float* c)
{
    asm volatile(
        "mma.sync.aligned.m16n8k8.row.col.f32.tf32.tf32.f32 "
        "{%0,%1,%2,%3}, {%4,%5,%6,%7}, {%8,%9}, {%10,%11,%12,%13};\n"
        : "=f"(d[0]), "=f"(d[1]), "=f"(d[2]), "=f"(d[3])
        : "r"(a[0]), "r"(a[1]), "r"(a[2]), "r"(a[3]),
          "r"(b[0]), "r"(b[1]),
          "f"(c[0]), "f"(c[1]), "f"(c[2]), "f"(c[3]));
}

// ============ double-buffered tf32 mma GEMM core ============
// C[M,N] = A[4096,1024] x Bop[N,K]^T + bias[N]
// mode 0: W [H,K,D]; Bop[n][k] = W[n>>6][k][n&63]
// mode 1: W [K,N];   Bop[n][k] = W[k*DMODEL + n]
#define KC   32
#define TS   36
#define GEMM_SMEM (512 * TS * 4)   // 2 x (A 128xTS) + 2 x (B 128xTS) floats

__device__ __forceinline__ void gemm_core(
    const float* __restrict__ A, const float* __restrict__ W,
    const float* __restrict__ bias, float* __restrict__ C, int mode,
    float* sm, int n0, int m0)
{
    float* AsF0 = sm;
    float* AsF1 = sm + 128 * TS;
    float* BsF0 = sm + 256 * TS;
    float* BsF1 = sm + 384 * TS;
    const uint32_t sA[2] = { smem_u32(AsF0), smem_u32(AsF1) };
    const uint32_t sB[2] = { smem_u32(BsF0), smem_u32(BsF1) };
    float* const AsF[2] = { AsF0, AsF1 };
    float* const BsF[2] = { BsF0, BsF1 };

    const int tid = threadIdx.x;
    const int wid = tid >> 5;
    const int lid = tid & 31;
    const int g   = lid >> 2;
    const int tig = lid & 3;
    const int wm  = wid >> 2;
    const int wn  = wid & 3;

    const int ng    = n0 + (tid & 127);
    const int khalf = (tid >> 7) * 16;

    float acc[4][4][4];
#pragma unroll
    for (int i = 0; i < 4; i++)
#pragma unroll
        for (int j = 0; j < 4; j++)
#pragma unroll
            for (int f = 0; f < 4; f++) acc[i][j][f] = 0.0f;

    // ---- async chunk loader ----
    auto load_chunk = [&](int c, int buf) {
        const int k0 = c * KC;
#pragma unroll
        for (int it = 0; it < 4; it++) {
            int i = tid + it * 256;
            int row = i >> 3, j = i & 7;
            cp_async16(sA[buf] + (uint32_t)(row * TS + j * 4) * 4,
                       A + (size_t)(m0 + row) * DMODEL + k0 + j * 4);
        }
        if (mode == 0) {
            const float* wb = W + (size_t)(ng >> 6) * (DMODEL * DHEAD) + (ng & 63);
#pragma unroll
            for (int k = 0; k < 16; k++) {
                cp_async4(sB[buf] + (uint32_t)((tid & 127) * TS + khalf + k) * 4,
                          wb + (size_t)(k0 + khalf + k) * DHEAD);
            }
        } else {
            const float* wb = W + ng;
#pragma unroll
            for (int k = 0; k < 16; k++) {
                cp_async4(sB[buf] + (uint32_t)((tid & 127) * TS + khalf + k) * 4,
                          wb + (size_t)(k0 + khalf + k) * DMODEL);
            }
        }
        cp_commit();
    };

    load_chunk(0, 0);

    const int NCH = DMODEL / KC;    // 32
    for (int c = 0; c < NCH; c++) {
        if (c + 1 < NCH) {
            load_chunk(c + 1, (c + 1) & 1);
            cp_wait<1>();
        } else {
            cp_wait<0>();
        }
        __syncthreads();

        const float* As_ = AsF[c & 1];
        const float* Bs_ = BsF[c & 1];
#pragma unroll
        for (int kk = 0; kk < KC; kk += 8) {
            uint32_t af[4][4];
            uint32_t bf[4][2];
#pragma unroll
            for (int mi = 0; mi < 4; mi++) {
                int r = wm * 64 + mi * 16 + g;
                af[mi][0] = f2tf32(As_[r * TS + kk + tig]);
                af[mi][1] = f2tf32(As_[(r + 8) * TS + kk + tig]);
                af[mi][2] = f2tf32(As_[r * TS + kk + tig + 4]);
                af[mi][3] = f2tf32(As_[(r + 8) * TS + kk + tig + 4]);
            }
#pragma unroll
            for (int nj = 0; nj < 4; nj++) {
                int n = wn * 32 + nj * 8 + g;
                bf[nj][0] = f2tf32(Bs_[n * TS + kk + tig]);
                bf[nj][1] = f2tf32(Bs_[n * TS + kk + tig + 4]);
            }
#pragma unroll
            for (int mi = 0; mi < 4; mi++)
#pragma unroll
                for (int nj = 0; nj < 4; nj++)
                    mma_tf32_16x8x8(acc[mi][nj], af[mi], bf[nj], acc[mi][nj]);
        }
        __syncthreads();   // reads done before chunk c+2 overwrites this buffer
    }

#pragma unroll
    for (int mi = 0; mi < 4; mi++) {
        int r0 = m0 + wm * 64 + mi * 16 + g;
#pragma unroll
        for (int nj = 0; nj < 4; nj++) {
            int c0 = n0 + wn * 32 + nj * 8 + tig * 2;
            float b0 = bias[c0], b1 = bias[c0 + 1];
            *(float2*)(C + (size_t)r0 * DMODEL + c0) =
                make_float2(acc[mi][nj][0] + b0, acc[mi][nj][1] + b1);
            *(float2*)(C + (size_t)(r0 + 8) * DMODEL + c0) =
                make_float2(acc[mi][nj][2] + b0, acc[mi][nj][3] + b1);
        }
    }
}

// fused QKV projection: grid (8, 32, 3)
__global__ __launch_bounds__(256, 2) void qkv_gemm(
    const float* __restrict__ xq, const float* __restrict__ xk, const float* __restrict__ xv,
    const float* __restrict__ wq, const float* __restrict__ wk, const float* __restrict__ wv,
    const float* __restrict__ bq, const float* __restrict__ bk, const float* __restrict__ bv,
    float* __restrict__ cq, float* __restrict__ ck, float* __restrict__ cv)
{
    extern __shared__ float smg[];
    const float* A = (blockIdx.z == 0) ? xq : (blockIdx.z == 1) ? xk : xv;
    const float* W = (blockIdx.z == 0) ? wq : (blockIdx.z == 1) ? wk : wv;
    const float* B = (blockIdx.z == 0) ? bq : (blockIdx.z == 1) ? bk : bv;
    float*       C = (blockIdx.z == 0) ? cq : (blockIdx.z == 1) ? ck : cv;
    gemm_core(A, W, B, C, 0, smg, blockIdx.x * 128, blockIdx.y * 128);
}

// output projection: grid (8, 32)
__global__ __launch_bounds__(256, 2) void wo_gemm(
    const float* __restrict__ A, const float* __restrict__ W,
    const float* __restrict__ bias, float* __restrict__ C)
{
    extern __shared__ float smg[];
    gemm_core(A, W, bias, C, 1, smg, blockIdx.x * 128, blockIdx.y * 128);
}

// ============ flash attention with mma.sync tf32 ============
// CTA: 128 q rows x one (h, b). 8 warps; warp w owns rows [w*16, w*16+16).
// smem: Q[0,128) | K[128,192) | P[192,320) | V[320,384), stride FS words.
#define FS 68

__global__ __launch_bounds__(256) void flash_attn_mma(
    const float* __restrict__ q, const float* __restrict__ k,
    const float* __restrict__ v, const float* __restrict__ amask,
    float* __restrict__ z)
{
    extern __shared__ uint32_t sm[];
    uint32_t* Qs = sm;                  // 128 x FS
    uint32_t* Ks = sm + 128 * FS;       // 64 x FS
    uint32_t* Ps = sm + 192 * FS;       // 128 x FS
    uint32_t* Vs = sm + 320 * FS;       // 64 x FS

    const int qt = (int)(gridDim.x - 1 - blockIdx.x);   // longest CTAs first
    const int h  = blockIdx.y;
    const int b  = blockIdx.z;
    const int tid = threadIdx.x;
    const int wid = tid >> 5;
    const int lid = tid & 31;
    const int g   = lid >> 2;
    const int tig = lid & 3;
    const int r0  = wid * 16;

    const size_t base = (size_t)b * S_LEN;
    const float* qp = q + (base + qt * 128) * DMODEL + h * 64;

#pragma unroll
    for (int it = 0; it < 8; it++) {
        int i = tid + it * 256;
        int row = i >> 4;
        int j = i & 15;
        float4 val = *(const float4*)(qp + (size_t)row * DMODEL + j * 4);
        uint32_t* d = Qs + row * FS + j * 4;
        d[0] = f2tf32(val.x); d[1] = f2tf32(val.y);
        d[2] = f2tf32(val.z); d[3] = f2tf32(val.w);
    }

    float o[8][4];
#pragma unroll
    for (int nj = 0; nj < 8; nj++)
#pragma unroll
        for (int f = 0; f < 4; f++) o[nj][f] = 0.0f;
    float mrow0 = -1e30f, mrow1 = -1e30f;
    float lrow0 = 0.0f,  lrow1 = 0.0f;

    const int qi0 = qt * 128 + r0 + g;
    const int qi1 = qi0 + 8;
    const int nkt = 2 * (qt + 1);

    for (int kt = 0; kt < nkt; kt++) {
        __syncthreads();   // prior PV reads of Vs complete before overwrite
        const float* kp = k + (base + kt * 64) * DMODEL + h * 64;
        const float* vp = v + (base + kt * 64) * DMODEL + h * 64;
#pragma unroll
        for (int it = 0; it < 4; it++) {
            int i = tid + it * 256;
            int row = i >> 4;
            int j = i & 15;
            float4 kv = *(const float4*)(kp + (size_t)row * DMODEL + j * 4);
            uint32_t* dk = Ks + row * FS + j * 4;
            dk[0] = f2tf32(kv.x); dk[1] = f2tf32(kv.y);
            dk[2] = f2tf32(kv.z); dk[3] = f2tf32(kv.w);
            float4 vv = *(const float4*)(vp + (size_t)row * DMODEL + j * 4);
            uint32_t* dv = Vs + row * FS + j * 4;
            dv[0] = f2tf32(vv.x); dv[1] = f2tf32(vv.y);
            dv[2] = f2tf32(vv.z); dv[3] = f2tf32(vv.w);
        }
        __syncthreads();

        // ---- S = Q K^T ----
        float sacc[8][4];
#pragma unroll
        for (int nj = 0; nj < 8; nj++)
#pragma unroll
            for (int f = 0; f < 4; f++) sacc[nj][f] = 0.0f;

#pragma unroll
        for (int kk = 0; kk < 64; kk += 8) {
            uint32_t a[4];
            a[0] = Qs[(r0 + g) * FS + kk + tig];
            a[1] = Qs[(r0 + g + 8) * FS + kk + tig];
            a[2] = Qs[(r0 + g) * FS + kk + tig + 4];
            a[3] = Qs[(r0 + g + 8) * FS + kk + tig + 4];
#pragma unroll
            for (int nj = 0; nj < 8; nj++) {
                uint32_t bb[2];
                bb[0] = Ks[(nj * 8 + g) * FS + kk + tig];
                bb[1] = Ks[(nj * 8 + g) * FS + kk + tig + 4];
                mma_tf32_16x8x8(sacc[nj], a, bb, sacc[nj]);
            }
        }

        // ---- scale, causal mask, additive mask ----
        float tmax0 = -1e30f, tmax1 = -1e30f;
#pragma unroll
        for (int nj = 0; nj < 8; nj++) {
            int kj = kt * 64 + nj * 8 + tig * 2;
            float am0 = amask[b * S_LEN + kj];
            float am1 = amask[b * S_LEN + kj + 1];
            float s0 = ((kj     <= qi0) ? sacc[nj][0] * 0.125f : IGNORE_VAL) + am0;
            float s1 = ((kj + 1 <= qi0) ? sacc[nj][1] * 0.125f : IGNORE_VAL) + am1;
            float s2 = ((kj     <= qi1) ? sacc[nj][2] * 0.125f : IGNORE_VAL) + am0;
            float s3 = ((kj + 1 <= qi1) ? sacc[nj][3] * 0.125f : IGNORE_VAL) + am1;
            sacc[nj][0] = s0; sacc[nj][1] = s1; sacc[nj][2] = s2; sacc[nj][3] = s3;
            tmax0 = fmaxf(tmax0, fmaxf(s0, s1));
            tmax1 = fmaxf(tmax1, fmaxf(s2, s3));
        }
        tmax0 = fmaxf(tmax0, __shfl_xor_sync(0xffffffffu, tmax0, 1));
        tmax0 = fmaxf(tmax0, __shfl_xor_sync(0xffffffffu, tmax0, 2));
        tmax1 = fmaxf(tmax1, __shfl_xor_sync(0xffffffffu, tmax1, 1));
        tmax1 = fmaxf(tmax1, __shfl_xor_sync(0xffffffffu, tmax1, 2));

        float mn0 = fmaxf(mrow0, tmax0);
        float mn1 = fmaxf(mrow1, tmax1);
        float alpha0 = __expf(mrow0 - mn0);
        float alpha1 = __expf(mrow1 - mn1);
        mrow0 = mn0; mrow1 = mn1;

        float rs0 = 0.0f, rs1 = 0.0f;
#pragma unroll
        for (int nj = 0; nj < 8; nj++) {
            float p0 = __expf(sacc[nj][0] - mn0);
            float p1 = __expf(sacc[nj][1] - mn0);
            float p2 = __expf(sacc[nj][2] - mn1);
            float p3 = __expf(sacc[nj][3] - mn1);
            sacc[nj][0] = p0; sacc[nj][1] = p1; sacc[nj][2] = p2; sacc[nj][3] = p3;
            rs0 += p0 + p1;
            rs1 += p2 + p3;
        }
        rs0 += __shfl_xor_sync(0xffffffffu, rs0, 1);
        rs0 += __shfl_xor_sync(0xffffffffu, rs0, 2);
        rs1 += __shfl_xor_sync(0xffffffffu, rs1, 1);
        rs1 += __shfl_xor_sync(0xffffffffu, rs1, 2);
        lrow0 = lrow0 * alpha0 + rs0;
        lrow1 = lrow1 * alpha1 + rs1;

#pragma unroll
        for (int nj = 0; nj < 8; nj++) {
            o[nj][0] *= alpha0; o[nj][1] *= alpha0;
            o[nj][2] *= alpha1; o[nj][3] *= alpha1;
        }

        // ---- stage P into its own region (warp-private rows) ----
#pragma unroll
        for (int nj = 0; nj < 8; nj++) {
            int col = nj * 8 + tig * 2;
            Ps[(r0 + g) * FS + col]     = f2tf32(sacc[nj][0]);
            Ps[(r0 + g) * FS + col + 1] = f2tf32(sacc[nj][1]);
            Ps[(r0 + g + 8) * FS + col]     = f2tf32(sacc[nj][2]);
            Ps[(r0 + g + 8) * FS + col + 1] = f2tf32(sacc[nj][3]);
        }
        __syncwarp();

        // ---- O += P V ----
#pragma unroll
        for (int kk = 0; kk < 64; kk += 8) {
            uint32_t a[4];
            a[0] = Ps[(r0 + g) * FS + kk + tig];
            a[1] = Ps[(r0 + g + 8) * FS + kk + tig];
            a[2] = Ps[(r0 + g) * FS + kk + tig + 4];
            a[3] = Ps[(r0 + g + 8) * FS + kk + tig + 4];
#pragma unroll
            for (int nj = 0; nj < 8; nj++) {
                uint32_t bb[2];
                bb[0] = Vs[(kk + tig) * FS + nj * 8 + g];
                bb[1] = Vs[(kk + tig + 4) * FS + nj * 8 + g];
                mma_tf32_16x8x8(o[nj], a, bb, o[nj]);
            }
        }
    }

    // ---- epilogue ----
    float inv0 = 1.0f / lrow0;
    float inv1 = 1.0f / lrow1;
    const size_t row0 = base + qt * 128 + r0 + g;
#pragma unroll
    for (int nj = 0; nj < 8; nj++) {
        int col = h * 64 + nj * 8 + tig * 2;
        *(float2*)(z + row0 * DMODEL + col) =
            make_float2(o[nj][0] * inv0, o[nj][1] * inv0);
        *(float2*)(z + (row0 + 8) * DMODEL + col) =
            make_float2(o[nj][2] * inv1, o[nj][3] * inv1);
    }
}

// ---------------- launch ----------------
extern "C" void kernel_launch(void* const* d_in, const int* in_sizes, int n_in,
                              void* d_out, int out_size)
{
    const float* x_q  = (const float*)d_in[0];
    const float* x_k  = (const float*)d_in[1];
    const float* x_v  = (const float*)d_in[2];
    const float* amsk = (const float*)d_in[3];
    const float* w_q  = (const float*)d_in[4];
    const float* w_k  = (const float*)d_in[5];
    const float* w_v  = (const float*)d_in[6];
    const float* w_o  = (const float*)d_in[7];
    const float* b_q  = (const float*)d_in[8];
    const float* b_k  = (const float*)d_in[9];
    const float* b_v  = (const float*)d_in[10];
    const float* b_o  = (const float*)d_in[11];
    float* out = (float*)d_out;

    float *gq, *gk, *gv, *gz;
    cudaGetSymbolAddress((void**)&gq, g_q);
    cudaGetSymbolAddress((void**)&gk, g_k);
    cudaGetSymbolAddress((void**)&gv, g_v);
    cudaGetSymbolAddress((void**)&gz, g_z);

    int fl_smem = 384 * FS * sizeof(uint32_t);   // 104,448 B
    cudaFuncSetAttribute(flash_attn_mma, cudaFuncAttributeMaxDynamicSharedMemorySize, fl_smem);
    cudaFuncSetAttribute(qkv_gemm, cudaFuncAttributeMaxDynamicSharedMemorySize, GEMM_SMEM);
    cudaFuncSetAttribute(wo_gemm, cudaFuncAttributeMaxDynamicSharedMemorySize, GEMM_SMEM);

    dim3 qgrid(DMODEL / 128, MROWS / 128, 3);
    qkv_gemm<<<qgrid, 256, GEMM_SMEM>>>(x_q, x_k, x_v, w_q, w_k, w_v,
                                        b_q, b_k, b_v, gq, gk, gv);

    dim3 fgrid(S_LEN / 128, NHEADS, BATCH);
    flash_attn_mma<<<fgrid, 256, fl_smem>>>(gq, gk, gv, amsk, gz);

    dim3 ogrid(DMODEL / 128, MROWS / 128);
    wo_gemm<<<ogrid, 256, GEMM_SMEM>>>(gz, w_o, b_o, out);

    (void)in_sizes; (void)n_in; (void)out_size;
}

// round 7
// speedup vs baseline: 1.3816x; 1.3816x over previous
#include <cuda_runtime.h>
#include <cuda_fp16.h>
#include <cstdint>
#include <math.h>

#define S_LEN   2048
#define BATCH   2
#define DMODEL  1024
#define NHEADS  16
#define DHEAD   64
#define MROWS   (BATCH * S_LEN)   // 4096
#define IGNORE_VAL (-100000.0f)

// ---------------- scratch ----------------
__device__ float g_q[MROWS * DMODEL];
__device__ float g_k[MROWS * DMODEL];
__device__ float g_v[MROWS * DMODEL];
__device__ float g_z[MROWS * DMODEL];

// ---------------- helpers ----------------
__device__ __forceinline__ uint32_t h2u(__half2 h) {
    return *reinterpret_cast<uint32_t*>(&h);
}
__device__ __forceinline__ uint32_t pack_h2(float a, float b) {
    __half2 h = __float22half2_rn(make_float2(a, b));
    return h2u(h);
}

__device__ __forceinline__ void mma_f16_16x8x16(
    float* d, const uint32_t* a, const uint32_t* b, const float* c)
{
    asm volatile(
        "mma.sync.aligned.m16n8k16.row.col.f32.f16.f16.f32 "
        "{%0,%1,%2,%3}, {%4,%5,%6,%7}, {%8,%9}, {%10,%11,%12,%13};\n"
        : "=f"(d[0]), "=f"(d[1]), "=f"(d[2]), "=f"(d[3])
        : "r"(a[0]), "r"(a[1]), "r"(a[2]), "r"(a[3]),
          "r"(b[0]), "r"(b[1]),
          "f"(c[0]), "f"(c[1]), "f"(c[2]), "f"(c[3]));
}

// ============ fp16 mma GEMM: C[M,N] = A[M,K] x Bop[N,K]^T + bias[N] ============
// mode 0: W [H=16,K=1024,D=64]; Bop[n][k] = W[n>>6][k][n&63]
// mode 1: W [K,N] row-major;    Bop[n][k] = W[k*DMODEL + n]
// CTA tile 128x128, 8 warps (2m x 4n), warp tile 64x32, k-chunk 64.
// smem rows: 64 halfs = 32 words data, stride TSg=36 words.
#define KCg  64
#define TSg  36

__device__ __forceinline__ void gemm_core(
    const float* __restrict__ A, const float* __restrict__ W,
    const float* __restrict__ bias, float* __restrict__ C, int mode,
    uint32_t* As, uint32_t* Bs, int n0, int m0)
{
    const int tid = threadIdx.x;
    const int wid = tid >> 5;
    const int lid = tid & 31;
    const int g   = lid >> 2;
    const int tig = lid & 3;
    const int wm  = wid >> 2;     // 0..1
    const int wn  = wid & 3;      // 0..3

    float acc[4][4][4];
#pragma unroll
    for (int i = 0; i < 4; i++)
#pragma unroll
        for (int j = 0; j < 4; j++)
#pragma unroll
            for (int f = 0; f < 4; f++) acc[i][j][f] = 0.0f;

    const int nl  = tid & 127;            // local n row for B gather
    const int ng  = n0 + nl;
    const int kg  = (tid >> 7) * 32;      // k sub-range base (0 or 32)

    const int NCH = DMODEL / KCg;         // 16
    for (int c = 0; c < NCH; c++) {
        const int k0 = c * KCg;
        __syncthreads();
        // ---- A tile: 128 rows x 64 f32 -> half2 ----
#pragma unroll
        for (int it = 0; it < 8; it++) {
            int i = tid + it * 256;       // 0..2047 over 128x16 float4
            int row = i >> 4;
            int j = i & 15;
            float4 v = *(const float4*)(A + (size_t)(m0 + row) * DMODEL + k0 + j * 4);
            As[row * TSg + j * 2 + 0] = pack_h2(v.x, v.y);
            As[row * TSg + j * 2 + 1] = pack_h2(v.z, v.w);
        }
        // ---- B tile: 128 n-rows x 64 k -> half2 (coalesced across n) ----
        if (mode == 0) {
            const float* wb = W + (size_t)(ng >> 6) * (DMODEL * DHEAD) + (ng & 63);
#pragma unroll
            for (int kp = 0; kp < 16; kp++) {
                int k = kg + kp * 2;
                float w0 = wb[(size_t)(k0 + k) * DHEAD];
                float w1 = wb[(size_t)(k0 + k + 1) * DHEAD];
                Bs[nl * TSg + (kg >> 1) + kp] = pack_h2(w0, w1);
            }
        } else {
            const float* wb = W + ng;
#pragma unroll
            for (int kp = 0; kp < 16; kp++) {
                int k = kg + kp * 2;
                float w0 = wb[(size_t)(k0 + k) * DMODEL];
                float w1 = wb[(size_t)(k0 + k + 1) * DMODEL];
                Bs[nl * TSg + (kg >> 1) + kp] = pack_h2(w0, w1);
            }
        }
        __syncthreads();

        // ---- compute: 4 k16-steps ----
#pragma unroll
        for (int kk = 0; kk < 4; kk++) {
            uint32_t af[4][4], bf[4][2];
#pragma unroll
            for (int mi = 0; mi < 4; mi++) {
                int r = wm * 64 + mi * 16 + g;
                af[mi][0] = As[r * TSg + kk * 8 + tig];
                af[mi][1] = As[(r + 8) * TSg + kk * 8 + tig];
                af[mi][2] = As[r * TSg + kk * 8 + tig + 4];
                af[mi][3] = As[(r + 8) * TSg + kk * 8 + tig + 4];
            }
#pragma unroll
            for (int nj = 0; nj < 4; nj++) {
                int n = wn * 32 + nj * 8 + g;
                bf[nj][0] = Bs[n * TSg + kk * 8 + tig];
                bf[nj][1] = Bs[n * TSg + kk * 8 + tig + 4];
            }
#pragma unroll
            for (int mi = 0; mi < 4; mi++)
#pragma unroll
                for (int nj = 0; nj < 4; nj++)
                    mma_f16_16x8x16(acc[mi][nj], af[mi], bf[nj], acc[mi][nj]);
        }
    }

#pragma unroll
    for (int mi = 0; mi < 4; mi++) {
        int r0 = m0 + wm * 64 + mi * 16 + g;
#pragma unroll
        for (int nj = 0; nj < 4; nj++) {
            int c0 = n0 + wn * 32 + nj * 8 + tig * 2;
            float b0 = bias[c0], b1 = bias[c0 + 1];
            *(float2*)(C + (size_t)r0 * DMODEL + c0) =
                make_float2(acc[mi][nj][0] + b0, acc[mi][nj][1] + b1);
            *(float2*)(C + (size_t)(r0 + 8) * DMODEL + c0) =
                make_float2(acc[mi][nj][2] + b0, acc[mi][nj][3] + b1);
        }
    }
}

__global__ __launch_bounds__(256) void qkv_gemm(
    const float* __restrict__ xq, const float* __restrict__ xk, const float* __restrict__ xv,
    const float* __restrict__ wq, const float* __restrict__ wk, const float* __restrict__ wv,
    const float* __restrict__ bq, const float* __restrict__ bk, const float* __restrict__ bv,
    float* __restrict__ cq, float* __restrict__ ck, float* __restrict__ cv)
{
    __shared__ uint32_t As[128 * TSg];
    __shared__ uint32_t Bs[128 * TSg];
    const float* A = (blockIdx.z == 0) ? xq : (blockIdx.z == 1) ? xk : xv;
    const float* W = (blockIdx.z == 0) ? wq : (blockIdx.z == 1) ? wk : wv;
    const float* B = (blockIdx.z == 0) ? bq : (blockIdx.z == 1) ? bk : bv;
    float*       C = (blockIdx.z == 0) ? cq : (blockIdx.z == 1) ? ck : cv;
    gemm_core(A, W, B, C, 0, As, Bs, blockIdx.x * 128, blockIdx.y * 128);
}

__global__ __launch_bounds__(256) void wo_gemm(
    const float* __restrict__ A, const float* __restrict__ W,
    const float* __restrict__ bias, float* __restrict__ C)
{
    __shared__ uint32_t As[128 * TSg];
    __shared__ uint32_t Bs[128 * TSg];
    gemm_core(A, W, bias, C, 1, As, Bs, blockIdx.x * 128, blockIdx.y * 128);
}

// ============ flash attention, fp16 mma ============
// CTA: 128 q rows x (h, b). 8 warps, warp w owns rows [16w, 16w+16).
// smem (uint32 words, stride FSH=36): Q[0,128) | K[128,192) | P[192,320) | Vt[320,384)
// Vt holds V transposed: Vt[d][kpos] as half2 over kpos pairs.
#define FSH 36

__global__ __launch_bounds__(256) void flash_attn_h(
    const float* __restrict__ q, const float* __restrict__ k,
    const float* __restrict__ v, const float* __restrict__ amask,
    float* __restrict__ z)
{
    extern __shared__ uint32_t sm[];
    uint32_t* Qs = sm;                   // 128 x FSH
    uint32_t* Ks = sm + 128 * FSH;       // 64 x FSH
    uint32_t* Ps = sm + 192 * FSH;       // 128 x FSH
    uint32_t* Vt = sm + 320 * FSH;       // 64 x FSH

    const int qt = (int)(gridDim.x - 1 - blockIdx.x);   // longest first
    const int h  = blockIdx.y;
    const int b  = blockIdx.z;
    const int tid = threadIdx.x;
    const int wid = tid >> 5;
    const int lid = tid & 31;
    const int g   = lid >> 2;
    const int tig = lid & 3;
    const int r0  = wid * 16;

    const size_t base = (size_t)b * S_LEN;
    const float* qp = q + (base + qt * 128) * DMODEL + h * 64;

    // Q tile: 128 x 64 f32 -> half2
#pragma unroll
    for (int it = 0; it < 8; it++) {
        int i = tid + it * 256;
        int row = i >> 4;
        int j = i & 15;
        float4 val = *(const float4*)(qp + (size_t)row * DMODEL + j * 4);
        Qs[row * FSH + j * 2 + 0] = pack_h2(val.x, val.y);
        Qs[row * FSH + j * 2 + 1] = pack_h2(val.z, val.w);
    }

    float o[8][4];
#pragma unroll
    for (int nj = 0; nj < 8; nj++)
#pragma unroll
        for (int f = 0; f < 4; f++) o[nj][f] = 0.0f;
    float mrow0 = -1e30f, mrow1 = -1e30f;
    float lrow0 = 0.0f,  lrow1 = 0.0f;

    const int qi0 = qt * 128 + r0 + g;
    const int qi1 = qi0 + 8;
    const int nkt = 2 * (qt + 1);

    // V-transpose loader indices
    const int vp_pair = tid & 31;        // kpos pair 0..31
    const int vdq     = tid >> 5;        // d-octet 0..7

    for (int kt = 0; kt < nkt; kt++) {
        __syncthreads();   // prior S reads of K and PV reads of Vt done
        const float* kp = k + (base + kt * 64) * DMODEL + h * 64;
        const float* vp = v + (base + kt * 64) * DMODEL + h * 64;
        // K tile 64x64 -> half2 (coalesced)
#pragma unroll
        for (int it = 0; it < 4; it++) {
            int i = tid + it * 256;
            int row = i >> 4;
            int j = i & 15;
            float4 kv = *(const float4*)(kp + (size_t)row * DMODEL + j * 4);
            Ks[row * FSH + j * 2 + 0] = pack_h2(kv.x, kv.y);
            Ks[row * FSH + j * 2 + 1] = pack_h2(kv.z, kv.w);
        }
        // V transposed: thread handles kpos rows {2p, 2p+1}, d cols [8dq, 8dq+8)
        {
            const float* va = vp + (size_t)(2 * vp_pair) * DMODEL + vdq * 8;
            const float* vb = va + DMODEL;
            float4 a0 = *(const float4*)(va);
            float4 a1 = *(const float4*)(va + 4);
            float4 b0 = *(const float4*)(vb);
            float4 b1 = *(const float4*)(vb + 4);
            int dbase = vdq * 8;
            Vt[(dbase + 0) * FSH + vp_pair] = pack_h2(a0.x, b0.x);
            Vt[(dbase + 1) * FSH + vp_pair] = pack_h2(a0.y, b0.y);
            Vt[(dbase + 2) * FSH + vp_pair] = pack_h2(a0.z, b0.z);
            Vt[(dbase + 3) * FSH + vp_pair] = pack_h2(a0.w, b0.w);
            Vt[(dbase + 4) * FSH + vp_pair] = pack_h2(a1.x, b1.x);
            Vt[(dbase + 5) * FSH + vp_pair] = pack_h2(a1.y, b1.y);
            Vt[(dbase + 6) * FSH + vp_pair] = pack_h2(a1.z, b1.z);
            Vt[(dbase + 7) * FSH + vp_pair] = pack_h2(a1.w, b1.w);
        }
        __syncthreads();

        // ---- S = Q K^T : 4 k16-steps ----
        float sacc[8][4];
#pragma unroll
        for (int nj = 0; nj < 8; nj++)
#pragma unroll
            for (int f = 0; f < 4; f++) sacc[nj][f] = 0.0f;

#pragma unroll
        for (int kk = 0; kk < 4; kk++) {
            uint32_t a[4];
            a[0] = Qs[(r0 + g) * FSH + kk * 8 + tig];
            a[1] = Qs[(r0 + g + 8) * FSH + kk * 8 + tig];
            a[2] = Qs[(r0 + g) * FSH + kk * 8 + tig + 4];
            a[3] = Qs[(r0 + g + 8) * FSH + kk * 8 + tig + 4];
#pragma unroll
            for (int nj = 0; nj < 8; nj++) {
                uint32_t bb[2];
                bb[0] = Ks[(nj * 8 + g) * FSH + kk * 8 + tig];
                bb[1] = Ks[(nj * 8 + g) * FSH + kk * 8 + tig + 4];
                mma_f16_16x8x16(sacc[nj], a, bb, sacc[nj]);
            }
        }

        // ---- scale, causal, additive mask ----
        float tmax0 = -1e30f, tmax1 = -1e30f;
#pragma unroll
        for (int nj = 0; nj < 8; nj++) {
            int kj = kt * 64 + nj * 8 + tig * 2;
            float am0 = amask[b * S_LEN + kj];
            float am1 = amask[b * S_LEN + kj + 1];
            float s0 = ((kj     <= qi0) ? sacc[nj][0] * 0.125f : IGNORE_VAL) + am0;
            float s1 = ((kj + 1 <= qi0) ? sacc[nj][1] * 0.125f : IGNORE_VAL) + am1;
            float s2 = ((kj     <= qi1) ? sacc[nj][2] * 0.125f : IGNORE_VAL) + am0;
            float s3 = ((kj + 1 <= qi1) ? sacc[nj][3] * 0.125f : IGNORE_VAL) + am1;
            sacc[nj][0] = s0; sacc[nj][1] = s1; sacc[nj][2] = s2; sacc[nj][3] = s3;
            tmax0 = fmaxf(tmax0, fmaxf(s0, s1));
            tmax1 = fmaxf(tmax1, fmaxf(s2, s3));
        }
        tmax0 = fmaxf(tmax0, __shfl_xor_sync(0xffffffffu, tmax0, 1));
        tmax0 = fmaxf(tmax0, __shfl_xor_sync(0xffffffffu, tmax0, 2));
        tmax1 = fmaxf(tmax1, __shfl_xor_sync(0xffffffffu, tmax1, 1));
        tmax1 = fmaxf(tmax1, __shfl_xor_sync(0xffffffffu, tmax1, 2));

        float mn0 = fmaxf(mrow0, tmax0);
        float mn1 = fmaxf(mrow1, tmax1);
        float alpha0 = __expf(mrow0 - mn0);
        float alpha1 = __expf(mrow1 - mn1);
        mrow0 = mn0; mrow1 = mn1;

        float rs0 = 0.0f, rs1 = 0.0f;
#pragma unroll
        for (int nj = 0; nj < 8; nj++) {
            float p0 = __expf(sacc[nj][0] - mn0);
            float p1 = __expf(sacc[nj][1] - mn0);
            float p2 = __expf(sacc[nj][2] - mn1);
            float p3 = __expf(sacc[nj][3] - mn1);
            sacc[nj][0] = p0; sacc[nj][1] = p1; sacc[nj][2] = p2; sacc[nj][3] = p3;
            rs0 += p0 + p1;
            rs1 += p2 + p3;
        }
        rs0 += __shfl_xor_sync(0xffffffffu, rs0, 1);
        rs0 += __shfl_xor_sync(0xffffffffu, rs0, 2);
        rs1 += __shfl_xor_sync(0xffffffffu, rs1, 1);
        rs1 += __shfl_xor_sync(0xffffffffu, rs1, 2);
        lrow0 = lrow0 * alpha0 + rs0;
        lrow1 = lrow1 * alpha1 + rs1;

#pragma unroll
        for (int nj = 0; nj < 8; nj++) {
            o[nj][0] *= alpha0; o[nj][1] *= alpha0;
            o[nj][2] *= alpha1; o[nj][3] *= alpha1;
        }

        // ---- stage P as half2 (warp-private rows) ----
#pragma unroll
        for (int nj = 0; nj < 8; nj++) {
            Ps[(r0 + g) * FSH + nj * 4 + tig]     = pack_h2(sacc[nj][0], sacc[nj][1]);
            Ps[(r0 + g + 8) * FSH + nj * 4 + tig] = pack_h2(sacc[nj][2], sacc[nj][3]);
        }
        __syncwarp();

        // ---- O += P V : 4 k16-steps over kpos ----
#pragma unroll
        for (int kk = 0; kk < 4; kk++) {
            uint32_t a[4];
            a[0] = Ps[(r0 + g) * FSH + kk * 8 + tig];
            a[1] = Ps[(r0 + g + 8) * FSH + kk * 8 + tig];
            a[2] = Ps[(r0 + g) * FSH + kk * 8 + tig + 4];
            a[3] = Ps[(r0 + g + 8) * FSH + kk * 8 + tig + 4];
#pragma unroll
            for (int nj = 0; nj < 8; nj++) {
                uint32_t bb[2];
                bb[0] = Vt[(nj * 8 + g) * FSH + kk * 8 + tig];
                bb[1] = Vt[(nj * 8 + g) * FSH + kk * 8 + tig + 4];
                mma_f16_16x8x16(o[nj], a, bb, o[nj]);
            }
        }
    }

    // ---- epilogue ----
    float inv0 = 1.0f / lrow0;
    float inv1 = 1.0f / lrow1;
    const size_t row0 = base + qt * 128 + r0 + g;
#pragma unroll
    for (int nj = 0; nj < 8; nj++) {
        int col = h * 64 + nj * 8 + tig * 2;
        *(float2*)(z + row0 * DMODEL + col) =
            make_float2(o[nj][0] * inv0, o[nj][1] * inv0);
        *(float2*)(z + (row0 + 8) * DMODEL + col) =
            make_float2(o[nj][2] * inv1, o[nj][3] * inv1);
    }
}

// ---------------- launch ----------------
extern "C" void kernel_launch(void* const* d_in, const int* in_sizes, int n_in,
                              void* d_out, int out_size)
{
    const float* x_q  = (const float*)d_in[0];
    const float* x_k  = (const float*)d_in[1];
    const float* x_v  = (const float*)d_in[2];
    const float* amsk = (const float*)d_in[3];
    const float* w_q  = (const float*)d_in[4];
    const float* w_k  = (const float*)d_in[5];
    const float* w_v  = (const float*)d_in[6];
    const float* w_o  = (const float*)d_in[7];
    const float* b_q  = (const float*)d_in[8];
    const float* b_k  = (const float*)d_in[9];
    const float* b_v  = (const float*)d_in[10];
    const float* b_o  = (const float*)d_in[11];
    float* out = (float*)d_out;

    float *gq, *gk, *gv, *gz;
    cudaGetSymbolAddress((void**)&gq, g_q);
    cudaGetSymbolAddress((void**)&gk, g_k);
    cudaGetSymbolAddress((void**)&gv, g_v);
    cudaGetSymbolAddress((void**)&gz, g_z);

    int fl_smem = 384 * FSH * sizeof(uint32_t);   // 55,296 B
    cudaFuncSetAttribute(flash_attn_h, cudaFuncAttributeMaxDynamicSharedMemorySize, fl_smem);

    dim3 qgrid(DMODEL / 128, MROWS / 128, 3);
    qkv_gemm<<<qgrid, 256>>>(x_q, x_k, x_v, w_q, w_k, w_v,
                             b_q, b_k, b_v, gq, gk, gv);

    dim3 fgrid(S_LEN / 128, NHEADS, BATCH);
    flash_attn_h<<<fgrid, 256, fl_smem>>>(gq, gk, gv, amsk, gz);

    dim3 ogrid(DMODEL / 128, MROWS / 128);
    wo_gemm<<<ogrid, 256>>>(gz, w_o, b_o, out);

    (void)in_sizes; (void)n_in; (void)out_size;
}

// round 8
// speedup vs baseline: 1.6371x; 1.1850x over previous
#include <cuda_runtime.h>
#include <cuda_fp16.h>
#include <cstdint>
#include <math.h>

#define S_LEN   2048
#define BATCH   2
#define DMODEL  1024
#define NHEADS  16
#define DHEAD   64
#define MROWS   (BATCH * S_LEN)   // 4096
#define IGNORE_VAL (-100000.0f)

// ---------------- scratch ----------------
__device__ float g_q[MROWS * DMODEL];
__device__ float g_k[MROWS * DMODEL];
__device__ float g_v[MROWS * DMODEL];
__device__ float g_z[MROWS * DMODEL];

// ---------------- helpers ----------------
__device__ __forceinline__ uint32_t h2u(__half2 h) {
    return *reinterpret_cast<uint32_t*>(&h);
}
__device__ __forceinline__ uint32_t pack_h2(float a, float b) {
    __half2 h = __float22half2_rn(make_float2(a, b));
    return h2u(h);
}

__device__ __forceinline__ void mma_f16_16x8x16(
    float* d, const uint32_t* a, const uint32_t* b, const float* c)
{
    asm volatile(
        "mma.sync.aligned.m16n8k16.row.col.f32.f16.f16.f32 "
        "{%0,%1,%2,%3}, {%4,%5,%6,%7}, {%8,%9}, {%10,%11,%12,%13};\n"
        : "=f"(d[0]), "=f"(d[1]), "=f"(d[2]), "=f"(d[3])
        : "r"(a[0]), "r"(a[1]), "r"(a[2]), "r"(a[3]),
          "r"(b[0]), "r"(b[1]),
          "f"(c[0]), "f"(c[1]), "f"(c[2]), "f"(c[3]));
}

// ============ fp16 mma GEMM: C[M,N] = A[M,K] x Bop[N,K]^T + bias[N] ============
// mode 0: W [H=16,K=1024,D=64]; Bop[n][k] = W[n>>6][k][n&63]
// mode 1: W [K,N] row-major;    Bop[n][k] = W[k*DMODEL + n]
// CTA tile 128x128, 8 warps (2m x 4n), warp tile 64x32, k-chunk 64.
#define KCg  64
#define TSg  36

__device__ __forceinline__ void gemm_core(
    const float* __restrict__ A, const float* __restrict__ W,
    const float* __restrict__ bias, float* __restrict__ C, int mode,
    uint32_t* As, uint32_t* Bs, int n0, int m0)
{
    const int tid = threadIdx.x;
    const int wid = tid >> 5;
    const int lid = tid & 31;
    const int g   = lid >> 2;
    const int tig = lid & 3;
    const int wm  = wid >> 2;     // 0..1
    const int wn  = wid & 3;      // 0..3

    float acc[4][4][4];
#pragma unroll
    for (int i = 0; i < 4; i++)
#pragma unroll
        for (int j = 0; j < 4; j++)
#pragma unroll
            for (int f = 0; f < 4; f++) acc[i][j][f] = 0.0f;

    const int nl  = tid & 127;            // local n row for B gather
    const int ng  = n0 + nl;
    const int kg  = (tid >> 7) * 32;      // k sub-range base (0 or 32)

    const int NCH = DMODEL / KCg;         // 16
    for (int c = 0; c < NCH; c++) {
        const int k0 = c * KCg;
        __syncthreads();
        // ---- A tile: 128 rows x 64 f32 -> half2 ----
#pragma unroll
        for (int it = 0; it < 8; it++) {
            int i = tid + it * 256;       // 0..2047 over 128x16 float4
            int row = i >> 4;
            int j = i & 15;
            float4 v = *(const float4*)(A + (size_t)(m0 + row) * DMODEL + k0 + j * 4);
            As[row * TSg + j * 2 + 0] = pack_h2(v.x, v.y);
            As[row * TSg + j * 2 + 1] = pack_h2(v.z, v.w);
        }
        // ---- B tile: 128 n-rows x 64 k -> half2 (coalesced across n) ----
        if (mode == 0) {
            const float* wb = W + (size_t)(ng >> 6) * (DMODEL * DHEAD) + (ng & 63);
#pragma unroll
            for (int kp = 0; kp < 16; kp++) {
                int k = kg + kp * 2;
                float w0 = wb[(size_t)(k0 + k) * DHEAD];
                float w1 = wb[(size_t)(k0 + k + 1) * DHEAD];
                Bs[nl * TSg + (kg >> 1) + kp] = pack_h2(w0, w1);
            }
        } else {
            const float* wb = W + ng;
#pragma unroll
            for (int kp = 0; kp < 16; kp++) {
                int k = kg + kp * 2;
                float w0 = wb[(size_t)(k0 + k) * DMODEL];
                float w1 = wb[(size_t)(k0 + k + 1) * DMODEL];
                Bs[nl * TSg + (kg >> 1) + kp] = pack_h2(w0, w1);
            }
        }
        __syncthreads();

        // ---- compute: 4 k16-steps ----
#pragma unroll
        for (int kk = 0; kk < 4; kk++) {
            uint32_t af[4][4], bf[4][2];
#pragma unroll
            for (int mi = 0; mi < 4; mi++) {
                int r = wm * 64 + mi * 16 + g;
                af[mi][0] = As[r * TSg + kk * 8 + tig];
                af[mi][1] = As[(r + 8) * TSg + kk * 8 + tig];
                af[mi][2] = As[r * TSg + kk * 8 + tig + 4];
                af[mi][3] = As[(r + 8) * TSg + kk * 8 + tig + 4];
            }
#pragma unroll
            for (int nj = 0; nj < 4; nj++) {
                int n = wn * 32 + nj * 8 + g;
                bf[nj][0] = Bs[n * TSg + kk * 8 + tig];
                bf[nj][1] = Bs[n * TSg + kk * 8 + tig + 4];
            }
#pragma unroll
            for (int mi = 0; mi < 4; mi++)
#pragma unroll
                for (int nj = 0; nj < 4; nj++)
                    mma_f16_16x8x16(acc[mi][nj], af[mi], bf[nj], acc[mi][nj]);
        }
    }

#pragma unroll
    for (int mi = 0; mi < 4; mi++) {
        int r0 = m0 + wm * 64 + mi * 16 + g;
#pragma unroll
        for (int nj = 0; nj < 4; nj++) {
            int c0 = n0 + wn * 32 + nj * 8 + tig * 2;
            float b0 = bias[c0], b1 = bias[c0 + 1];
            *(float2*)(C + (size_t)r0 * DMODEL + c0) =
                make_float2(acc[mi][nj][0] + b0, acc[mi][nj][1] + b1);
            *(float2*)(C + (size_t)(r0 + 8) * DMODEL + c0) =
                make_float2(acc[mi][nj][2] + b0, acc[mi][nj][3] + b1);
        }
    }
}

__global__ __launch_bounds__(256, 2) void qkv_gemm(
    const float* __restrict__ xq, const float* __restrict__ xk, const float* __restrict__ xv,
    const float* __restrict__ wq, const float* __restrict__ wk, const float* __restrict__ wv,
    const float* __restrict__ bq, const float* __restrict__ bk, const float* __restrict__ bv,
    float* __restrict__ cq, float* __restrict__ ck, float* __restrict__ cv)
{
    __shared__ uint32_t As[128 * TSg];
    __shared__ uint32_t Bs[128 * TSg];
    const float* A = (blockIdx.z == 0) ? xq : (blockIdx.z == 1) ? xk : xv;
    const float* W = (blockIdx.z == 0) ? wq : (blockIdx.z == 1) ? wk : wv;
    const float* B = (blockIdx.z == 0) ? bq : (blockIdx.z == 1) ? bk : bv;
    float*       C = (blockIdx.z == 0) ? cq : (blockIdx.z == 1) ? ck : cv;
    gemm_core(A, W, B, C, 0, As, Bs, blockIdx.x * 128, blockIdx.y * 128);
}

__global__ __launch_bounds__(256, 2) void wo_gemm(
    const float* __restrict__ A, const float* __restrict__ W,
    const float* __restrict__ bias, float* __restrict__ C)
{
    __shared__ uint32_t As[128 * TSg];
    __shared__ uint32_t Bs[128 * TSg];
    gemm_core(A, W, bias, C, 1, As, Bs, blockIdx.x * 128, blockIdx.y * 128);
}

// ============ flash attention, fp16 mma (unchanged from R7) ============
#define FSH 36

__global__ __launch_bounds__(256) void flash_attn_h(
    const float* __restrict__ q, const float* __restrict__ k,
    const float* __restrict__ v, const float* __restrict__ amask,
    float* __restrict__ z)
{
    extern __shared__ uint32_t sm[];
    uint32_t* Qs = sm;                   // 128 x FSH
    uint32_t* Ks = sm + 128 * FSH;       // 64 x FSH
    uint32_t* Ps = sm + 192 * FSH;       // 128 x FSH
    uint32_t* Vt = sm + 320 * FSH;       // 64 x FSH

    const int qt = (int)(gridDim.x - 1 - blockIdx.x);
    const int h  = blockIdx.y;
    const int b  = blockIdx.z;
    const int tid = threadIdx.x;
    const int wid = tid >> 5;
    const int lid = tid & 31;
    const int g   = lid >> 2;
    const int tig = lid & 3;
    const int r0  = wid * 16;

    const size_t base = (size_t)b * S_LEN;
    const float* qp = q + (base + qt * 128) * DMODEL + h * 64;

#pragma unroll
    for (int it = 0; it < 8; it++) {
        int i = tid + it * 256;
        int row = i >> 4;
        int j = i & 15;
        float4 val = *(const float4*)(qp + (size_t)row * DMODEL + j * 4);
        Qs[row * FSH + j * 2 + 0] = pack_h2(val.x, val.y);
        Qs[row * FSH + j * 2 + 1] = pack_h2(val.z, val.w);
    }

    float o[8][4];
#pragma unroll
    for (int nj = 0; nj < 8; nj++)
#pragma unroll
        for (int f = 0; f < 4; f++) o[nj][f] = 0.0f;
    float mrow0 = -1e30f, mrow1 = -1e30f;
    float lrow0 = 0.0f,  lrow1 = 0.0f;

    const int qi0 = qt * 128 + r0 + g;
    const int qi1 = qi0 + 8;
    const int nkt = 2 * (qt + 1);

    const int vp_pair = tid & 31;
    const int vdq     = tid >> 5;

    for (int kt = 0; kt < nkt; kt++) {
        __syncthreads();
        const float* kp = k + (base + kt * 64) * DMODEL + h * 64;
        const float* vp = v + (base + kt * 64) * DMODEL + h * 64;
#pragma unroll
        for (int it = 0; it < 4; it++) {
            int i = tid + it * 256;
            int row = i >> 4;
            int j = i & 15;
            float4 kv = *(const float4*)(kp + (size_t)row * DMODEL + j * 4);
            Ks[row * FSH + j * 2 + 0] = pack_h2(kv.x, kv.y);
            Ks[row * FSH + j * 2 + 1] = pack_h2(kv.z, kv.w);
        }
        {
            const float* va = vp + (size_t)(2 * vp_pair) * DMODEL + vdq * 8;
            const float* vb = va + DMODEL;
            float4 a0 = *(const float4*)(va);
            float4 a1 = *(const float4*)(va + 4);
            float4 b0 = *(const float4*)(vb);
            float4 b1 = *(const float4*)(vb + 4);
            int dbase = vdq * 8;
            Vt[(dbase + 0) * FSH + vp_pair] = pack_h2(a0.x, b0.x);
            Vt[(dbase + 1) * FSH + vp_pair] = pack_h2(a0.y, b0.y);
            Vt[(dbase + 2) * FSH + vp_pair] = pack_h2(a0.z, b0.z);
            Vt[(dbase + 3) * FSH + vp_pair] = pack_h2(a0.w, b0.w);
            Vt[(dbase + 4) * FSH + vp_pair] = pack_h2(a1.x, b1.x);
            Vt[(dbase + 5) * FSH + vp_pair] = pack_h2(a1.y, b1.y);
            Vt[(dbase + 6) * FSH + vp_pair] = pack_h2(a1.z, b1.z);
            Vt[(dbase + 7) * FSH + vp_pair] = pack_h2(a1.w, b1.w);
        }
        __syncthreads();

        float sacc[8][4];
#pragma unroll
        for (int nj = 0; nj < 8; nj++)
#pragma unroll
            for (int f = 0; f < 4; f++) sacc[nj][f] = 0.0f;

#pragma unroll
        for (int kk = 0; kk < 4; kk++) {
            uint32_t a[4];
            a[0] = Qs[(r0 + g) * FSH + kk * 8 + tig];
            a[1] = Qs[(r0 + g + 8) * FSH + kk * 8 + tig];
            a[2] = Qs[(r0 + g) * FSH + kk * 8 + tig + 4];
            a[3] = Qs[(r0 + g + 8) * FSH + kk * 8 + tig + 4];
#pragma unroll
            for (int nj = 0; nj < 8; nj++) {
                uint32_t bb[2];
                bb[0] = Ks[(nj * 8 + g) * FSH + kk * 8 + tig];
                bb[1] = Ks[(nj * 8 + g) * FSH + kk * 8 + tig + 4];
                mma_f16_16x8x16(sacc[nj], a, bb, sacc[nj]);
            }
        }

        float tmax0 = -1e30f, tmax1 = -1e30f;
#pragma unroll
        for (int nj = 0; nj < 8; nj++) {
            int kj = kt * 64 + nj * 8 + tig * 2;
            float am0 = amask[b * S_LEN + kj];
            float am1 = amask[b * S_LEN + kj + 1];
            float s0 = ((kj     <= qi0) ? sacc[nj][0] * 0.125f : IGNORE_VAL) + am0;
            float s1 = ((kj + 1 <= qi0) ? sacc[nj][1] * 0.125f : IGNORE_VAL) + am1;
            float s2 = ((kj     <= qi1) ? sacc[nj][2] * 0.125f : IGNORE_VAL) + am0;
            float s3 = ((kj + 1 <= qi1) ? sacc[nj][3] * 0.125f : IGNORE_VAL) + am1;
            sacc[nj][0] = s0; sacc[nj][1] = s1; sacc[nj][2] = s2; sacc[nj][3] = s3;
            tmax0 = fmaxf(tmax0, fmaxf(s0, s1));
            tmax1 = fmaxf(tmax1, fmaxf(s2, s3));
        }
        tmax0 = fmaxf(tmax0, __shfl_xor_sync(0xffffffffu, tmax0, 1));
        tmax0 = fmaxf(tmax0, __shfl_xor_sync(0xffffffffu, tmax0, 2));
        tmax1 = fmaxf(tmax1, __shfl_xor_sync(0xffffffffu, tmax1, 1));
        tmax1 = fmaxf(tmax1, __shfl_xor_sync(0xffffffffu, tmax1, 2));

        float mn0 = fmaxf(mrow0, tmax0);
        float mn1 = fmaxf(mrow1, tmax1);
        float alpha0 = __expf(mrow0 - mn0);
        float alpha1 = __expf(mrow1 - mn1);
        mrow0 = mn0; mrow1 = mn1;

        float rs0 = 0.0f, rs1 = 0.0f;
#pragma unroll
        for (int nj = 0; nj < 8; nj++) {
            float p0 = __expf(sacc[nj][0] - mn0);
            float p1 = __expf(sacc[nj][1] - mn0);
            float p2 = __expf(sacc[nj][2] - mn1);
            float p3 = __expf(sacc[nj][3] - mn1);
            sacc[nj][0] = p0; sacc[nj][1] = p1; sacc[nj][2] = p2; sacc[nj][3] = p3;
            rs0 += p0 + p1;
            rs1 += p2 + p3;
        }
        rs0 += __shfl_xor_sync(0xffffffffu, rs0, 1);
        rs0 += __shfl_xor_sync(0xffffffffu, rs0, 2);
        rs1 += __shfl_xor_sync(0xffffffffu, rs1, 1);
        rs1 += __shfl_xor_sync(0xffffffffu, rs1, 2);
        lrow0 = lrow0 * alpha0 + rs0;
        lrow1 = lrow1 * alpha1 + rs1;

#pragma unroll
        for (int nj = 0; nj < 8; nj++) {
            o[nj][0] *= alpha0; o[nj][1] *= alpha0;
            o[nj][2] *= alpha1; o[nj][3] *= alpha1;
        }

#pragma unroll
        for (int nj = 0; nj < 8; nj++) {
            Ps[(r0 + g) * FSH + nj * 4 + tig]     = pack_h2(sacc[nj][0], sacc[nj][1]);
            Ps[(r0 + g + 8) * FSH + nj * 4 + tig] = pack_h2(sacc[nj][2], sacc[nj][3]);
        }
        __syncwarp();

#pragma unroll
        for (int kk = 0; kk < 4; kk++) {
            uint32_t a[4];
            a[0] = Ps[(r0 + g) * FSH + kk * 8 + tig];
            a[1] = Ps[(r0 + g + 8) * FSH + kk * 8 + tig];
            a[2] = Ps[(r0 + g) * FSH + kk * 8 + tig + 4];
            a[3] = Ps[(r0 + g + 8) * FSH + kk * 8 + tig + 4];
#pragma unroll
            for (int nj = 0; nj < 8; nj++) {
                uint32_t bb[2];
                bb[0] = Vt[(nj * 8 + g) * FSH + kk * 8 + tig];
                bb[1] = Vt[(nj * 8 + g) * FSH + kk * 8 + tig + 4];
                mma_f16_16x8x16(o[nj], a, bb, o[nj]);
            }
        }
    }

    float inv0 = 1.0f / lrow0;
    float inv1 = 1.0f / lrow1;
    const size_t row0 = base + qt * 128 + r0 + g;
#pragma unroll
    for (int nj = 0; nj < 8; nj++) {
        int col = h * 64 + nj * 8 + tig * 2;
        *(float2*)(z + row0 * DMODEL + col) =
            make_float2(o[nj][0] * inv0, o[nj][1] * inv0);
        *(float2*)(z + (row0 + 8) * DMODEL + col) =
            make_float2(o[nj][2] * inv1, o[nj][3] * inv1);
    }
}

// ---------------- launch ----------------
extern "C" void kernel_launch(void* const* d_in, const int* in_sizes, int n_in,
                              void* d_out, int out_size)
{
    const float* x_q  = (const float*)d_in[0];
    const float* x_k  = (const float*)d_in[1];
    const float* x_v  = (const float*)d_in[2];
    const float* amsk = (const float*)d_in[3];
    const float* w_q  = (const float*)d_in[4];
    const float* w_k  = (const float*)d_in[5];
    const float* w_v  = (const float*)d_in[6];
    const float* w_o  = (const float*)d_in[7];
    const float* b_q  = (const float*)d_in[8];
    const float* b_k  = (const float*)d_in[9];
    const float* b_v  = (const float*)d_in[10];
    const float* b_o  = (const float*)d_in[11];
    float* out = (float*)d_out;

    float *gq, *gk, *gv, *gz;
    cudaGetSymbolAddress((void**)&gq, g_q);
    cudaGetSymbolAddress((void**)&gk, g_k);
    cudaGetSymbolAddress((void**)&gv, g_v);
    cudaGetSymbolAddress((void**)&gz, g_z);

    int fl_smem = 384 * FSH * sizeof(uint32_t);   // 55,296 B
    cudaFuncSetAttribute(flash_attn_h, cudaFuncAttributeMaxDynamicSharedMemorySize, fl_smem);

    dim3 qgrid(DMODEL / 128, MROWS / 128, 3);
    qkv_gemm<<<qgrid, 256>>>(x_q, x_k, x_v, w_q, w_k, w_v,
                             b_q, b_k, b_v, gq, gk, gv);

    dim3 fgrid(S_LEN / 128, NHEADS, BATCH);
    flash_attn_h<<<fgrid, 256, fl_smem>>>(gq, gk, gv, amsk, gz);

    dim3 ogrid(DMODEL / 128, MROWS / 128);
    wo_gemm<<<ogrid, 256>>>(gz, w_o, b_o, out);

    (void)in_sizes; (void)n_in; (void)out_size;
}

// round 10
// speedup vs baseline: 1.9071x; 1.1649x over previous
#include <cuda_runtime.h>
#include <cuda_fp16.h>
#include <cstdint>
#include <math.h>

#define S_LEN   2048
#define BATCH   2
#define DMODEL  1024
#define NHEADS  16
#define DHEAD   64
#define MROWS   (BATCH * S_LEN)   // 4096
#define IGNORE_VAL (-100000.0f)

// ---------------- scratch (half everywhere) ----------------
__device__ __half g_hxq[MROWS * DMODEL];
__device__ __half g_hxk[MROWS * DMODEL];
__device__ __half g_hxv[MROWS * DMODEL];
__device__ __half g_hwq[DMODEL * DMODEL];   // [n][k]
__device__ __half g_hwk[DMODEL * DMODEL];
__device__ __half g_hwv[DMODEL * DMODEL];
__device__ __half g_hwo[DMODEL * DMODEL];   // [n][k]
__device__ __half g_hq[MROWS * DMODEL];
__device__ __half g_hk[MROWS * DMODEL];
__device__ __half g_hv[MROWS * DMODEL];
__device__ __half g_hz[MROWS * DMODEL];

// ---------------- helpers ----------------
__device__ __forceinline__ uint32_t smem_u32(const void* p) {
    uint32_t a;
    asm("{ .reg .u64 t; cvta.to.shared.u64 t, %1; cvt.u32.u64 %0, t; }" : "=r"(a) : "l"(p));
    return a;
}
__device__ __forceinline__ uint32_t pack_h2(float a, float b) {
    __half2 h = __float22half2_rn(make_float2(a, b));
    return *reinterpret_cast<uint32_t*>(&h);
}
__device__ __forceinline__ uint32_t prmt(uint32_t a, uint32_t b, uint32_t sel) {
    uint32_t r;
    asm("prmt.b32 %0, %1, %2, %3;" : "=r"(r) : "r"(a), "r"(b), "r"(sel));
    return r;
}
__device__ __forceinline__ void cp_async16(uint32_t dst, const void* src) {
    asm volatile("cp.async.cg.shared.global [%0], [%1], 16;" :: "r"(dst), "l"(src));
}
__device__ __forceinline__ void cp_commit() {
    asm volatile("cp.async.commit_group;" ::: "memory");
}
template <int N>
__device__ __forceinline__ void cp_wait() {
    asm volatile("cp.async.wait_group %0;" :: "n"(N) : "memory");
}
__device__ __forceinline__ void mma_f16_16x8x16(
    float* d, const uint32_t* a, const uint32_t* b, const float* c)
{
    asm volatile(
        "mma.sync.aligned.m16n8k16.row.col.f32.f16.f16.f32 "
        "{%0,%1,%2,%3}, {%4,%5,%6,%7}, {%8,%9}, {%10,%11,%12,%13};\n"
        : "=f"(d[0]), "=f"(d[1]), "=f"(d[2]), "=f"(d[3])
        : "r"(a[0]), "r"(a[1]), "r"(a[2]), "r"(a[3]),
          "r"(b[0]), "r"(b[1]),
          "f"(c[0]), "f"(c[1]), "f"(c[2]), "f"(c[3]));
}

// ================= conversion kernels =================
__global__ void conv_x(const float* __restrict__ xq, const float* __restrict__ xk,
                       const float* __restrict__ xv,
                       __half* __restrict__ hq, __half* __restrict__ hk,
                       __half* __restrict__ hv)
{
    const float* src = (blockIdx.y == 0) ? xq : (blockIdx.y == 1) ? xk : xv;
    __half* dst = (blockIdx.y == 0) ? hq : (blockIdx.y == 1) ? hk : hv;
    int idx = blockIdx.x * 256 + threadIdx.x;     // float4 index
    float4 v = *(const float4*)(src + (size_t)idx * 4);
    uint32_t* d = (uint32_t*)(dst + (size_t)idx * 4);
    d[0] = pack_h2(v.x, v.y);
    d[1] = pack_h2(v.z, v.w);
}

// QKV weights: W[h][k][d] f32 -> hw[(h*64+d)][k] half. grid (16 ktile, 16 h, 3)
__global__ void conv_w(const float* __restrict__ wq, const float* __restrict__ wk,
                       const float* __restrict__ wv,
                       __half* __restrict__ hwq, __half* __restrict__ hwk,
                       __half* __restrict__ hwv)
{
    __shared__ float s[64][65];
    const float* W = (blockIdx.z == 0) ? wq : (blockIdx.z == 1) ? wk : wv;
    __half* hw = (blockIdx.z == 0) ? hwq : (blockIdx.z == 1) ? hwk : hwv;
    const int k0 = blockIdx.x * 64;
    const int h  = blockIdx.y;
    const int tid = threadIdx.x;
#pragma unroll
    for (int it = 0; it < 4; it++) {
        int idx = tid + it * 256;
        int kk = idx >> 4, d4 = (idx & 15) * 4;
        float4 v = *(const float4*)(W + (size_t)h * DMODEL * DHEAD + (size_t)(k0 + kk) * DHEAD + d4);
        s[kk][d4 + 0] = v.x; s[kk][d4 + 1] = v.y;
        s[kk][d4 + 2] = v.z; s[kk][d4 + 3] = v.w;
    }
    __syncthreads();
    int d = tid >> 2, seg = (tid & 3) * 16;
    uint32_t* dst = (uint32_t*)(hw + (size_t)(h * 64 + d) * DMODEL + k0 + seg);
#pragma unroll
    for (int j = 0; j < 8; j++)
        dst[j] = pack_h2(s[seg + 2 * j][d], s[seg + 2 * j + 1][d]);
}

// W_O: w[k][n] f32 -> hwo[n][k] half. grid (16 ktile, 16 ntile)
__global__ void conv_wo(const float* __restrict__ w, __half* __restrict__ hwo)
{
    __shared__ float s[64][65];
    const int k0 = blockIdx.x * 64;
    const int n0 = blockIdx.y * 64;
    const int tid = threadIdx.x;
#pragma unroll
    for (int it = 0; it < 4; it++) {
        int idx = tid + it * 256;
        int kk = idx >> 4, n4 = (idx & 15) * 4;
        float4 v = *(const float4*)(w + (size_t)(k0 + kk) * DMODEL + n0 + n4);
        s[kk][n4 + 0] = v.x; s[kk][n4 + 1] = v.y;
        s[kk][n4 + 2] = v.z; s[kk][n4 + 3] = v.w;
    }
    __syncthreads();
    int n = tid >> 2, seg = (tid & 3) * 16;
    uint32_t* dst = (uint32_t*)(hwo + (size_t)(n0 + n) * DMODEL + k0 + seg);
#pragma unroll
    for (int j = 0; j < 8; j++)
        dst[j] = pack_h2(s[seg + 2 * j][n], s[seg + 2 * j + 1][n]);
}

// ============ half GEMM, cp.async double-buffered ============
#define TSg 36
#define GEMM_SMEM (4 * 128 * TSg * 4)   // 73,728 B

__device__ __forceinline__ void gemm_pipe(
    const __half* __restrict__ A, const __half* __restrict__ B,
    uint32_t* smg, int n0, int m0, float acc[4][4][4])
{
    uint32_t* AsF[2] = { smg, smg + 128 * TSg };
    uint32_t* BsF[2] = { smg + 256 * TSg, smg + 384 * TSg };
    const uint32_t sA[2] = { smem_u32(AsF[0]), smem_u32(AsF[1]) };
    const uint32_t sB[2] = { smem_u32(BsF[0]), smem_u32(BsF[1]) };

    const int tid = threadIdx.x;
    const int wid = tid >> 5;
    const int lid = tid & 31;
    const int g   = lid >> 2;
    const int tig = lid & 3;
    const int wm  = wid >> 2;
    const int wn  = wid & 3;

#pragma unroll
    for (int i = 0; i < 4; i++)
#pragma unroll
        for (int j = 0; j < 4; j++)
#pragma unroll
            for (int f = 0; f < 4; f++) acc[i][j][f] = 0.0f;

    auto load_chunk = [&](int c, int buf) {
        const int k0 = c * 64;
#pragma unroll
        for (int it = 0; it < 4; it++) {
            int i = tid + it * 256;
            int row = i >> 3, j = i & 7;
            cp_async16(sA[buf] + (uint32_t)(row * TSg + j * 4) * 4,
                       A + (size_t)(m0 + row) * DMODEL + k0 + j * 8);
            cp_async16(sB[buf] + (uint32_t)(row * TSg + j * 4) * 4,
                       B + (size_t)(n0 + row) * DMODEL + k0 + j * 8);
        }
        cp_commit();
    };

    load_chunk(0, 0);
    const int NCH = DMODEL / 64;   // 16
    for (int c = 0; c < NCH; c++) {
        if (c + 1 < NCH) {
            load_chunk(c + 1, (c + 1) & 1);
            cp_wait<1>();
        } else {
            cp_wait<0>();
        }
        __syncthreads();

        const uint32_t* As_ = AsF[c & 1];
        const uint32_t* Bs_ = BsF[c & 1];
#pragma unroll
        for (int kk = 0; kk < 4; kk++) {
            uint32_t af[4][4], bf[4][2];
#pragma unroll
            for (int mi = 0; mi < 4; mi++) {
                int r = wm * 64 + mi * 16 + g;
                af[mi][0] = As_[r * TSg + kk * 8 + tig];
                af[mi][1] = As_[(r + 8) * TSg + kk * 8 + tig];
                af[mi][2] = As_[r * TSg + kk * 8 + tig + 4];
                af[mi][3] = As_[(r + 8) * TSg + kk * 8 + tig + 4];
            }
#pragma unroll
            for (int nj = 0; nj < 4; nj++) {
                int n = wn * 32 + nj * 8 + g;
                bf[nj][0] = Bs_[n * TSg + kk * 8 + tig];
                bf[nj][1] = Bs_[n * TSg + kk * 8 + tig + 4];
            }
#pragma unroll
            for (int mi = 0; mi < 4; mi++)
#pragma unroll
                for (int nj = 0; nj < 4; nj++)
                    mma_f16_16x8x16(acc[mi][nj], af[mi], bf[nj], acc[mi][nj]);
        }
        __syncthreads();
    }
}

__global__ __launch_bounds__(256, 2) void qkv_gemm(
    const __half* __restrict__ xq, const __half* __restrict__ xk, const __half* __restrict__ xv,
    const __half* __restrict__ wq, const __half* __restrict__ wk, const __half* __restrict__ wv,
    const float* __restrict__ bq, const float* __restrict__ bk, const float* __restrict__ bv,
    __half* __restrict__ cq, __half* __restrict__ ck, __half* __restrict__ cv)
{
    extern __shared__ uint32_t smg[];
    const __half* A = (blockIdx.z == 0) ? xq : (blockIdx.z == 1) ? xk : xv;
    const __half* B = (blockIdx.z == 0) ? wq : (blockIdx.z == 1) ? wk : wv;
    const float* bias = (blockIdx.z == 0) ? bq : (blockIdx.z == 1) ? bk : bv;
    __half*      C = (blockIdx.z == 0) ? cq : (blockIdx.z == 1) ? ck : cv;
    const int n0 = blockIdx.x * 128, m0 = blockIdx.y * 128;

    float acc[4][4][4];
    gemm_pipe(A, B, smg, n0, m0, acc);

    const int lid = threadIdx.x & 31;
    const int g = lid >> 2, tig = lid & 3;
    const int wm = (threadIdx.x >> 5) >> 2, wn = (threadIdx.x >> 5) & 3;
#pragma unroll
    for (int mi = 0; mi < 4; mi++) {
        int r0 = m0 + wm * 64 + mi * 16 + g;
#pragma unroll
        for (int nj = 0; nj < 4; nj++) {
            int c0 = n0 + wn * 32 + nj * 8 + tig * 2;
            float b0 = bias[c0], b1 = bias[c0 + 1];
            *(uint32_t*)(C + (size_t)r0 * DMODEL + c0) =
                pack_h2(acc[mi][nj][0] + b0, acc[mi][nj][1] + b1);
            *(uint32_t*)(C + (size_t)(r0 + 8) * DMODEL + c0) =
                pack_h2(acc[mi][nj][2] + b0, acc[mi][nj][3] + b1);
        }
    }
}

__global__ __launch_bounds__(256, 2) void wo_gemm(
    const __half* __restrict__ A, const __half* __restrict__ B,
    const float* __restrict__ bias, float* __restrict__ C)
{
    extern __shared__ uint32_t smg[];
    const int n0 = blockIdx.x * 128, m0 = blockIdx.y * 128;

    float acc[4][4][4];
    gemm_pipe(A, B, smg, n0, m0, acc);

    const int lid = threadIdx.x & 31;
    const int g = lid >> 2, tig = lid & 3;
    const int wm = (threadIdx.x >> 5) >> 2, wn = (threadIdx.x >> 5) & 3;
#pragma unroll
    for (int mi = 0; mi < 4; mi++) {
        int r0 = m0 + wm * 64 + mi * 16 + g;
#pragma unroll
        for (int nj = 0; nj < 4; nj++) {
            int c0 = n0 + wn * 32 + nj * 8 + tig * 2;
            float b0 = bias[c0], b1 = bias[c0 + 1];
            *(float2*)(C + (size_t)r0 * DMODEL + c0) =
                make_float2(acc[mi][nj][0] + b0, acc[mi][nj][1] + b1);
            *(float2*)(C + (size_t)(r0 + 8) * DMODEL + c0) =
                make_float2(acc[mi][nj][2] + b0, acc[mi][nj][3] + b1);
        }
    }
}

// ============ flash attention, all-half I/O ============
#define FSH 36

__global__ __launch_bounds__(256) void flash_attn_h(
    const __half* __restrict__ q, const __half* __restrict__ k,
    const __half* __restrict__ v, const float* __restrict__ amask,
    __half* __restrict__ z)
{
    extern __shared__ uint32_t sm[];
    uint32_t* Qs = sm;                   // 128 x FSH
    uint32_t* Ks = sm + 128 * FSH;       // 64 x FSH
    uint32_t* Ps = sm + 192 * FSH;       // 128 x FSH
    uint32_t* Vt = sm + 320 * FSH;       // 64 x FSH

    const int qt = (int)(gridDim.x - 1 - blockIdx.x);
    const int h  = blockIdx.y;
    const int b  = blockIdx.z;
    const int tid = threadIdx.x;
    const int wid = tid >> 5;
    const int lid = tid & 31;
    const int g   = lid >> 2;
    const int tig = lid & 3;
    const int r0  = wid * 16;

    const size_t base = (size_t)b * S_LEN;
    const __half* qp = q + (base + qt * 128) * DMODEL + h * 64;

    // Q tile: 128 rows x 64 halfs = 1024 uint4 (8 per row)
#pragma unroll
    for (int it = 0; it < 4; it++) {
        int i = tid + it * 256;          // 0..1023
        int row = i >> 3, j = i & 7;
        *(uint4*)(Qs + row * FSH + j * 4) =
            *(const uint4*)((const char*)(qp + (size_t)row * DMODEL) + j * 16);
    }

    float o[8][4];
#pragma unroll
    for (int nj = 0; nj < 8; nj++)
#pragma unroll
        for (int f = 0; f < 4; f++) o[nj][f] = 0.0f;
    float mrow0 = -1e30f, mrow1 = -1e30f;
    float lrow0 = 0.0f,  lrow1 = 0.0f;

    const int qi0 = qt * 128 + r0 + g;
    const int qi1 = qi0 + 8;
    const int nkt = 2 * (qt + 1);

    const int vp_pair = tid & 31;        // kpos pair 0..31
    const int vdq     = tid >> 5;        // d octet 0..7

    for (int kt = 0; kt < nkt; kt++) {
        __syncthreads();
        const __half* kp = k + (base + kt * 64) * DMODEL + h * 64;
        const __half* vp = v + (base + kt * 64) * DMODEL + h * 64;
        // K tile: 64 rows x 64 halfs = 512 uint4 (8 per row)
#pragma unroll
        for (int it = 0; it < 2; it++) {
            int i = tid + it * 256;      // 0..511
            int row = i >> 3, j = i & 7;
            *(uint4*)(Ks + row * FSH + j * 4) =
                *(const uint4*)((const char*)(kp + (size_t)row * DMODEL) + j * 16);
        }
        // V transposed via PRMT: rows {2p, 2p+1}, d cols [8dq, 8dq+8)
        {
            uint4 a = *(const uint4*)(vp + (size_t)(2 * vp_pair) * DMODEL + vdq * 8);
            uint4 bq4 = *(const uint4*)(vp + (size_t)(2 * vp_pair + 1) * DMODEL + vdq * 8);
            int dbase = vdq * 8;
            Vt[(dbase + 0) * FSH + vp_pair] = prmt(a.x, bq4.x, 0x5410);
            Vt[(dbase + 1) * FSH + vp_pair] = prmt(a.x, bq4.x, 0x7632);
            Vt[(dbase + 2) * FSH + vp_pair] = prmt(a.y, bq4.y, 0x5410);
            Vt[(dbase + 3) * FSH + vp_pair] = prmt(a.y, bq4.y, 0x7632);
            Vt[(dbase + 4) * FSH + vp_pair] = prmt(a.z, bq4.z, 0x5410);
            Vt[(dbase + 5) * FSH + vp_pair] = prmt(a.z, bq4.z, 0x7632);
            Vt[(dbase + 6) * FSH + vp_pair] = prmt(a.w, bq4.w, 0x5410);
            Vt[(dbase + 7) * FSH + vp_pair] = prmt(a.w, bq4.w, 0x7632);
        }
        __syncthreads();

        // ---- S = Q K^T ----
        float sacc[8][4];
#pragma unroll
        for (int nj = 0; nj < 8; nj++)
#pragma unroll
            for (int f = 0; f < 4; f++) sacc[nj][f] = 0.0f;

#pragma unroll
        for (int kk = 0; kk < 4; kk++) {
            uint32_t a[4];
            a[0] = Qs[(r0 + g) * FSH + kk * 8 + tig];
            a[1] = Qs[(r0 + g + 8) * FSH + kk * 8 + tig];
            a[2] = Qs[(r0 + g) * FSH + kk * 8 + tig + 4];
            a[3] = Qs[(r0 + g + 8) * FSH + kk * 8 + tig + 4];
#pragma unroll
            for (int nj = 0; nj < 8; nj++) {
                uint32_t bb[2];
                bb[0] = Ks[(nj * 8 + g) * FSH + kk * 8 + tig];
                bb[1] = Ks[(nj * 8 + g) * FSH + kk * 8 + tig + 4];
                mma_f16_16x8x16(sacc[nj], a, bb, sacc[nj]);
            }
        }

        // ---- scale, causal, additive mask ----
        float tmax0 = -1e30f, tmax1 = -1e30f;
#pragma unroll
        for (int nj = 0; nj < 8; nj++) {
            int kj = kt * 64 + nj * 8 + tig * 2;
            float am0 = amask[b * S_LEN + kj];
            float am1 = amask[b * S_LEN + kj + 1];
            float s0 = ((kj     <= qi0) ? sacc[nj][0] * 0.125f : IGNORE_VAL) + am0;
            float s1 = ((kj + 1 <= qi0) ? sacc[nj][1] * 0.125f : IGNORE_VAL) + am1;
            float s2 = ((kj     <= qi1) ? sacc[nj][2] * 0.125f : IGNORE_VAL) + am0;
            float s3 = ((kj + 1 <= qi1) ? sacc[nj][3] * 0.125f : IGNORE_VAL) + am1;
            sacc[nj][0] = s0; sacc[nj][1] = s1; sacc[nj][2] = s2; sacc[nj][3] = s3;
            tmax0 = fmaxf(tmax0, fmaxf(s0, s1));
            tmax1 = fmaxf(tmax1, fmaxf(s2, s3));
        }
        tmax0 = fmaxf(tmax0, __shfl_xor_sync(0xffffffffu, tmax0, 1));
        tmax0 = fmaxf(tmax0, __shfl_xor_sync(0xffffffffu, tmax0, 2));
        tmax1 = fmaxf(tmax1, __shfl_xor_sync(0xffffffffu, tmax1, 1));
        tmax1 = fmaxf(tmax1, __shfl_xor_sync(0xffffffffu, tmax1, 2));

        float mn0 = fmaxf(mrow0, tmax0);
        float mn1 = fmaxf(mrow1, tmax1);
        float alpha0 = __expf(mrow0 - mn0);
        float alpha1 = __expf(mrow1 - mn1);
        mrow0 = mn0; mrow1 = mn1;

        float rs0 = 0.0f, rs1 = 0.0f;
#pragma unroll
        for (int nj = 0; nj < 8; nj++) {
            float p0 = __expf(sacc[nj][0] - mn0);
            float p1 = __expf(sacc[nj][1] - mn0);
            float p2 = __expf(sacc[nj][2] - mn1);
            float p3 = __expf(sacc[nj][3] - mn1);
            sacc[nj][0] = p0; sacc[nj][1] = p1; sacc[nj][2] = p2; sacc[nj][3] = p3;
            rs0 += p0 + p1;
            rs1 += p2 + p3;
        }
        rs0 += __shfl_xor_sync(0xffffffffu, rs0, 1);
        rs0 += __shfl_xor_sync(0xffffffffu, rs0, 2);
        rs1 += __shfl_xor_sync(0xffffffffu, rs1, 1);
        rs1 += __shfl_xor_sync(0xffffffffu, rs1, 2);
        lrow0 = lrow0 * alpha0 + rs0;
        lrow1 = lrow1 * alpha1 + rs1;

#pragma unroll
        for (int nj = 0; nj < 8; nj++) {
            o[nj][0] *= alpha0; o[nj][1] *= alpha0;
            o[nj][2] *= alpha1; o[nj][3] *= alpha1;
        }

#pragma unroll
        for (int nj = 0; nj < 8; nj++) {
            Ps[(r0 + g) * FSH + nj * 4 + tig]     = pack_h2(sacc[nj][0], sacc[nj][1]);
            Ps[(r0 + g + 8) * FSH + nj * 4 + tig] = pack_h2(sacc[nj][2], sacc[nj][3]);
        }
        __syncwarp();

#pragma unroll
        for (int kk = 0; kk < 4; kk++) {
            uint32_t a[4];
            a[0] = Ps[(r0 + g) * FSH + kk * 8 + tig];
            a[1] = Ps[(r0 + g + 8) * FSH + kk * 8 + tig];
            a[2] = Ps[(r0 + g) * FSH + kk * 8 + tig + 4];
            a[3] = Ps[(r0 + g + 8) * FSH + kk * 8 + tig + 4];
#pragma unroll
            for (int nj = 0; nj < 8; nj++) {
                uint32_t bb[2];
                bb[0] = Vt[(nj * 8 + g) * FSH + kk * 8 + tig];
                bb[1] = Vt[(nj * 8 + g) * FSH + kk * 8 + tig + 4];
                mma_f16_16x8x16(o[nj], a, bb, o[nj]);
            }
        }
    }

    // ---- epilogue: write z as half ----
    float inv0 = 1.0f / lrow0;
    float inv1 = 1.0f / lrow1;
    const size_t row0 = base + qt * 128 + r0 + g;
#pragma unroll
    for (int nj = 0; nj < 8; nj++) {
        int col = h * 64 + nj * 8 + tig * 2;
        *(uint32_t*)(z + row0 * DMODEL + col) =
            pack_h2(o[nj][0] * inv0, o[nj][1] * inv0);
        *(uint32_t*)(z + (row0 + 8) * DMODEL + col) =
            pack_h2(o[nj][2] * inv1, o[nj][3] * inv1);
    }
}

// ---------------- launch ----------------
extern "C" void kernel_launch(void* const* d_in, const int* in_sizes, int n_in,
                              void* d_out, int out_size)
{
    const float* x_q  = (const float*)d_in[0];
    const float* x_k  = (const float*)d_in[1];
    const float* x_v  = (const float*)d_in[2];
    const float* amsk = (const float*)d_in[3];
    const float* w_q  = (const float*)d_in[4];
    const float* w_k  = (const float*)d_in[5];
    const float* w_v  = (const float*)d_in[6];
    const float* w_o  = (const float*)d_in[7];
    const float* b_q  = (const float*)d_in[8];
    const float* b_k  = (const float*)d_in[9];
    const float* b_v  = (const float*)d_in[10];
    const float* b_o  = (const float*)d_in[11];
    float* out = (float*)d_out;

    __half *hxq, *hxk, *hxv, *hwq, *hwk, *hwv, *hwo, *hq, *hk, *hv, *hz;
    cudaGetSymbolAddress((void**)&hxq, g_hxq);
    cudaGetSymbolAddress((void**)&hxk, g_hxk);
    cudaGetSymbolAddress((void**)&hxv, g_hxv);
    cudaGetSymbolAddress((void**)&hwq, g_hwq);
    cudaGetSymbolAddress((void**)&hwk, g_hwk);
    cudaGetSymbolAddress((void**)&hwv, g_hwv);
    cudaGetSymbolAddress((void**)&hwo, g_hwo);
    cudaGetSymbolAddress((void**)&hq,  g_hq);
    cudaGetSymbolAddress((void**)&hk,  g_hk);
    cudaGetSymbolAddress((void**)&hv,  g_hv);
    cudaGetSymbolAddress((void**)&hz,  g_hz);

    int fl_smem = 384 * FSH * sizeof(uint32_t);   // 55,296 B
    cudaFuncSetAttribute(flash_attn_h, cudaFuncAttributeMaxDynamicSharedMemorySize, fl_smem);
    cudaFuncSetAttribute(qkv_gemm, cudaFuncAttributeMaxDynamicSharedMemorySize, GEMM_SMEM);
    cudaFuncSetAttribute(wo_gemm, cudaFuncAttributeMaxDynamicSharedMemorySize, GEMM_SMEM);

    // conversions
    dim3 cxg(MROWS * DMODEL / (256 * 4), 3);
    conv_x<<<cxg, 256>>>(x_q, x_k, x_v, hxq, hxk, hxv);
    dim3 cwg(DMODEL / 64, NHEADS, 3);
    conv_w<<<cwg, 256>>>(w_q, w_k, w_v, hwq, hwk, hwv);
    dim3 cog(DMODEL / 64, DMODEL / 64);
    conv_wo<<<cog, 256>>>(w_o, hwo);

    // QKV projections
    dim3 qgrid(DMODEL / 128, MROWS / 128, 3);
    qkv_gemm<<<qgrid, 256, GEMM_SMEM>>>(hxq, hxk, hxv, hwq, hwk, hwv,
                                        b_q, b_k, b_v, hq, hk, hv);

    // flash attention
    dim3 fgrid(S_LEN / 128, NHEADS, BATCH);
    flash_attn_h<<<fgrid, 256, fl_smem>>>(hq, hk, hv, amsk, hz);

    // output projection
    dim3 ogrid(DMODEL / 128, MROWS / 128);
    wo_gemm<<<ogrid, 256, GEMM_SMEM>>>(hz, hwo, b_o, out);

    (void)in_sizes; (void)n_in; (void)out_size;
}

// round 11
// speedup vs baseline: 1.9213x; 1.0075x over previous
#include <cuda_runtime.h>
#include <cuda_fp16.h>
#include <cstdint>
#include <math.h>

#define S_LEN   2048
#define BATCH   2
#define DMODEL  1024
#define NHEADS  16
#define DHEAD   64
#define MROWS   (BATCH * S_LEN)   // 4096
#define IGNORE_VAL (-100000.0f)

// ---------------- scratch (half everywhere) ----------------
__device__ __half g_hxq[MROWS * DMODEL];
__device__ __half g_hxk[MROWS * DMODEL];
__device__ __half g_hxv[MROWS * DMODEL];
__device__ __half g_hwq[DMODEL * DMODEL];   // [n][k]
__device__ __half g_hwk[DMODEL * DMODEL];
__device__ __half g_hwv[DMODEL * DMODEL];
__device__ __half g_hwo[DMODEL * DMODEL];   // [n][k]
__device__ __half g_hq[MROWS * DMODEL];
__device__ __half g_hk[MROWS * DMODEL];
__device__ __half g_hv[MROWS * DMODEL];
__device__ __half g_hz[MROWS * DMODEL];

// ---------------- helpers ----------------
__device__ __forceinline__ uint32_t smem_u32(const void* p) {
    uint32_t a;
    asm("{ .reg .u64 t; cvta.to.shared.u64 t, %1; cvt.u32.u64 %0, t; }" : "=r"(a) : "l"(p));
    return a;
}
__device__ __forceinline__ uint32_t pack_h2(float a, float b) {
    __half2 h = __float22half2_rn(make_float2(a, b));
    return *reinterpret_cast<uint32_t*>(&h);
}
__device__ __forceinline__ uint32_t prmt(uint32_t a, uint32_t b, uint32_t sel) {
    uint32_t r;
    asm("prmt.b32 %0, %1, %2, %3;" : "=r"(r) : "r"(a), "r"(b), "r"(sel));
    return r;
}
__device__ __forceinline__ void cp_async16(uint32_t dst, const void* src) {
    asm volatile("cp.async.cg.shared.global [%0], [%1], 16;" :: "r"(dst), "l"(src));
}
__device__ __forceinline__ void cp_commit() {
    asm volatile("cp.async.commit_group;" ::: "memory");
}
template <int N>
__device__ __forceinline__ void cp_wait() {
    asm volatile("cp.async.wait_group %0;" :: "n"(N) : "memory");
}
__device__ __forceinline__ void mma_f16_16x8x16(
    float* d, const uint32_t* a, const uint32_t* b, const float* c)
{
    asm volatile(
        "mma.sync.aligned.m16n8k16.row.col.f32.f16.f16.f32 "
        "{%0,%1,%2,%3}, {%4,%5,%6,%7}, {%8,%9}, {%10,%11,%12,%13};\n"
        : "=f"(d[0]), "=f"(d[1]), "=f"(d[2]), "=f"(d[3])
        : "r"(a[0]), "r"(a[1]), "r"(a[2]), "r"(a[3]),
          "r"(b[0]), "r"(b[1]),
          "f"(c[0]), "f"(c[1]), "f"(c[2]), "f"(c[3]));
}

// ================= conversion kernels =================
__global__ void conv_x(const float* __restrict__ xq, const float* __restrict__ xk,
                       const float* __restrict__ xv,
                       __half* __restrict__ hq, __half* __restrict__ hk,
                       __half* __restrict__ hv)
{
    const float* src = (blockIdx.y == 0) ? xq : (blockIdx.y == 1) ? xk : xv;
    __half* dst = (blockIdx.y == 0) ? hq : (blockIdx.y == 1) ? hk : hv;
    int idx = blockIdx.x * 256 + threadIdx.x;     // float4 index
    float4 v = *(const float4*)(src + (size_t)idx * 4);
    uint32_t* d = (uint32_t*)(dst + (size_t)idx * 4);
    d[0] = pack_h2(v.x, v.y);
    d[1] = pack_h2(v.z, v.w);
}

// QKV weights: W[h][k][d] f32 -> hw[(h*64+d)][k] half. grid (16 ktile, 16 h, 3)
__global__ void conv_w(const float* __restrict__ wq, const float* __restrict__ wk,
                       const float* __restrict__ wv,
                       __half* __restrict__ hwq, __half* __restrict__ hwk,
                       __half* __restrict__ hwv)
{
    __shared__ float s[64][65];
    const float* W = (blockIdx.z == 0) ? wq : (blockIdx.z == 1) ? wk : wv;
    __half* hw = (blockIdx.z == 0) ? hwq : (blockIdx.z == 1) ? hwk : hwv;
    const int k0 = blockIdx.x * 64;
    const int h  = blockIdx.y;
    const int tid = threadIdx.x;
#pragma unroll
    for (int it = 0; it < 4; it++) {
        int idx = tid + it * 256;
        int kk = idx >> 4, d4 = (idx & 15) * 4;
        float4 v = *(const float4*)(W + (size_t)h * DMODEL * DHEAD + (size_t)(k0 + kk) * DHEAD + d4);
        s[kk][d4 + 0] = v.x; s[kk][d4 + 1] = v.y;
        s[kk][d4 + 2] = v.z; s[kk][d4 + 3] = v.w;
    }
    __syncthreads();
    int d = tid >> 2, seg = (tid & 3) * 16;
    uint32_t* dst = (uint32_t*)(hw + (size_t)(h * 64 + d) * DMODEL + k0 + seg);
#pragma unroll
    for (int j = 0; j < 8; j++)
        dst[j] = pack_h2(s[seg + 2 * j][d], s[seg + 2 * j + 1][d]);
}

// W_O: w[k][n] f32 -> hwo[n][k] half. grid (16 ktile, 16 ntile)
__global__ void conv_wo(const float* __restrict__ w, __half* __restrict__ hwo)
{
    __shared__ float s[64][65];
    const int k0 = blockIdx.x * 64;
    const int n0 = blockIdx.y * 64;
    const int tid = threadIdx.x;
#pragma unroll
    for (int it = 0; it < 4; it++) {
        int idx = tid + it * 256;
        int kk = idx >> 4, n4 = (idx & 15) * 4;
        float4 v = *(const float4*)(w + (size_t)(k0 + kk) * DMODEL + n0 + n4);
        s[kk][n4 + 0] = v.x; s[kk][n4 + 1] = v.y;
        s[kk][n4 + 2] = v.z; s[kk][n4 + 3] = v.w;
    }
    __syncthreads();
    int n = tid >> 2, seg = (tid & 3) * 16;
    uint32_t* dst = (uint32_t*)(hwo + (size_t)(n0 + n) * DMODEL + k0 + seg);
#pragma unroll
    for (int j = 0; j < 8; j++)
        dst[j] = pack_h2(s[seg + 2 * j][n], s[seg + 2 * j + 1][n]);
}

// ============ half GEMM, cp.async double-buffered (unchanged from R10) ============
#define TSg 36
#define GEMM_SMEM (4 * 128 * TSg * 4)   // 73,728 B

__device__ __forceinline__ void gemm_pipe(
    const __half* __restrict__ A, const __half* __restrict__ B,
    uint32_t* smg, int n0, int m0, float acc[4][4][4])
{
    uint32_t* AsF[2] = { smg, smg + 128 * TSg };
    uint32_t* BsF[2] = { smg + 256 * TSg, smg + 384 * TSg };
    const uint32_t sA[2] = { smem_u32(AsF[0]), smem_u32(AsF[1]) };
    const uint32_t sB[2] = { smem_u32(BsF[0]), smem_u32(BsF[1]) };

    const int tid = threadIdx.x;
    const int wid = tid >> 5;
    const int lid = tid & 31;
    const int g   = lid >> 2;
    const int tig = lid & 3;
    const int wm  = wid >> 2;
    const int wn  = wid & 3;

#pragma unroll
    for (int i = 0; i < 4; i++)
#pragma unroll
        for (int j = 0; j < 4; j++)
#pragma unroll
            for (int f = 0; f < 4; f++) acc[i][j][f] = 0.0f;

    auto load_chunk = [&](int c, int buf) {
        const int k0 = c * 64;
#pragma unroll
        for (int it = 0; it < 4; it++) {
            int i = tid + it * 256;
            int row = i >> 3, j = i & 7;
            cp_async16(sA[buf] + (uint32_t)(row * TSg + j * 4) * 4,
                       A + (size_t)(m0 + row) * DMODEL + k0 + j * 8);
            cp_async16(sB[buf] + (uint32_t)(row * TSg + j * 4) * 4,
                       B + (size_t)(n0 + row) * DMODEL + k0 + j * 8);
        }
        cp_commit();
    };

    load_chunk(0, 0);
    const int NCH = DMODEL / 64;   // 16
    for (int c = 0; c < NCH; c++) {
        if (c + 1 < NCH) {
            load_chunk(c + 1, (c + 1) & 1);
            cp_wait<1>();
        } else {
            cp_wait<0>();
        }
        __syncthreads();

        const uint32_t* As_ = AsF[c & 1];
        const uint32_t* Bs_ = BsF[c & 1];
#pragma unroll
        for (int kk = 0; kk < 4; kk++) {
            uint32_t af[4][4], bf[4][2];
#pragma unroll
            for (int mi = 0; mi < 4; mi++) {
                int r = wm * 64 + mi * 16 + g;
                af[mi][0] = As_[r * TSg + kk * 8 + tig];
                af[mi][1] = As_[(r + 8) * TSg + kk * 8 + tig];
                af[mi][2] = As_[r * TSg + kk * 8 + tig + 4];
                af[mi][3] = As_[(r + 8) * TSg + kk * 8 + tig + 4];
            }
#pragma unroll
            for (int nj = 0; nj < 4; nj++) {
                int n = wn * 32 + nj * 8 + g;
                bf[nj][0] = Bs_[n * TSg + kk * 8 + tig];
                bf[nj][1] = Bs_[n * TSg + kk * 8 + tig + 4];
            }
#pragma unroll
            for (int mi = 0; mi < 4; mi++)
#pragma unroll
                for (int nj = 0; nj < 4; nj++)
                    mma_f16_16x8x16(acc[mi][nj], af[mi], bf[nj], acc[mi][nj]);
        }
        __syncthreads();
    }
}

__global__ __launch_bounds__(256, 2) void qkv_gemm(
    const __half* __restrict__ xq, const __half* __restrict__ xk, const __half* __restrict__ xv,
    const __half* __restrict__ wq, const __half* __restrict__ wk, const __half* __restrict__ wv,
    const float* __restrict__ bq, const float* __restrict__ bk, const float* __restrict__ bv,
    __half* __restrict__ cq, __half* __restrict__ ck, __half* __restrict__ cv)
{
    extern __shared__ uint32_t smg[];
    const __half* A = (blockIdx.z == 0) ? xq : (blockIdx.z == 1) ? xk : xv;
    const __half* B = (blockIdx.z == 0) ? wq : (blockIdx.z == 1) ? wk : wv;
    const float* bias = (blockIdx.z == 0) ? bq : (blockIdx.z == 1) ? bk : bv;
    __half*      C = (blockIdx.z == 0) ? cq : (blockIdx.z == 1) ? ck : cv;
    const int n0 = blockIdx.x * 128, m0 = blockIdx.y * 128;

    float acc[4][4][4];
    gemm_pipe(A, B, smg, n0, m0, acc);

    const int lid = threadIdx.x & 31;
    const int g = lid >> 2, tig = lid & 3;
    const int wm = (threadIdx.x >> 5) >> 2, wn = (threadIdx.x >> 5) & 3;
#pragma unroll
    for (int mi = 0; mi < 4; mi++) {
        int r0 = m0 + wm * 64 + mi * 16 + g;
#pragma unroll
        for (int nj = 0; nj < 4; nj++) {
            int c0 = n0 + wn * 32 + nj * 8 + tig * 2;
            float b0 = bias[c0], b1 = bias[c0 + 1];
            *(uint32_t*)(C + (size_t)r0 * DMODEL + c0) =
                pack_h2(acc[mi][nj][0] + b0, acc[mi][nj][1] + b1);
            *(uint32_t*)(C + (size_t)(r0 + 8) * DMODEL + c0) =
                pack_h2(acc[mi][nj][2] + b0, acc[mi][nj][3] + b1);
        }
    }
}

__global__ __launch_bounds__(256, 2) void wo_gemm(
    const __half* __restrict__ A, const __half* __restrict__ B,
    const float* __restrict__ bias, float* __restrict__ C)
{
    extern __shared__ uint32_t smg[];
    const int n0 = blockIdx.x * 128, m0 = blockIdx.y * 128;

    float acc[4][4][4];
    gemm_pipe(A, B, smg, n0, m0, acc);

    const int lid = threadIdx.x & 31;
    const int g = lid >> 2, tig = lid & 3;
    const int wm = (threadIdx.x >> 5) >> 2, wn = (threadIdx.x >> 5) & 3;
#pragma unroll
    for (int mi = 0; mi < 4; mi++) {
        int r0 = m0 + wm * 64 + mi * 16 + g;
#pragma unroll
        for (int nj = 0; nj < 4; nj++) {
            int c0 = n0 + wn * 32 + nj * 8 + tig * 2;
            float b0 = bias[c0], b1 = bias[c0 + 1];
            *(float2*)(C + (size_t)r0 * DMODEL + c0) =
                make_float2(acc[mi][nj][0] + b0, acc[mi][nj][1] + b1);
            *(float2*)(C + (size_t)(r0 + 8) * DMODEL + c0) =
                make_float2(acc[mi][nj][2] + b0, acc[mi][nj][3] + b1);
        }
    }
}

// ============ flash attention, all-half I/O, register-prefetched K/V ============
#define FSH 36

__global__ __launch_bounds__(256, 2) void flash_attn_h(
    const __half* __restrict__ q, const __half* __restrict__ k,
    const __half* __restrict__ v, const float* __restrict__ amask,
    __half* __restrict__ z)
{
    extern __shared__ uint32_t sm[];
    uint32_t* Qs = sm;                   // 128 x FSH
    uint32_t* Ks = sm + 128 * FSH;       // 64 x FSH
    uint32_t* Ps = sm + 192 * FSH;       // 128 x FSH
    uint32_t* Vt = sm + 320 * FSH;       // 64 x FSH

    const int qt = (int)(gridDim.x - 1 - blockIdx.x);
    const int h  = blockIdx.y;
    const int b  = blockIdx.z;
    const int tid = threadIdx.x;
    const int wid = tid >> 5;
    const int lid = tid & 31;
    const int g   = lid >> 2;
    const int tig = lid & 3;
    const int r0  = wid * 16;

    const size_t base = (size_t)b * S_LEN;
    const __half* qp = q + (base + qt * 128) * DMODEL + h * 64;

    // Q tile: 128 rows x 64 halfs = 1024 uint4 (8 per row)
#pragma unroll
    for (int it = 0; it < 4; it++) {
        int i = tid + it * 256;          // 0..1023
        int row = i >> 3, j = i & 7;
        *(uint4*)(Qs + row * FSH + j * 4) =
            *(const uint4*)((const char*)(qp + (size_t)row * DMODEL) + j * 16);
    }

    float o[8][4];
#pragma unroll
    for (int nj = 0; nj < 8; nj++)
#pragma unroll
        for (int f = 0; f < 4; f++) o[nj][f] = 0.0f;
    float mrow0 = -1e30f, mrow1 = -1e30f;
    float lrow0 = 0.0f,  lrow1 = 0.0f;

    const int qi0 = qt * 128 + r0 + g;
    const int qi1 = qi0 + 8;
    const int nkt = 2 * (qt + 1);

    // per-thread loader coordinates
    const int krow0 = tid >> 3,         kj0 = tid & 7;          // K uint4 #1
    const int krow1 = (tid + 256) >> 3, kj1 = tid & 7;          // K uint4 #2
    const int vp_pair = tid & 31;        // kpos pair 0..31
    const int vdq     = tid >> 5;        // d octet 0..7

    // prefetch registers (hold tile kt during iteration kt)
    uint4 kr0, kr1, vr0, vr1;
    {
        const __half* kp = k + base * DMODEL + h * 64;   // kt = 0
        const __half* vp = v + base * DMODEL + h * 64;
        kr0 = *(const uint4*)((const char*)(kp + (size_t)krow0 * DMODEL) + kj0 * 16);
        kr1 = *(const uint4*)((const char*)(kp + (size_t)krow1 * DMODEL) + kj1 * 16);
        vr0 = *(const uint4*)(vp + (size_t)(2 * vp_pair) * DMODEL + vdq * 8);
        vr1 = *(const uint4*)(vp + (size_t)(2 * vp_pair + 1) * DMODEL + vdq * 8);
    }

    for (int kt = 0; kt < nkt; kt++) {
        __syncthreads();   // all warps done reading Ks/Vt of previous tile

        // ---- store prefetched tile into smem ----
        *(uint4*)(Ks + krow0 * FSH + kj0 * 4) = kr0;
        *(uint4*)(Ks + krow1 * FSH + kj1 * 4) = kr1;
        {
            int dbase = vdq * 8;
            Vt[(dbase + 0) * FSH + vp_pair] = prmt(vr0.x, vr1.x, 0x5410);
            Vt[(dbase + 1) * FSH + vp_pair] = prmt(vr0.x, vr1.x, 0x7632);
            Vt[(dbase + 2) * FSH + vp_pair] = prmt(vr0.y, vr1.y, 0x5410);
            Vt[(dbase + 3) * FSH + vp_pair] = prmt(vr0.y, vr1.y, 0x7632);
            Vt[(dbase + 4) * FSH + vp_pair] = prmt(vr0.z, vr1.z, 0x5410);
            Vt[(dbase + 5) * FSH + vp_pair] = prmt(vr0.z, vr1.z, 0x7632);
            Vt[(dbase + 6) * FSH + vp_pair] = prmt(vr0.w, vr1.w, 0x5410);
            Vt[(dbase + 7) * FSH + vp_pair] = prmt(vr0.w, vr1.w, 0x7632);
        }
        __syncthreads();

        // ---- issue prefetch for next tile (overlaps with compute below) ----
        if (kt + 1 < nkt) {
            const __half* kp = k + (base + (kt + 1) * 64) * DMODEL + h * 64;
            const __half* vp = v + (base + (kt + 1) * 64) * DMODEL + h * 64;
            kr0 = *(const uint4*)((const char*)(kp + (size_t)krow0 * DMODEL) + kj0 * 16);
            kr1 = *(const uint4*)((const char*)(kp + (size_t)krow1 * DMODEL) + kj1 * 16);
            vr0 = *(const uint4*)(vp + (size_t)(2 * vp_pair) * DMODEL + vdq * 8);
            vr1 = *(const uint4*)(vp + (size_t)(2 * vp_pair + 1) * DMODEL + vdq * 8);
        }

        // ---- S = Q K^T ----
        float sacc[8][4];
#pragma unroll
        for (int nj = 0; nj < 8; nj++)
#pragma unroll
            for (int f = 0; f < 4; f++) sacc[nj][f] = 0.0f;

#pragma unroll
        for (int kk = 0; kk < 4; kk++) {
            uint32_t a[4];
            a[0] = Qs[(r0 + g) * FSH + kk * 8 + tig];
            a[1] = Qs[(r0 + g + 8) * FSH + kk * 8 + tig];
            a[2] = Qs[(r0 + g) * FSH + kk * 8 + tig + 4];
            a[3] = Qs[(r0 + g + 8) * FSH + kk * 8 + tig + 4];
#pragma unroll
            for (int nj = 0; nj < 8; nj++) {
                uint32_t bb[2];
                bb[0] = Ks[(nj * 8 + g) * FSH + kk * 8 + tig];
                bb[1] = Ks[(nj * 8 + g) * FSH + kk * 8 + tig + 4];
                mma_f16_16x8x16(sacc[nj], a, bb, sacc[nj]);
            }
        }

        // ---- scale, causal, additive mask ----
        float tmax0 = -1e30f, tmax1 = -1e30f;
#pragma unroll
        for (int nj = 0; nj < 8; nj++) {
            int kj = kt * 64 + nj * 8 + tig * 2;
            float am0 = amask[b * S_LEN + kj];
            float am1 = amask[b * S_LEN + kj + 1];
            float s0 = ((kj     <= qi0) ? sacc[nj][0] * 0.125f : IGNORE_VAL) + am0;
            float s1 = ((kj + 1 <= qi0) ? sacc[nj][1] * 0.125f : IGNORE_VAL) + am1;
            float s2 = ((kj     <= qi1) ? sacc[nj][2] * 0.125f : IGNORE_VAL) + am0;
            float s3 = ((kj + 1 <= qi1) ? sacc[nj][3] * 0.125f : IGNORE_VAL) + am1;
            sacc[nj][0] = s0; sacc[nj][1] = s1; sacc[nj][2] = s2; sacc[nj][3] = s3;
            tmax0 = fmaxf(tmax0, fmaxf(s0, s1));
            tmax1 = fmaxf(tmax1, fmaxf(s2, s3));
        }
        tmax0 = fmaxf(tmax0, __shfl_xor_sync(0xffffffffu, tmax0, 1));
        tmax0 = fmaxf(tmax0, __shfl_xor_sync(0xffffffffu, tmax0, 2));
        tmax1 = fmaxf(tmax1, __shfl_xor_sync(0xffffffffu, tmax1, 1));
        tmax1 = fmaxf(tmax1, __shfl_xor_sync(0xffffffffu, tmax1, 2));

        float mn0 = fmaxf(mrow0, tmax0);
        float mn1 = fmaxf(mrow1, tmax1);
        float alpha0 = __expf(mrow0 - mn0);
        float alpha1 = __expf(mrow1 - mn1);
        mrow0 = mn0; mrow1 = mn1;

        float rs0 = 0.0f, rs1 = 0.0f;
#pragma unroll
        for (int nj = 0; nj < 8; nj++) {
            float p0 = __expf(sacc[nj][0] - mn0);
            float p1 = __expf(sacc[nj][1] - mn0);
            float p2 = __expf(sacc[nj][2] - mn1);
            float p3 = __expf(sacc[nj][3] - mn1);
            sacc[nj][0] = p0; sacc[nj][1] = p1; sacc[nj][2] = p2; sacc[nj][3] = p3;
            rs0 += p0 + p1;
            rs1 += p2 + p3;
        }
        rs0 += __shfl_xor_sync(0xffffffffu, rs0, 1);
        rs0 += __shfl_xor_sync(0xffffffffu, rs0, 2);
        rs1 += __shfl_xor_sync(0xffffffffu, rs1, 1);
        rs1 += __shfl_xor_sync(0xffffffffu, rs1, 2);
        lrow0 = lrow0 * alpha0 + rs0;
        lrow1 = lrow1 * alpha1 + rs1;

#pragma unroll
        for (int nj = 0; nj < 8; nj++) {
            o[nj][0] *= alpha0; o[nj][1] *= alpha0;
            o[nj][2] *= alpha1; o[nj][3] *= alpha1;
        }

#pragma unroll
        for (int nj = 0; nj < 8; nj++) {
            Ps[(r0 + g) * FSH + nj * 4 + tig]     = pack_h2(sacc[nj][0], sacc[nj][1]);
            Ps[(r0 + g + 8) * FSH + nj * 4 + tig] = pack_h2(sacc[nj][2], sacc[nj][3]);
        }
        __syncwarp();

#pragma unroll
        for (int kk = 0; kk < 4; kk++) {
            uint32_t a[4];
            a[0] = Ps[(r0 + g) * FSH + kk * 8 + tig];
            a[1] = Ps[(r0 + g + 8) * FSH + kk * 8 + tig];
            a[2] = Ps[(r0 + g) * FSH + kk * 8 + tig + 4];
            a[3] = Ps[(r0 + g + 8) * FSH + kk * 8 + tig + 4];
#pragma unroll
            for (int nj = 0; nj < 8; nj++) {
                uint32_t bb[2];
                bb[0] = Vt[(nj * 8 + g) * FSH + kk * 8 + tig];
                bb[1] = Vt[(nj * 8 + g) * FSH + kk * 8 + tig + 4];
                mma_f16_16x8x16(o[nj], a, bb, o[nj]);
            }
        }
    }

    // ---- epilogue: write z as half ----
    float inv0 = 1.0f / lrow0;
    float inv1 = 1.0f / lrow1;
    const size_t row0 = base + qt * 128 + r0 + g;
#pragma unroll
    for (int nj = 0; nj < 8; nj++) {
        int col = h * 64 + nj * 8 + tig * 2;
        *(uint32_t*)(z + row0 * DMODEL + col) =
            pack_h2(o[nj][0] * inv0, o[nj][1] * inv0);
        *(uint32_t*)(z + (row0 + 8) * DMODEL + col) =
            pack_h2(o[nj][2] * inv1, o[nj][3] * inv1);
    }
}

// ---------------- launch ----------------
extern "C" void kernel_launch(void* const* d_in, const int* in_sizes, int n_in,
                              void* d_out, int out_size)
{
    const float* x_q  = (const float*)d_in[0];
    const float* x_k  = (const float*)d_in[1];
    const float* x_v  = (const float*)d_in[2];
    const float* amsk = (const float*)d_in[3];
    const float* w_q  = (const float*)d_in[4];
    const float* w_k  = (const float*)d_in[5];
    const float* w_v  = (const float*)d_in[6];
    const float* w_o  = (const float*)d_in[7];
    const float* b_q  = (const float*)d_in[8];
    const float* b_k  = (const float*)d_in[9];
    const float* b_v  = (const float*)d_in[10];
    const float* b_o  = (const float*)d_in[11];
    float* out = (float*)d_out;

    __half *hxq, *hxk, *hxv, *hwq, *hwk, *hwv, *hwo, *hq, *hk, *hv, *hz;
    cudaGetSymbolAddress((void**)&hxq, g_hxq);
    cudaGetSymbolAddress((void**)&hxk, g_hxk);
    cudaGetSymbolAddress((void**)&hxv, g_hxv);
    cudaGetSymbolAddress((void**)&hwq, g_hwq);
    cudaGetSymbolAddress((void**)&hwk, g_hwk);
    cudaGetSymbolAddress((void**)&hwv, g_hwv);
    cudaGetSymbolAddress((void**)&hwo, g_hwo);
    cudaGetSymbolAddress((void**)&hq,  g_hq);
    cudaGetSymbolAddress((void**)&hk,  g_hk);
    cudaGetSymbolAddress((void**)&hv,  g_hv);
    cudaGetSymbolAddress((void**)&hz,  g_hz);

    int fl_smem = 384 * FSH * sizeof(uint32_t);   // 55,296 B
    cudaFuncSetAttribute(flash_attn_h, cudaFuncAttributeMaxDynamicSharedMemorySize, fl_smem);
    cudaFuncSetAttribute(qkv_gemm, cudaFuncAttributeMaxDynamicSharedMemorySize, GEMM_SMEM);
    cudaFuncSetAttribute(wo_gemm, cudaFuncAttributeMaxDynamicSharedMemorySize, GEMM_SMEM);

    // conversions
    dim3 cxg(MROWS * DMODEL / (256 * 4), 3);
    conv_x<<<cxg, 256>>>(x_q, x_k, x_v, hxq, hxk, hxv);
    dim3 cwg(DMODEL / 64, NHEADS, 3);
    conv_w<<<cwg, 256>>>(w_q, w_k, w_v, hwq, hwk, hwv);
    dim3 cog(DMODEL / 64, DMODEL / 64);
    conv_wo<<<cog, 256>>>(w_o, hwo);

    // QKV projections
    dim3 qgrid(DMODEL / 128, MROWS / 128, 3);
    qkv_gemm<<<qgrid, 256, GEMM_SMEM>>>(hxq, hxk, hxv, hwq, hwk, hwv,
                                        b_q, b_k, b_v, hq, hk, hv);

    // flash attention
    dim3 fgrid(S_LEN / 128, NHEADS, BATCH);
    flash_attn_h<<<fgrid, 256, fl_smem>>>(hq, hk, hv, amsk, hz);

    // output projection
    dim3 ogrid(DMODEL / 128, MROWS / 128);
    wo_gemm<<<ogrid, 256, GEMM_SMEM>>>(hz, hwo, b_o, out);

    (void)in_sizes; (void)n_in; (void)out_size;
}

// round 12
// speedup vs baseline: 2.0564x; 1.0703x over previous
#include <cuda_runtime.h>
#include <cuda_fp16.h>
#include <cstdint>
#include <math.h>

#define S_LEN   2048
#define BATCH   2
#define DMODEL  1024
#define NHEADS  16
#define DHEAD   64
#define MROWS   (BATCH * S_LEN)   // 4096
#define IGNORE_VAL (-100000.0f)

// ---------------- scratch (half everywhere) ----------------
__device__ __half g_hxq[MROWS * DMODEL];
__device__ __half g_hxk[MROWS * DMODEL];
__device__ __half g_hxv[MROWS * DMODEL];
__device__ __half g_hwq[DMODEL * DMODEL];   // [n][k]
__device__ __half g_hwk[DMODEL * DMODEL];
__device__ __half g_hwv[DMODEL * DMODEL];
__device__ __half g_hwo[DMODEL * DMODEL];   // [n][k]
__device__ __half g_hq[MROWS * DMODEL];
__device__ __half g_hk[MROWS * DMODEL];
__device__ __half g_hv[MROWS * DMODEL];
__device__ __half g_hz[MROWS * DMODEL];

// ---------------- helpers ----------------
__device__ __forceinline__ uint32_t smem_u32(const void* p) {
    uint32_t a;
    asm("{ .reg .u64 t; cvta.to.shared.u64 t, %1; cvt.u32.u64 %0, t; }" : "=r"(a) : "l"(p));
    return a;
}
__device__ __forceinline__ uint32_t pack_h2(float a, float b) {
    __half2 h = __float22half2_rn(make_float2(a, b));
    return *reinterpret_cast<uint32_t*>(&h);
}
__device__ __forceinline__ uint32_t prmt(uint32_t a, uint32_t b, uint32_t sel) {
    uint32_t r;
    asm("prmt.b32 %0, %1, %2, %3;" : "=r"(r) : "r"(a), "r"(b), "r"(sel));
    return r;
}
__device__ __forceinline__ void cp_async16(uint32_t dst, const void* src) {
    asm volatile("cp.async.cg.shared.global [%0], [%1], 16;" :: "r"(dst), "l"(src));
}
__device__ __forceinline__ void cp_commit() {
    asm volatile("cp.async.commit_group;" ::: "memory");
}
template <int N>
__device__ __forceinline__ void cp_wait() {
    asm volatile("cp.async.wait_group %0;" :: "n"(N) : "memory");
}
__device__ __forceinline__ void mma_f16_16x8x16(
    float* d, const uint32_t* a, const uint32_t* b, const float* c)
{
    asm volatile(
        "mma.sync.aligned.m16n8k16.row.col.f32.f16.f16.f32 "
        "{%0,%1,%2,%3}, {%4,%5,%6,%7}, {%8,%9}, {%10,%11,%12,%13};\n"
        : "=f"(d[0]), "=f"(d[1]), "=f"(d[2]), "=f"(d[3])
        : "r"(a[0]), "r"(a[1]), "r"(a[2]), "r"(a[3]),
          "r"(b[0]), "r"(b[1]),
          "f"(c[0]), "f"(c[1]), "f"(c[2]), "f"(c[3]));
}

// ================= conversion kernels =================
__global__ void conv_x(const float* __restrict__ xq, const float* __restrict__ xk,
                       const float* __restrict__ xv,
                       __half* __restrict__ hq, __half* __restrict__ hk,
                       __half* __restrict__ hv)
{
    const float* src = (blockIdx.y == 0) ? xq : (blockIdx.y == 1) ? xk : xv;
    __half* dst = (blockIdx.y == 0) ? hq : (blockIdx.y == 1) ? hk : hv;
    int idx = blockIdx.x * 256 + threadIdx.x;     // float4 index
    float4 v = *(const float4*)(src + (size_t)idx * 4);
    uint32_t* d = (uint32_t*)(dst + (size_t)idx * 4);
    d[0] = pack_h2(v.x, v.y);
    d[1] = pack_h2(v.z, v.w);
}

// QKV weights: W[h][k][d] f32 -> hw[(h*64+d)][k] half. grid (16 ktile, 16 h, 3)
__global__ void conv_w(const float* __restrict__ wq, const float* __restrict__ wk,
                       const float* __restrict__ wv,
                       __half* __restrict__ hwq, __half* __restrict__ hwk,
                       __half* __restrict__ hwv)
{
    __shared__ float s[64][65];
    const float* W = (blockIdx.z == 0) ? wq : (blockIdx.z == 1) ? wk : wv;
    __half* hw = (blockIdx.z == 0) ? hwq : (blockIdx.z == 1) ? hwk : hwv;
    const int k0 = blockIdx.x * 64;
    const int h  = blockIdx.y;
    const int tid = threadIdx.x;
#pragma unroll
    for (int it = 0; it < 4; it++) {
        int idx = tid + it * 256;
        int kk = idx >> 4, d4 = (idx & 15) * 4;
        float4 v = *(const float4*)(W + (size_t)h * DMODEL * DHEAD + (size_t)(k0 + kk) * DHEAD + d4);
        s[kk][d4 + 0] = v.x; s[kk][d4 + 1] = v.y;
        s[kk][d4 + 2] = v.z; s[kk][d4 + 3] = v.w;
    }
    __syncthreads();
    int d = tid >> 2, seg = (tid & 3) * 16;
    uint32_t* dst = (uint32_t*)(hw + (size_t)(h * 64 + d) * DMODEL + k0 + seg);
#pragma unroll
    for (int j = 0; j < 8; j++)
        dst[j] = pack_h2(s[seg + 2 * j][d], s[seg + 2 * j + 1][d]);
}

// W_O: w[k][n] f32 -> hwo[n][k] half. grid (16 ktile, 16 ntile)
__global__ void conv_wo(const float* __restrict__ w, __half* __restrict__ hwo)
{
    __shared__ float s[64][65];
    const int k0 = blockIdx.x * 64;
    const int n0 = blockIdx.y * 64;
    const int tid = threadIdx.x;
#pragma unroll
    for (int it = 0; it < 4; it++) {
        int idx = tid + it * 256;
        int kk = idx >> 4, n4 = (idx & 15) * 4;
        float4 v = *(const float4*)(w + (size_t)(k0 + kk) * DMODEL + n0 + n4);
        s[kk][n4 + 0] = v.x; s[kk][n4 + 1] = v.y;
        s[kk][n4 + 2] = v.z; s[kk][n4 + 3] = v.w;
    }
    __syncthreads();
    int n = tid >> 2, seg = (tid & 3) * 16;
    uint32_t* dst = (uint32_t*)(hwo + (size_t)(n0 + n) * DMODEL + k0 + seg);
#pragma unroll
    for (int j = 0; j < 8; j++)
        dst[j] = pack_h2(s[seg + 2 * j][n], s[seg + 2 * j + 1][n]);
}

// ============ half GEMM, cp.async double-buffered (unchanged) ============
#define TSg 36
#define GEMM_SMEM (4 * 128 * TSg * 4)   // 73,728 B

__device__ __forceinline__ void gemm_pipe(
    const __half* __restrict__ A, const __half* __restrict__ B,
    uint32_t* smg, int n0, int m0, float acc[4][4][4])
{
    uint32_t* AsF[2] = { smg, smg + 128 * TSg };
    uint32_t* BsF[2] = { smg + 256 * TSg, smg + 384 * TSg };
    const uint32_t sA[2] = { smem_u32(AsF[0]), smem_u32(AsF[1]) };
    const uint32_t sB[2] = { smem_u32(BsF[0]), smem_u32(BsF[1]) };

    const int tid = threadIdx.x;
    const int wid = tid >> 5;
    const int lid = tid & 31;
    const int g   = lid >> 2;
    const int tig = lid & 3;
    const int wm  = wid >> 2;
    const int wn  = wid & 3;

#pragma unroll
    for (int i = 0; i < 4; i++)
#pragma unroll
        for (int j = 0; j < 4; j++)
#pragma unroll
            for (int f = 0; f < 4; f++) acc[i][j][f] = 0.0f;

    auto load_chunk = [&](int c, int buf) {
        const int k0 = c * 64;
#pragma unroll
        for (int it = 0; it < 4; it++) {
            int i = tid + it * 256;
            int row = i >> 3, j = i & 7;
            cp_async16(sA[buf] + (uint32_t)(row * TSg + j * 4) * 4,
                       A + (size_t)(m0 + row) * DMODEL + k0 + j * 8);
            cp_async16(sB[buf] + (uint32_t)(row * TSg + j * 4) * 4,
                       B + (size_t)(n0 + row) * DMODEL + k0 + j * 8);
        }
        cp_commit();
    };

    load_chunk(0, 0);
    const int NCH = DMODEL / 64;   // 16
    for (int c = 0; c < NCH; c++) {
        if (c + 1 < NCH) {
            load_chunk(c + 1, (c + 1) & 1);
            cp_wait<1>();
        } else {
            cp_wait<0>();
        }
        __syncthreads();

        const uint32_t* As_ = AsF[c & 1];
        const uint32_t* Bs_ = BsF[c & 1];
#pragma unroll
        for (int kk = 0; kk < 4; kk++) {
            uint32_t af[4][4], bf[4][2];
#pragma unroll
            for (int mi = 0; mi < 4; mi++) {
                int r = wm * 64 + mi * 16 + g;
                af[mi][0] = As_[r * TSg + kk * 8 + tig];
                af[mi][1] = As_[(r + 8) * TSg + kk * 8 + tig];
                af[mi][2] = As_[r * TSg + kk * 8 + tig + 4];
                af[mi][3] = As_[(r + 8) * TSg + kk * 8 + tig + 4];
            }
#pragma unroll
            for (int nj = 0; nj < 4; nj++) {
                int n = wn * 32 + nj * 8 + g;
                bf[nj][0] = Bs_[n * TSg + kk * 8 + tig];
                bf[nj][1] = Bs_[n * TSg + kk * 8 + tig + 4];
            }
#pragma unroll
            for (int mi = 0; mi < 4; mi++)
#pragma unroll
                for (int nj = 0; nj < 4; nj++)
                    mma_f16_16x8x16(acc[mi][nj], af[mi], bf[nj], acc[mi][nj]);
        }
        __syncthreads();
    }
}

__global__ __launch_bounds__(256, 2) void qkv_gemm(
    const __half* __restrict__ xq, const __half* __restrict__ xk, const __half* __restrict__ xv,
    const __half* __restrict__ wq, const __half* __restrict__ wk, const __half* __restrict__ wv,
    const float* __restrict__ bq, const float* __restrict__ bk, const float* __restrict__ bv,
    __half* __restrict__ cq, __half* __restrict__ ck, __half* __restrict__ cv)
{
    extern __shared__ uint32_t smg[];
    const __half* A = (blockIdx.z == 0) ? xq : (blockIdx.z == 1) ? xk : xv;
    const __half* B = (blockIdx.z == 0) ? wq : (blockIdx.z == 1) ? wk : wv;
    const float* bias = (blockIdx.z == 0) ? bq : (blockIdx.z == 1) ? bk : bv;
    __half*      C = (blockIdx.z == 0) ? cq : (blockIdx.z == 1) ? ck : cv;
    const int n0 = blockIdx.x * 128, m0 = blockIdx.y * 128;

    float acc[4][4][4];
    gemm_pipe(A, B, smg, n0, m0, acc);

    const int lid = threadIdx.x & 31;
    const int g = lid >> 2, tig = lid & 3;
    const int wm = (threadIdx.x >> 5) >> 2, wn = (threadIdx.x >> 5) & 3;
#pragma unroll
    for (int mi = 0; mi < 4; mi++) {
        int r0 = m0 + wm * 64 + mi * 16 + g;
#pragma unroll
        for (int nj = 0; nj < 4; nj++) {
            int c0 = n0 + wn * 32 + nj * 8 + tig * 2;
            float b0 = bias[c0], b1 = bias[c0 + 1];
            *(uint32_t*)(C + (size_t)r0 * DMODEL + c0) =
                pack_h2(acc[mi][nj][0] + b0, acc[mi][nj][1] + b1);
            *(uint32_t*)(C + (size_t)(r0 + 8) * DMODEL + c0) =
                pack_h2(acc[mi][nj][2] + b0, acc[mi][nj][3] + b1);
        }
    }
}

__global__ __launch_bounds__(256, 2) void wo_gemm(
    const __half* __restrict__ A, const __half* __restrict__ B,
    const float* __restrict__ bias, float* __restrict__ C)
{
    extern __shared__ uint32_t smg[];
    const int n0 = blockIdx.x * 128, m0 = blockIdx.y * 128;

    float acc[4][4][4];
    gemm_pipe(A, B, smg, n0, m0, acc);

    const int lid = threadIdx.x & 31;
    const int g = lid >> 2, tig = lid & 3;
    const int wm = (threadIdx.x >> 5) >> 2, wn = (threadIdx.x >> 5) & 3;
#pragma unroll
    for (int mi = 0; mi < 4; mi++) {
        int r0 = m0 + wm * 64 + mi * 16 + g;
#pragma unroll
        for (int nj = 0; nj < 4; nj++) {
            int c0 = n0 + wn * 32 + nj * 8 + tig * 2;
            float b0 = bias[c0], b1 = bias[c0 + 1];
            *(float2*)(C + (size_t)r0 * DMODEL + c0) =
                make_float2(acc[mi][nj][0] + b0, acc[mi][nj][1] + b1);
            *(float2*)(C + (size_t)(r0 + 8) * DMODEL + c0) =
                make_float2(acc[mi][nj][2] + b0, acc[mi][nj][3] + b1);
        }
    }
}

// ============ flash attention: P-in-registers + double-buffered K/V ============
// smem (uint32 words, stride FSH=36):
//   Qs [0,128) | K0 [128,192) | V0t [192,256) | K1 [256,320) | V1t [320,384)
#define FSH 36

__global__ __launch_bounds__(256, 2) void flash_attn_h(
    const __half* __restrict__ q, const __half* __restrict__ k,
    const __half* __restrict__ v, const float* __restrict__ amask,
    __half* __restrict__ z)
{
    extern __shared__ uint32_t sm[];
    uint32_t* Qs = sm;                   // 128 x FSH

    const int qt = (int)(gridDim.x - 1 - blockIdx.x);
    const int h  = blockIdx.y;
    const int b  = blockIdx.z;
    const int tid = threadIdx.x;
    const int lid = tid & 31;
    const int g   = lid >> 2;
    const int tig = lid & 3;
    const int r0  = (tid >> 5) * 16;

    const size_t base = (size_t)b * S_LEN;
    const __half* qp = q + (base + qt * 128) * DMODEL + h * 64;

    // Q tile: 128 rows x 64 halfs = 1024 uint4 (8 per row)
#pragma unroll
    for (int it = 0; it < 4; it++) {
        int i = tid + it * 256;
        int row = i >> 3, j = i & 7;
        *(uint4*)(Qs + row * FSH + j * 4) =
            *(const uint4*)((const char*)(qp + (size_t)row * DMODEL) + j * 16);
    }

    float o[8][4];
#pragma unroll
    for (int nj = 0; nj < 8; nj++)
#pragma unroll
        for (int f = 0; f < 4; f++) o[nj][f] = 0.0f;
    float mrow0 = -1e30f, mrow1 = -1e30f;
    float lrow0 = 0.0f,  lrow1 = 0.0f;

    const int qi0 = qt * 128 + r0 + g;
    const int qi1 = qi0 + 8;
    const int nkt = 2 * (qt + 1);

    // per-thread loader coordinates
    const int krow0 = tid >> 3,         kj0 = tid & 7;
    const int krow1 = (tid + 256) >> 3, kj1 = tid & 7;
    const int vp_pair = tid & 31;
    const int vdq     = tid >> 5;

    uint4 kr0, kr1, vr0, vr1;
    auto load_regs = [&](int kt) {
        const __half* kp = k + (base + kt * 64) * DMODEL + h * 64;
        const __half* vp = v + (base + kt * 64) * DMODEL + h * 64;
        kr0 = *(const uint4*)((const char*)(kp + (size_t)krow0 * DMODEL) + kj0 * 16);
        kr1 = *(const uint4*)((const char*)(kp + (size_t)krow1 * DMODEL) + kj1 * 16);
        vr0 = *(const uint4*)(vp + (size_t)(2 * vp_pair) * DMODEL + vdq * 8);
        vr1 = *(const uint4*)(vp + (size_t)(2 * vp_pair + 1) * DMODEL + vdq * 8);
    };
    auto store_regs = [&](int buf) {
        uint32_t* Ksb = sm + (128 + buf * 128) * FSH;
        uint32_t* Vtb = Ksb + 64 * FSH;
        *(uint4*)(Ksb + krow0 * FSH + kj0 * 4) = kr0;
        *(uint4*)(Ksb + krow1 * FSH + kj1 * 4) = kr1;
        int dbase = vdq * 8;
        Vtb[(dbase + 0) * FSH + vp_pair] = prmt(vr0.x, vr1.x, 0x5410);
        Vtb[(dbase + 1) * FSH + vp_pair] = prmt(vr0.x, vr1.x, 0x7632);
        Vtb[(dbase + 2) * FSH + vp_pair] = prmt(vr0.y, vr1.y, 0x5410);
        Vtb[(dbase + 3) * FSH + vp_pair] = prmt(vr0.y, vr1.y, 0x7632);
        Vtb[(dbase + 4) * FSH + vp_pair] = prmt(vr0.z, vr1.z, 0x5410);
        Vtb[(dbase + 5) * FSH + vp_pair] = prmt(vr0.z, vr1.z, 0x7632);
        Vtb[(dbase + 6) * FSH + vp_pair] = prmt(vr0.w, vr1.w, 0x5410);
        Vtb[(dbase + 7) * FSH + vp_pair] = prmt(vr0.w, vr1.w, 0x7632);
    };

    // preamble: tile0 -> buf0; tile1 -> regs
    load_regs(0);
    store_regs(0);
    if (nkt > 1) load_regs(1);

    for (int kt = 0; kt < nkt; kt++) {
        __syncthreads();   // tile kt writes visible; readers of tile kt-1 done
        const int buf = kt & 1;
        const uint32_t* Ks = sm + (128 + buf * 128) * FSH;
        const uint32_t* Vt = Ks + 64 * FSH;

        // stage tile kt+1 into the other buffer; start loads for kt+2
        if (kt + 1 < nkt) store_regs(buf ^ 1);
        if (kt + 2 < nkt) load_regs(kt + 2);

        // ---- S = Q K^T ----
        float sacc[8][4];
#pragma unroll
        for (int nj = 0; nj < 8; nj++)
#pragma unroll
            for (int f = 0; f < 4; f++) sacc[nj][f] = 0.0f;

#pragma unroll
        for (int kk = 0; kk < 4; kk++) {
            uint32_t a[4];
            a[0] = Qs[(r0 + g) * FSH + kk * 8 + tig];
            a[1] = Qs[(r0 + g + 8) * FSH + kk * 8 + tig];
            a[2] = Qs[(r0 + g) * FSH + kk * 8 + tig + 4];
            a[3] = Qs[(r0 + g + 8) * FSH + kk * 8 + tig + 4];
#pragma unroll
            for (int nj = 0; nj < 8; nj++) {
                uint32_t bb[2];
                bb[0] = Ks[(nj * 8 + g) * FSH + kk * 8 + tig];
                bb[1] = Ks[(nj * 8 + g) * FSH + kk * 8 + tig + 4];
                mma_f16_16x8x16(sacc[nj], a, bb, sacc[nj]);
            }
        }

        // ---- scale, causal, additive mask ----
        float tmax0 = -1e30f, tmax1 = -1e30f;
#pragma unroll
        for (int nj = 0; nj < 8; nj++) {
            int kj = kt * 64 + nj * 8 + tig * 2;
            float am0 = amask[b * S_LEN + kj];
            float am1 = amask[b * S_LEN + kj + 1];
            float s0 = ((kj     <= qi0) ? sacc[nj][0] * 0.125f : IGNORE_VAL) + am0;
            float s1 = ((kj + 1 <= qi0) ? sacc[nj][1] * 0.125f : IGNORE_VAL) + am1;
            float s2 = ((kj     <= qi1) ? sacc[nj][2] * 0.125f : IGNORE_VAL) + am0;
            float s3 = ((kj + 1 <= qi1) ? sacc[nj][3] * 0.125f : IGNORE_VAL) + am1;
            sacc[nj][0] = s0; sacc[nj][1] = s1; sacc[nj][2] = s2; sacc[nj][3] = s3;
            tmax0 = fmaxf(tmax0, fmaxf(s0, s1));
            tmax1 = fmaxf(tmax1, fmaxf(s2, s3));
        }
        tmax0 = fmaxf(tmax0, __shfl_xor_sync(0xffffffffu, tmax0, 1));
        tmax0 = fmaxf(tmax0, __shfl_xor_sync(0xffffffffu, tmax0, 2));
        tmax1 = fmaxf(tmax1, __shfl_xor_sync(0xffffffffu, tmax1, 1));
        tmax1 = fmaxf(tmax1, __shfl_xor_sync(0xffffffffu, tmax1, 2));

        float mn0 = fmaxf(mrow0, tmax0);
        float mn1 = fmaxf(mrow1, tmax1);
        float alpha0 = __expf(mrow0 - mn0);
        float alpha1 = __expf(mrow1 - mn1);
        mrow0 = mn0; mrow1 = mn1;

        float rs0 = 0.0f, rs1 = 0.0f;
#pragma unroll
        for (int nj = 0; nj < 8; nj++) {
            float p0 = __expf(sacc[nj][0] - mn0);
            float p1 = __expf(sacc[nj][1] - mn0);
            float p2 = __expf(sacc[nj][2] - mn1);
            float p3 = __expf(sacc[nj][3] - mn1);
            sacc[nj][0] = p0; sacc[nj][1] = p1; sacc[nj][2] = p2; sacc[nj][3] = p3;
            rs0 += p0 + p1;
            rs1 += p2 + p3;
        }
        rs0 += __shfl_xor_sync(0xffffffffu, rs0, 1);
        rs0 += __shfl_xor_sync(0xffffffffu, rs0, 2);
        rs1 += __shfl_xor_sync(0xffffffffu, rs1, 1);
        rs1 += __shfl_xor_sync(0xffffffffu, rs1, 2);
        lrow0 = lrow0 * alpha0 + rs0;
        lrow1 = lrow1 * alpha1 + rs1;

#pragma unroll
        for (int nj = 0; nj < 8; nj++) {
            o[nj][0] *= alpha0; o[nj][1] *= alpha0;
            o[nj][2] *= alpha1; o[nj][3] *= alpha1;
        }

        // ---- O += P V : P stays in registers (S-accum layout == A-frag layout) ----
#pragma unroll
        for (int kk = 0; kk < 4; kk++) {
            uint32_t a[4];
            a[0] = pack_h2(sacc[2 * kk][0],     sacc[2 * kk][1]);
            a[1] = pack_h2(sacc[2 * kk][2],     sacc[2 * kk][3]);
            a[2] = pack_h2(sacc[2 * kk + 1][0], sacc[2 * kk + 1][1]);
            a[3] = pack_h2(sacc[2 * kk + 1][2], sacc[2 * kk + 1][3]);
#pragma unroll
            for (int nj = 0; nj < 8; nj++) {
                uint32_t bb[2];
                bb[0] = Vt[(nj * 8 + g) * FSH + kk * 8 + tig];
                bb[1] = Vt[(nj * 8 + g) * FSH + kk * 8 + tig + 4];
                mma_f16_16x8x16(o[nj], a, bb, o[nj]);
            }
        }
    }

    // ---- epilogue: write z as half ----
    float inv0 = 1.0f / lrow0;
    float inv1 = 1.0f / lrow1;
    const size_t row0 = base + qt * 128 + r0 + g;
#pragma unroll
    for (int nj = 0; nj < 8; nj++) {
        int col = h * 64 + nj * 8 + tig * 2;
        *(uint32_t*)(z + row0 * DMODEL + col) =
            pack_h2(o[nj][0] * inv0, o[nj][1] * inv0);
        *(uint32_t*)(z + (row0 + 8) * DMODEL + col) =
            pack_h2(o[nj][2] * inv1, o[nj][3] * inv1);
    }
}

// ---------------- launch ----------------
extern "C" void kernel_launch(void* const* d_in, const int* in_sizes, int n_in,
                              void* d_out, int out_size)
{
    const float* x_q  = (const float*)d_in[0];
    const float* x_k  = (const float*)d_in[1];
    const float* x_v  = (const float*)d_in[2];
    const float* amsk = (const float*)d_in[3];
    const float* w_q  = (const float*)d_in[4];
    const float* w_k  = (const float*)d_in[5];
    const float* w_v  = (const float*)d_in[6];
    const float* w_o  = (const float*)d_in[7];
    const float* b_q  = (const float*)d_in[8];
    const float* b_k  = (const float*)d_in[9];
    const float* b_v  = (const float*)d_in[10];
    const float* b_o  = (const float*)d_in[11];
    float* out = (float*)d_out;

    __half *hxq, *hxk, *hxv, *hwq, *hwk, *hwv, *hwo, *hq, *hk, *hv, *hz;
    cudaGetSymbolAddress((void**)&hxq, g_hxq);
    cudaGetSymbolAddress((void**)&hxk, g_hxk);
    cudaGetSymbolAddress((void**)&hxv, g_hxv);
    cudaGetSymbolAddress((void**)&hwq, g_hwq);
    cudaGetSymbolAddress((void**)&hwk, g_hwk);
    cudaGetSymbolAddress((void**)&hwv, g_hwv);
    cudaGetSymbolAddress((void**)&hwo, g_hwo);
    cudaGetSymbolAddress((void**)&hq,  g_hq);
    cudaGetSymbolAddress((void**)&hk,  g_hk);
    cudaGetSymbolAddress((void**)&hv,  g_hv);
    cudaGetSymbolAddress((void**)&hz,  g_hz);

    int fl_smem = 384 * FSH * sizeof(uint32_t);   // 55,296 B
    cudaFuncSetAttribute(flash_attn_h, cudaFuncAttributeMaxDynamicSharedMemorySize, fl_smem);
    cudaFuncSetAttribute(qkv_gemm, cudaFuncAttributeMaxDynamicSharedMemorySize, GEMM_SMEM);
    cudaFuncSetAttribute(wo_gemm, cudaFuncAttributeMaxDynamicSharedMemorySize, GEMM_SMEM);

    // conversions
    dim3 cxg(MROWS * DMODEL / (256 * 4), 3);
    conv_x<<<cxg, 256>>>(x_q, x_k, x_v, hxq, hxk, hxv);
    dim3 cwg(DMODEL / 64, NHEADS, 3);
    conv_w<<<cwg, 256>>>(w_q, w_k, w_v, hwq, hwk, hwv);
    dim3 cog(DMODEL / 64, DMODEL / 64);
    conv_wo<<<cog, 256>>>(w_o, hwo);

    // QKV projections
    dim3 qgrid(DMODEL / 128, MROWS / 128, 3);
    qkv_gemm<<<qgrid, 256, GEMM_SMEM>>>(hxq, hxk, hxv, hwq, hwk, hwv,
                                        b_q, b_k, b_v, hq, hk, hv);

    // flash attention
    dim3 fgrid(S_LEN / 128, NHEADS, BATCH);
    flash_attn_h<<<fgrid, 256, fl_smem>>>(hq, hk, hv, amsk, hz);

    // output projection
    dim3 ogrid(DMODEL / 128, MROWS / 128);
    wo_gemm<<<ogrid, 256, GEMM_SMEM>>>(hz, hwo, b_o, out);

    (void)in_sizes; (void)n_in; (void)out_size;
}

// round 13
// speedup vs baseline: 2.1740x; 1.0572x over previous
#include <cuda_runtime.h>
#include <cuda_fp16.h>
#include <cstdint>
#include <math.h>

#define S_LEN   2048
#define BATCH   2
#define DMODEL  1024
#define NHEADS  16
#define DHEAD   64
#define MROWS   (BATCH * S_LEN)   // 4096
#define IGNORE_VAL (-100000.0f)

// ---------------- scratch (half everywhere) ----------------
__device__ __half g_hxq[MROWS * DMODEL];
__device__ __half g_hxk[MROWS * DMODEL];
__device__ __half g_hxv[MROWS * DMODEL];
__device__ __half g_hwq[DMODEL * DMODEL];   // [n][k]
__device__ __half g_hwk[DMODEL * DMODEL];
__device__ __half g_hwv[DMODEL * DMODEL];
__device__ __half g_hwo[DMODEL * DMODEL];   // [n][k]
__device__ __half g_hq[MROWS * DMODEL];
__device__ __half g_hk[MROWS * DMODEL];
__device__ __half g_hv[MROWS * DMODEL];
__device__ __half g_hz[MROWS * DMODEL];

// ---------------- helpers ----------------
__device__ __forceinline__ uint32_t smem_u32(const void* p) {
    uint32_t a;
    asm("{ .reg .u64 t; cvta.to.shared.u64 t, %1; cvt.u32.u64 %0, t; }" : "=r"(a) : "l"(p));
    return a;
}
__device__ __forceinline__ uint32_t pack_h2(float a, float b) {
    __half2 h = __float22half2_rn(make_float2(a, b));
    return *reinterpret_cast<uint32_t*>(&h);
}
__device__ __forceinline__ uint32_t prmt(uint32_t a, uint32_t b, uint32_t sel) {
    uint32_t r;
    asm("prmt.b32 %0, %1, %2, %3;" : "=r"(r) : "r"(a), "r"(b), "r"(sel));
    return r;
}
__device__ __forceinline__ void cp_async16(uint32_t dst, const void* src) {
    asm volatile("cp.async.cg.shared.global [%0], [%1], 16;" :: "r"(dst), "l"(src));
}
__device__ __forceinline__ void cp_commit() {
    asm volatile("cp.async.commit_group;" ::: "memory");
}
template <int N>
__device__ __forceinline__ void cp_wait() {
    asm volatile("cp.async.wait_group %0;" :: "n"(N) : "memory");
}
__device__ __forceinline__ void ldsm_x4(uint32_t& r0, uint32_t& r1, uint32_t& r2, uint32_t& r3,
                                        uint32_t addr) {
    asm volatile("ldmatrix.sync.aligned.m8n8.x4.shared.b16 {%0,%1,%2,%3}, [%4];"
        : "=r"(r0), "=r"(r1), "=r"(r2), "=r"(r3) : "r"(addr));
}
__device__ __forceinline__ void mma_f16_16x8x16(
    float* d, const uint32_t* a, const uint32_t* b, const float* c)
{
    asm volatile(
        "mma.sync.aligned.m16n8k16.row.col.f32.f16.f16.f32 "
        "{%0,%1,%2,%3}, {%4,%5,%6,%7}, {%8,%9}, {%10,%11,%12,%13};\n"
        : "=f"(d[0]), "=f"(d[1]), "=f"(d[2]), "=f"(d[3])
        : "r"(a[0]), "r"(a[1]), "r"(a[2]), "r"(a[3]),
          "r"(b[0]), "r"(b[1]),
          "f"(c[0]), "f"(c[1]), "f"(c[2]), "f"(c[3]));
}

// ================= conversion kernels (unchanged) =================
__global__ void conv_x(const float* __restrict__ xq, const float* __restrict__ xk,
                       const float* __restrict__ xv,
                       __half* __restrict__ hq, __half* __restrict__ hk,
                       __half* __restrict__ hv)
{
    const float* src = (blockIdx.y == 0) ? xq : (blockIdx.y == 1) ? xk : xv;
    __half* dst = (blockIdx.y == 0) ? hq : (blockIdx.y == 1) ? hk : hv;
    int idx = blockIdx.x * 256 + threadIdx.x;
    float4 v = *(const float4*)(src + (size_t)idx * 4);
    uint32_t* d = (uint32_t*)(dst + (size_t)idx * 4);
    d[0] = pack_h2(v.x, v.y);
    d[1] = pack_h2(v.z, v.w);
}

__global__ void conv_w(const float* __restrict__ wq, const float* __restrict__ wk,
                       const float* __restrict__ wv,
                       __half* __restrict__ hwq, __half* __restrict__ hwk,
                       __half* __restrict__ hwv)
{
    __shared__ float s[64][65];
    const float* W = (blockIdx.z == 0) ? wq : (blockIdx.z == 1) ? wk : wv;
    __half* hw = (blockIdx.z == 0) ? hwq : (blockIdx.z == 1) ? hwk : hwv;
    const int k0 = blockIdx.x * 64;
    const int h  = blockIdx.y;
    const int tid = threadIdx.x;
#pragma unroll
    for (int it = 0; it < 4; it++) {
        int idx = tid + it * 256;
        int kk = idx >> 4, d4 = (idx & 15) * 4;
        float4 v = *(const float4*)(W + (size_t)h * DMODEL * DHEAD + (size_t)(k0 + kk) * DHEAD + d4);
        s[kk][d4 + 0] = v.x; s[kk][d4 + 1] = v.y;
        s[kk][d4 + 2] = v.z; s[kk][d4 + 3] = v.w;
    }
    __syncthreads();
    int d = tid >> 2, seg = (tid & 3) * 16;
    uint32_t* dst = (uint32_t*)(hw + (size_t)(h * 64 + d) * DMODEL + k0 + seg);
#pragma unroll
    for (int j = 0; j < 8; j++)
        dst[j] = pack_h2(s[seg + 2 * j][d], s[seg + 2 * j + 1][d]);
}

__global__ void conv_wo(const float* __restrict__ w, __half* __restrict__ hwo)
{
    __shared__ float s[64][65];
    const int k0 = blockIdx.x * 64;
    const int n0 = blockIdx.y * 64;
    const int tid = threadIdx.x;
#pragma unroll
    for (int it = 0; it < 4; it++) {
        int idx = tid + it * 256;
        int kk = idx >> 4, n4 = (idx & 15) * 4;
        float4 v = *(const float4*)(w + (size_t)(k0 + kk) * DMODEL + n0 + n4);
        s[kk][n4 + 0] = v.x; s[kk][n4 + 1] = v.y;
        s[kk][n4 + 2] = v.z; s[kk][n4 + 3] = v.w;
    }
    __syncthreads();
    int n = tid >> 2, seg = (tid & 3) * 16;
    uint32_t* dst = (uint32_t*)(hwo + (size_t)(n0 + n) * DMODEL + k0 + seg);
#pragma unroll
    for (int j = 0; j < 8; j++)
        dst[j] = pack_h2(s[seg + 2 * j][n], s[seg + 2 * j + 1][n]);
}

// ============ half GEMM: 3-stage cp.async ring + ldmatrix fragments ============
#define TSg 36
#define GEMM_SMEM (6 * 128 * TSg * 4)   // 110,592 B (3 stages x (A 128xTSg + B 128xTSg))

__device__ __forceinline__ void gemm_pipe(
    const __half* __restrict__ A, const __half* __restrict__ B,
    uint32_t* smg, int n0, int m0, float acc[4][4][4])
{
    const int tid = threadIdx.x;
    const int wid = tid >> 5;
    const int lid = tid & 31;
    const int wm  = wid >> 2;
    const int wn  = wid & 3;

    // stage byte-addresses
    uint32_t stA[3], stB[3];
#pragma unroll
    for (int s = 0; s < 3; s++) {
        stA[s] = smem_u32(smg + s * 256 * TSg);
        stB[s] = stA[s] + 128 * TSg * 4;
    }

#pragma unroll
    for (int i = 0; i < 4; i++)
#pragma unroll
        for (int j = 0; j < 4; j++)
#pragma unroll
            for (int f = 0; f < 4; f++) acc[i][j][f] = 0.0f;

    auto load_chunk = [&](int c, int s) {
        const int k0 = c * 64;
        const uint32_t aA = stA[s], aB = stB[s];
#pragma unroll
        for (int it = 0; it < 4; it++) {
            int i = tid + it * 256;
            int row = i >> 3, j = i & 7;
            cp_async16(aA + (uint32_t)((row * TSg + j * 4) << 2),
                       A + (size_t)(m0 + row) * DMODEL + k0 + j * 8);
            cp_async16(aB + (uint32_t)((row * TSg + j * 4) << 2),
                       B + (size_t)(n0 + row) * DMODEL + k0 + j * 8);
        }
        cp_commit();
    };

    // ldmatrix per-thread address components
    const int m8   = lid >> 3;                      // matrix index 0..3
    const int a_row = (lid & 7) + (m8 & 1) * 8;     // A: m0/m2 rows 0-7, m1/m3 rows 8-15
    const int a_cw  = (m8 >> 1) * 4;                // A: m2/m3 at k+8 (4 words)
    const int b_row = (lid & 7) + (m8 >> 1) * 8;    // B: m2/m3 rows +8
    const int b_cw  = (m8 & 1) * 4;                 // B: m1/m3 at k+8

    load_chunk(0, 0);
    load_chunk(1, 1);

    const int NCH = DMODEL / 64;   // 16
    for (int c = 0; c < NCH; c++) {
        cp_wait<1>();      // chunk c complete (c+1 may be in flight)
        __syncthreads();   // visibility of all threads' cp.async; frees buf (c+2)%3
        if (c + 2 < NCH) load_chunk(c + 2, (c + 2) % 3);

        const int s = c % 3;
        const uint32_t aA = stA[s], aB = stB[s];
#pragma unroll
        for (int kk = 0; kk < 4; kk++) {
            uint32_t af[4][4], bf[4][2];
#pragma unroll
            for (int mi = 0; mi < 4; mi++) {
                uint32_t addr = aA + (uint32_t)((((wm * 64 + mi * 16 + a_row) * TSg)
                                                + kk * 8 + a_cw) << 2);
                ldsm_x4(af[mi][0], af[mi][1], af[mi][2], af[mi][3], addr);
            }
#pragma unroll
            for (int njp = 0; njp < 2; njp++) {
                uint32_t addr = aB + (uint32_t)((((wn * 32 + njp * 16 + b_row) * TSg)
                                                + kk * 8 + b_cw) << 2);
                ldsm_x4(bf[2 * njp][0], bf[2 * njp][1],
                        bf[2 * njp + 1][0], bf[2 * njp + 1][1], addr);
            }
#pragma unroll
            for (int mi = 0; mi < 4; mi++)
#pragma unroll
                for (int nj = 0; nj < 4; nj++)
                    mma_f16_16x8x16(acc[mi][nj], af[mi], bf[nj], acc[mi][nj]);
        }
    }
}

__global__ __launch_bounds__(256, 2) void qkv_gemm(
    const __half* __restrict__ xq, const __half* __restrict__ xk, const __half* __restrict__ xv,
    const __half* __restrict__ wq, const __half* __restrict__ wk, const __half* __restrict__ wv,
    const float* __restrict__ bq, const float* __restrict__ bk, const float* __restrict__ bv,
    __half* __restrict__ cq, __half* __restrict__ ck, __half* __restrict__ cv)
{
    extern __shared__ uint32_t smg[];
    const __half* A = (blockIdx.z == 0) ? xq : (blockIdx.z == 1) ? xk : xv;
    const __half* B = (blockIdx.z == 0) ? wq : (blockIdx.z == 1) ? wk : wv;
    const float* bias = (blockIdx.z == 0) ? bq : (blockIdx.z == 1) ? bk : bv;
    __half*      C = (blockIdx.z == 0) ? cq : (blockIdx.z == 1) ? ck : cv;
    const int n0 = blockIdx.x * 128, m0 = blockIdx.y * 128;

    float acc[4][4][4];
    gemm_pipe(A, B, smg, n0, m0, acc);

    const int lid = threadIdx.x & 31;
    const int g = lid >> 2, tig = lid & 3;
    const int wm = (threadIdx.x >> 5) >> 2, wn = (threadIdx.x >> 5) & 3;
#pragma unroll
    for (int mi = 0; mi < 4; mi++) {
        int r0 = m0 + wm * 64 + mi * 16 + g;
#pragma unroll
        for (int nj = 0; nj < 4; nj++) {
            int c0 = n0 + wn * 32 + nj * 8 + tig * 2;
            float b0 = bias[c0], b1 = bias[c0 + 1];
            *(uint32_t*)(C + (size_t)r0 * DMODEL + c0) =
                pack_h2(acc[mi][nj][0] + b0, acc[mi][nj][1] + b1);
            *(uint32_t*)(C + (size_t)(r0 + 8) * DMODEL + c0) =
                pack_h2(acc[mi][nj][2] + b0, acc[mi][nj][3] + b1);
        }
    }
}

__global__ __launch_bounds__(256, 2) void wo_gemm(
    const __half* __restrict__ A, const __half* __restrict__ B,
    const float* __restrict__ bias, float* __restrict__ C)
{
    extern __shared__ uint32_t smg[];
    const int n0 = blockIdx.x * 128, m0 = blockIdx.y * 128;

    float acc[4][4][4];
    gemm_pipe(A, B, smg, n0, m0, acc);

    const int lid = threadIdx.x & 31;
    const int g = lid >> 2, tig = lid & 3;
    const int wm = (threadIdx.x >> 5) >> 2, wn = (threadIdx.x >> 5) & 3;
#pragma unroll
    for (int mi = 0; mi < 4; mi++) {
        int r0 = m0 + wm * 64 + mi * 16 + g;
#pragma unroll
        for (int nj = 0; nj < 4; nj++) {
            int c0 = n0 + wn * 32 + nj * 8 + tig * 2;
            float b0 = bias[c0], b1 = bias[c0 + 1];
            *(float2*)(C + (size_t)r0 * DMODEL + c0) =
                make_float2(acc[mi][nj][0] + b0, acc[mi][nj][1] + b1);
            *(float2*)(C + (size_t)(r0 + 8) * DMODEL + c0) =
                make_float2(acc[mi][nj][2] + b0, acc[mi][nj][3] + b1);
        }
    }
}

// ============ flash attention (unchanged from R12) ============
#define FSH 36

__global__ __launch_bounds__(256, 2) void flash_attn_h(
    const __half* __restrict__ q, const __half* __restrict__ k,
    const __half* __restrict__ v, const float* __restrict__ amask,
    __half* __restrict__ z)
{
    extern __shared__ uint32_t sm[];
    uint32_t* Qs = sm;                   // 128 x FSH

    const int qt = (int)(gridDim.x - 1 - blockIdx.x);
    const int h  = blockIdx.y;
    const int b  = blockIdx.z;
    const int tid = threadIdx.x;
    const int lid = tid & 31;
    const int g   = lid >> 2;
    const int tig = lid & 3;
    const int r0  = (tid >> 5) * 16;

    const size_t base = (size_t)b * S_LEN;
    const __half* qp = q + (base + qt * 128) * DMODEL + h * 64;

#pragma unroll
    for (int it = 0; it < 4; it++) {
        int i = tid + it * 256;
        int row = i >> 3, j = i & 7;
        *(uint4*)(Qs + row * FSH + j * 4) =
            *(const uint4*)((const char*)(qp + (size_t)row * DMODEL) + j * 16);
    }

    float o[8][4];
#pragma unroll
    for (int nj = 0; nj < 8; nj++)
#pragma unroll
        for (int f = 0; f < 4; f++) o[nj][f] = 0.0f;
    float mrow0 = -1e30f, mrow1 = -1e30f;
    float lrow0 = 0.0f,  lrow1 = 0.0f;

    const int qi0 = qt * 128 + r0 + g;
    const int qi1 = qi0 + 8;
    const int nkt = 2 * (qt + 1);

    const int krow0 = tid >> 3,         kj0 = tid & 7;
    const int krow1 = (tid + 256) >> 3, kj1 = tid & 7;
    const int vp_pair = tid & 31;
    const int vdq     = tid >> 5;

    uint4 kr0, kr1, vr0, vr1;
    auto load_regs = [&](int kt) {
        const __half* kp = k + (base + kt * 64) * DMODEL + h * 64;
        const __half* vp = v + (base + kt * 64) * DMODEL + h * 64;
        kr0 = *(const uint4*)((const char*)(kp + (size_t)krow0 * DMODEL) + kj0 * 16);
        kr1 = *(const uint4*)((const char*)(kp + (size_t)krow1 * DMODEL) + kj1 * 16);
        vr0 = *(const uint4*)(vp + (size_t)(2 * vp_pair) * DMODEL + vdq * 8);
        vr1 = *(const uint4*)(vp + (size_t)(2 * vp_pair + 1) * DMODEL + vdq * 8);
    };
    auto store_regs = [&](int buf) {
        uint32_t* Ksb = sm + (128 + buf * 128) * FSH;
        uint32_t* Vtb = Ksb + 64 * FSH;
        *(uint4*)(Ksb + krow0 * FSH + kj0 * 4) = kr0;
        *(uint4*)(Ksb + krow1 * FSH + kj1 * 4) = kr1;
        int dbase = vdq * 8;
        Vtb[(dbase + 0) * FSH + vp_pair] = prmt(vr0.x, vr1.x, 0x5410);
        Vtb[(dbase + 1) * FSH + vp_pair] = prmt(vr0.x, vr1.x, 0x7632);
        Vtb[(dbase + 2) * FSH + vp_pair] = prmt(vr0.y, vr1.y, 0x5410);
        Vtb[(dbase + 3) * FSH + vp_pair] = prmt(vr0.y, vr1.y, 0x7632);
        Vtb[(dbase + 4) * FSH + vp_pair] = prmt(vr0.z, vr1.z, 0x5410);
        Vtb[(dbase + 5) * FSH + vp_pair] = prmt(vr0.z, vr1.z, 0x7632);
        Vtb[(dbase + 6) * FSH + vp_pair] = prmt(vr0.w, vr1.w, 0x5410);
        Vtb[(dbase + 7) * FSH + vp_pair] = prmt(vr0.w, vr1.w, 0x7632);
    };

    load_regs(0);
    store_regs(0);
    if (nkt > 1) load_regs(1);

    for (int kt = 0; kt < nkt; kt++) {
        __syncthreads();
        const int buf = kt & 1;
        const uint32_t* Ks = sm + (128 + buf * 128) * FSH;
        const uint32_t* Vt = Ks + 64 * FSH;

        if (kt + 1 < nkt) store_regs(buf ^ 1);
        if (kt + 2 < nkt) load_regs(kt + 2);

        float sacc[8][4];
#pragma unroll
        for (int nj = 0; nj < 8; nj++)
#pragma unroll
            for (int f = 0; f < 4; f++) sacc[nj][f] = 0.0f;

#pragma unroll
        for (int kk = 0; kk < 4; kk++) {
            uint32_t a[4];
            a[0] = Qs[(r0 + g) * FSH + kk * 8 + tig];
            a[1] = Qs[(r0 + g + 8) * FSH + kk * 8 + tig];
            a[2] = Qs[(r0 + g) * FSH + kk * 8 + tig + 4];
            a[3] = Qs[(r0 + g + 8) * FSH + kk * 8 + tig + 4];
#pragma unroll
            for (int nj = 0; nj < 8; nj++) {
                uint32_t bb[2];
                bb[0] = Ks[(nj * 8 + g) * FSH + kk * 8 + tig];
                bb[1] = Ks[(nj * 8 + g) * FSH + kk * 8 + tig + 4];
                mma_f16_16x8x16(sacc[nj], a, bb, sacc[nj]);
            }
        }

        float tmax0 = -1e30f, tmax1 = -1e30f;
#pragma unroll
        for (int nj = 0; nj < 8; nj++) {
            int kj = kt * 64 + nj * 8 + tig * 2;
            float am0 = amask[b * S_LEN + kj];
            float am1 = amask[b * S_LEN + kj + 1];
            float s0 = ((kj     <= qi0) ? sacc[nj][0] * 0.125f : IGNORE_VAL) + am0;
            float s1 = ((kj + 1 <= qi0) ? sacc[nj][1] * 0.125f : IGNORE_VAL) + am1;
            float s2 = ((kj     <= qi1) ? sacc[nj][2] * 0.125f : IGNORE_VAL) + am0;
            float s3 = ((kj + 1 <= qi1) ? sacc[nj][3] * 0.125f : IGNORE_VAL) + am1;
            sacc[nj][0] = s0; sacc[nj][1] = s1; sacc[nj][2] = s2; sacc[nj][3] = s3;
            tmax0 = fmaxf(tmax0, fmaxf(s0, s1));
            tmax1 = fmaxf(tmax1, fmaxf(s2, s3));
        }
        tmax0 = fmaxf(tmax0, __shfl_xor_sync(0xffffffffu, tmax0, 1));
        tmax0 = fmaxf(tmax0, __shfl_xor_sync(0xffffffffu, tmax0, 2));
        tmax1 = fmaxf(tmax1, __shfl_xor_sync(0xffffffffu, tmax1, 1));
        tmax1 = fmaxf(tmax1, __shfl_xor_sync(0xffffffffu, tmax1, 2));

        float mn0 = fmaxf(mrow0, tmax0);
        float mn1 = fmaxf(mrow1, tmax1);
        float alpha0 = __expf(mrow0 - mn0);
        float alpha1 = __expf(mrow1 - mn1);
        mrow0 = mn0; mrow1 = mn1;

        float rs0 = 0.0f, rs1 = 0.0f;
#pragma unroll
        for (int nj = 0; nj < 8; nj++) {
            float p0 = __expf(sacc[nj][0] - mn0);
            float p1 = __expf(sacc[nj][1] - mn0);
            float p2 = __expf(sacc[nj][2] - mn1);
            float p3 = __expf(sacc[nj][3] - mn1);
            sacc[nj][0] = p0; sacc[nj][1] = p1; sacc[nj][2] = p2; sacc[nj][3] = p3;
            rs0 += p0 + p1;
            rs1 += p2 + p3;
        }
        rs0 += __shfl_xor_sync(0xffffffffu, rs0, 1);
        rs0 += __shfl_xor_sync(0xffffffffu, rs0, 2);
        rs1 += __shfl_xor_sync(0xffffffffu, rs1, 1);
        rs1 += __shfl_xor_sync(0xffffffffu, rs1, 2);
        lrow0 = lrow0 * alpha0 + rs0;
        lrow1 = lrow1 * alpha1 + rs1;

#pragma unroll
        for (int nj = 0; nj < 8; nj++) {
            o[nj][0] *= alpha0; o[nj][1] *= alpha0;
            o[nj][2] *= alpha1; o[nj][3] *= alpha1;
        }

#pragma unroll
        for (int kk = 0; kk < 4; kk++) {
            uint32_t a[4];
            a[0] = pack_h2(sacc[2 * kk][0],     sacc[2 * kk][1]);
            a[1] = pack_h2(sacc[2 * kk][2],     sacc[2 * kk][3]);
            a[2] = pack_h2(sacc[2 * kk + 1][0], sacc[2 * kk + 1][1]);
            a[3] = pack_h2(sacc[2 * kk + 1][2], sacc[2 * kk + 1][3]);
#pragma unroll
            for (int nj = 0; nj < 8; nj++) {
                uint32_t bb[2];
                bb[0] = Vt[(nj * 8 + g) * FSH + kk * 8 + tig];
                bb[1] = Vt[(nj * 8 + g) * FSH + kk * 8 + tig + 4];
                mma_f16_16x8x16(o[nj], a, bb, o[nj]);
            }
        }
    }

    float inv0 = 1.0f / lrow0;
    float inv1 = 1.0f / lrow1;
    const size_t row0 = base + qt * 128 + r0 + g;
#pragma unroll
    for (int nj = 0; nj < 8; nj++) {
        int col = h * 64 + nj * 8 + tig * 2;
        *(uint32_t*)(z + row0 * DMODEL + col) =
            pack_h2(o[nj][0] * inv0, o[nj][1] * inv0);
        *(uint32_t*)(z + (row0 + 8) * DMODEL + col) =
            pack_h2(o[nj][2] * inv1, o[nj][3] * inv1);
    }
}

// ---------------- launch ----------------
extern "C" void kernel_launch(void* const* d_in, const int* in_sizes, int n_in,
                              void* d_out, int out_size)
{
    const float* x_q  = (const float*)d_in[0];
    const float* x_k  = (const float*)d_in[1];
    const float* x_v  = (const float*)d_in[2];
    const float* amsk = (const float*)d_in[3];
    const float* w_q  = (const float*)d_in[4];
    const float* w_k  = (const float*)d_in[5];
    const float* w_v  = (const float*)d_in[6];
    const float* w_o  = (const float*)d_in[7];
    const float* b_q  = (const float*)d_in[8];
    const float* b_k  = (const float*)d_in[9];
    const float* b_v  = (const float*)d_in[10];
    const float* b_o  = (const float*)d_in[11];
    float* out = (float*)d_out;

    __half *hxq, *hxk, *hxv, *hwq, *hwk, *hwv, *hwo, *hq, *hk, *hv, *hz;
    cudaGetSymbolAddress((void**)&hxq, g_hxq);
    cudaGetSymbolAddress((void**)&hxk, g_hxk);
    cudaGetSymbolAddress((void**)&hxv, g_hxv);
    cudaGetSymbolAddress((void**)&hwq, g_hwq);
    cudaGetSymbolAddress((void**)&hwk, g_hwk);
    cudaGetSymbolAddress((void**)&hwv, g_hwv);
    cudaGetSymbolAddress((void**)&hwo, g_hwo);
    cudaGetSymbolAddress((void**)&hq,  g_hq);
    cudaGetSymbolAddress((void**)&hk,  g_hk);
    cudaGetSymbolAddress((void**)&hv,  g_hv);
    cudaGetSymbolAddress((void**)&hz,  g_hz);

    int fl_smem = 384 * FSH * sizeof(uint32_t);   // 55,296 B
    cudaFuncSetAttribute(flash_attn_h, cudaFuncAttributeMaxDynamicSharedMemorySize, fl_smem);
    cudaFuncSetAttribute(qkv_gemm, cudaFuncAttributeMaxDynamicSharedMemorySize, GEMM_SMEM);
    cudaFuncSetAttribute(wo_gemm, cudaFuncAttributeMaxDynamicSharedMemorySize, GEMM_SMEM);

    // conversions
    dim3 cxg(MROWS * DMODEL / (256 * 4), 3);
    conv_x<<<cxg, 256>>>(x_q, x_k, x_v, hxq, hxk, hxv);
    dim3 cwg(DMODEL / 64, NHEADS, 3);
    conv_w<<<cwg, 256>>>(w_q, w_k, w_v, hwq, hwk, hwv);
    dim3 cog(DMODEL / 64, DMODEL / 64);
    conv_wo<<<cog, 256>>>(w_o, hwo);

    // QKV projections
    dim3 qgrid(DMODEL / 128, MROWS / 128, 3);
    qkv_gemm<<<qgrid, 256, GEMM_SMEM>>>(hxq, hxk, hxv, hwq, hwk, hwv,
                                        b_q, b_k, b_v, hq, hk, hv);

    // flash attention
    dim3 fgrid(S_LEN / 128, NHEADS, BATCH);
    flash_attn_h<<<fgrid, 256, fl_smem>>>(hq, hk, hv, amsk, hz);

    // output projection
    dim3 ogrid(DMODEL / 128, MROWS / 128);
    wo_gemm<<<ogrid, 256, GEMM_SMEM>>>(hz, hwo, b_o, out);

    (void)in_sizes; (void)n_in; (void)out_size;
}

// round 14
// speedup vs baseline: 2.3200x; 1.0671x over previous
#include <cuda_runtime.h>
#include <cuda_fp16.h>
#include <cstdint>
#include <math.h>

#define S_LEN   2048
#define BATCH   2
#define DMODEL  1024
#define NHEADS  16
#define DHEAD   64
#define MROWS   (BATCH * S_LEN)   // 4096
#define IGNORE_VAL (-100000.0f)

// ---------------- scratch (half everywhere) ----------------
__device__ __half g_hxq[MROWS * DMODEL];
__device__ __half g_hxk[MROWS * DMODEL];
__device__ __half g_hxv[MROWS * DMODEL];
__device__ __half g_hwq[DMODEL * DMODEL];   // [n][k]
__device__ __half g_hwk[DMODEL * DMODEL];
__device__ __half g_hwv[DMODEL * DMODEL];
__device__ __half g_hwo[DMODEL * DMODEL];   // [n][k]
__device__ __half g_hq[MROWS * DMODEL];
__device__ __half g_hk[MROWS * DMODEL];
__device__ __half g_hv[MROWS * DMODEL];
__device__ __half g_hz[MROWS * DMODEL];

// ---------------- helpers ----------------
__device__ __forceinline__ uint32_t smem_u32(const void* p) {
    uint32_t a;
    asm("{ .reg .u64 t; cvta.to.shared.u64 t, %1; cvt.u32.u64 %0, t; }" : "=r"(a) : "l"(p));
    return a;
}
__device__ __forceinline__ uint32_t pack_h2(float a, float b) {
    __half2 h = __float22half2_rn(make_float2(a, b));
    return *reinterpret_cast<uint32_t*>(&h);
}
__device__ __forceinline__ uint32_t prmt(uint32_t a, uint32_t b, uint32_t sel) {
    uint32_t r;
    asm("prmt.b32 %0, %1, %2, %3;" : "=r"(r) : "r"(a), "r"(b), "r"(sel));
    return r;
}
__device__ __forceinline__ void cp_async16(uint32_t dst, const void* src) {
    asm volatile("cp.async.cg.shared.global [%0], [%1], 16;" :: "r"(dst), "l"(src));
}
__device__ __forceinline__ void cp_commit() {
    asm volatile("cp.async.commit_group;" ::: "memory");
}
template <int N>
__device__ __forceinline__ void cp_wait() {
    asm volatile("cp.async.wait_group %0;" :: "n"(N) : "memory");
}
__device__ __forceinline__ void ldsm_x4(uint32_t& r0, uint32_t& r1, uint32_t& r2, uint32_t& r3,
                                        uint32_t addr) {
    asm volatile("ldmatrix.sync.aligned.m8n8.x4.shared.b16 {%0,%1,%2,%3}, [%4];"
        : "=r"(r0), "=r"(r1), "=r"(r2), "=r"(r3) : "r"(addr));
}
__device__ __forceinline__ void mma_f16_16x8x16(
    float* d, const uint32_t* a, const uint32_t* b, const float* c)
{
    asm volatile(
        "mma.sync.aligned.m16n8k16.row.col.f32.f16.f16.f32 "
        "{%0,%1,%2,%3}, {%4,%5,%6,%7}, {%8,%9}, {%10,%11,%12,%13};\n"
        : "=f"(d[0]), "=f"(d[1]), "=f"(d[2]), "=f"(d[3])
        : "r"(a[0]), "r"(a[1]), "r"(a[2]), "r"(a[3]),
          "r"(b[0]), "r"(b[1]),
          "f"(c[0]), "f"(c[1]), "f"(c[2]), "f"(c[3]));
}

// ================= conversion kernels (unchanged) =================
__global__ void conv_x(const float* __restrict__ xq, const float* __restrict__ xk,
                       const float* __restrict__ xv,
                       __half* __restrict__ hq, __half* __restrict__ hk,
                       __half* __restrict__ hv)
{
    const float* src = (blockIdx.y == 0) ? xq : (blockIdx.y == 1) ? xk : xv;
    __half* dst = (blockIdx.y == 0) ? hq : (blockIdx.y == 1) ? hk : hv;
    int idx = blockIdx.x * 256 + threadIdx.x;
    float4 v = *(const float4*)(src + (size_t)idx * 4);
    uint32_t* d = (uint32_t*)(dst + (size_t)idx * 4);
    d[0] = pack_h2(v.x, v.y);
    d[1] = pack_h2(v.z, v.w);
}

__global__ void conv_w(const float* __restrict__ wq, const float* __restrict__ wk,
                       const float* __restrict__ wv,
                       __half* __restrict__ hwq, __half* __restrict__ hwk,
                       __half* __restrict__ hwv)
{
    __shared__ float s[64][65];
    const float* W = (blockIdx.z == 0) ? wq : (blockIdx.z == 1) ? wk : wv;
    __half* hw = (blockIdx.z == 0) ? hwq : (blockIdx.z == 1) ? hwk : hwv;
    const int k0 = blockIdx.x * 64;
    const int h  = blockIdx.y;
    const int tid = threadIdx.x;
#pragma unroll
    for (int it = 0; it < 4; it++) {
        int idx = tid + it * 256;
        int kk = idx >> 4, d4 = (idx & 15) * 4;
        float4 v = *(const float4*)(W + (size_t)h * DMODEL * DHEAD + (size_t)(k0 + kk) * DHEAD + d4);
        s[kk][d4 + 0] = v.x; s[kk][d4 + 1] = v.y;
        s[kk][d4 + 2] = v.z; s[kk][d4 + 3] = v.w;
    }
    __syncthreads();
    int d = tid >> 2, seg = (tid & 3) * 16;
    uint32_t* dst = (uint32_t*)(hw + (size_t)(h * 64 + d) * DMODEL + k0 + seg);
#pragma unroll
    for (int j = 0; j < 8; j++)
        dst[j] = pack_h2(s[seg + 2 * j][d], s[seg + 2 * j + 1][d]);
}

__global__ void conv_wo(const float* __restrict__ w, __half* __restrict__ hwo)
{
    __shared__ float s[64][65];
    const int k0 = blockIdx.x * 64;
    const int n0 = blockIdx.y * 64;
    const int tid = threadIdx.x;
#pragma unroll
    for (int it = 0; it < 4; it++) {
        int idx = tid + it * 256;
        int kk = idx >> 4, n4 = (idx & 15) * 4;
        float4 v = *(const float4*)(w + (size_t)(k0 + kk) * DMODEL + n0 + n4);
        s[kk][n4 + 0] = v.x; s[kk][n4 + 1] = v.y;
        s[kk][n4 + 2] = v.z; s[kk][n4 + 3] = v.w;
    }
    __syncthreads();
    int n = tid >> 2, seg = (tid & 3) * 16;
    uint32_t* dst = (uint32_t*)(hwo + (size_t)(n0 + n) * DMODEL + k0 + seg);
#pragma unroll
    for (int j = 0; j < 8; j++)
        dst[j] = pack_h2(s[seg + 2 * j][n], s[seg + 2 * j + 1][n]);
}

// ============ half GEMM: 3-stage cp.async ring + ldmatrix (unchanged R13) ============
#define TSg 36
#define GEMM_SMEM (6 * 128 * TSg * 4)   // 110,592 B

__device__ __forceinline__ void gemm_pipe(
    const __half* __restrict__ A, const __half* __restrict__ B,
    uint32_t* smg, int n0, int m0, float acc[4][4][4])
{
    const int tid = threadIdx.x;
    const int wid = tid >> 5;
    const int lid = tid & 31;
    const int wm  = wid >> 2;
    const int wn  = wid & 3;

    uint32_t stA[3], stB[3];
#pragma unroll
    for (int s = 0; s < 3; s++) {
        stA[s] = smem_u32(smg + s * 256 * TSg);
        stB[s] = stA[s] + 128 * TSg * 4;
    }

#pragma unroll
    for (int i = 0; i < 4; i++)
#pragma unroll
        for (int j = 0; j < 4; j++)
#pragma unroll
            for (int f = 0; f < 4; f++) acc[i][j][f] = 0.0f;

    auto load_chunk = [&](int c, int s) {
        const int k0 = c * 64;
        const uint32_t aA = stA[s], aB = stB[s];
#pragma unroll
        for (int it = 0; it < 4; it++) {
            int i = tid + it * 256;
            int row = i >> 3, j = i & 7;
            cp_async16(aA + (uint32_t)((row * TSg + j * 4) << 2),
                       A + (size_t)(m0 + row) * DMODEL + k0 + j * 8);
            cp_async16(aB + (uint32_t)((row * TSg + j * 4) << 2),
                       B + (size_t)(n0 + row) * DMODEL + k0 + j * 8);
        }
        cp_commit();
    };

    const int m8   = lid >> 3;
    const int a_row = (lid & 7) + (m8 & 1) * 8;
    const int a_cw  = (m8 >> 1) * 4;
    const int b_row = (lid & 7) + (m8 >> 1) * 8;
    const int b_cw  = (m8 & 1) * 4;

    load_chunk(0, 0);
    load_chunk(1, 1);

    const int NCH = DMODEL / 64;   // 16
    for (int c = 0; c < NCH; c++) {
        cp_wait<1>();
        __syncthreads();
        if (c + 2 < NCH) load_chunk(c + 2, (c + 2) % 3);

        const int s = c % 3;
        const uint32_t aA = stA[s], aB = stB[s];
#pragma unroll
        for (int kk = 0; kk < 4; kk++) {
            uint32_t af[4][4], bf[4][2];
#pragma unroll
            for (int mi = 0; mi < 4; mi++) {
                uint32_t addr = aA + (uint32_t)((((wm * 64 + mi * 16 + a_row) * TSg)
                                                + kk * 8 + a_cw) << 2);
                ldsm_x4(af[mi][0], af[mi][1], af[mi][2], af[mi][3], addr);
            }
#pragma unroll
            for (int njp = 0; njp < 2; njp++) {
                uint32_t addr = aB + (uint32_t)((((wn * 32 + njp * 16 + b_row) * TSg)
                                                + kk * 8 + b_cw) << 2);
                ldsm_x4(bf[2 * njp][0], bf[2 * njp][1],
                        bf[2 * njp + 1][0], bf[2 * njp + 1][1], addr);
            }
#pragma unroll
            for (int mi = 0; mi < 4; mi++)
#pragma unroll
                for (int nj = 0; nj < 4; nj++)
                    mma_f16_16x8x16(acc[mi][nj], af[mi], bf[nj], acc[mi][nj]);
        }
    }
}

__global__ __launch_bounds__(256, 2) void qkv_gemm(
    const __half* __restrict__ xq, const __half* __restrict__ xk, const __half* __restrict__ xv,
    const __half* __restrict__ wq, const __half* __restrict__ wk, const __half* __restrict__ wv,
    const float* __restrict__ bq, const float* __restrict__ bk, const float* __restrict__ bv,
    __half* __restrict__ cq, __half* __restrict__ ck, __half* __restrict__ cv)
{
    extern __shared__ uint32_t smg[];
    const __half* A = (blockIdx.z == 0) ? xq : (blockIdx.z == 1) ? xk : xv;
    const __half* B = (blockIdx.z == 0) ? wq : (blockIdx.z == 1) ? wk : wv;
    const float* bias = (blockIdx.z == 0) ? bq : (blockIdx.z == 1) ? bk : bv;
    __half*      C = (blockIdx.z == 0) ? cq : (blockIdx.z == 1) ? ck : cv;
    const int n0 = blockIdx.x * 128, m0 = blockIdx.y * 128;

    float acc[4][4][4];
    gemm_pipe(A, B, smg, n0, m0, acc);

    const int lid = threadIdx.x & 31;
    const int g = lid >> 2, tig = lid & 3;
    const int wm = (threadIdx.x >> 5) >> 2, wn = (threadIdx.x >> 5) & 3;
#pragma unroll
    for (int mi = 0; mi < 4; mi++) {
        int r0 = m0 + wm * 64 + mi * 16 + g;
#pragma unroll
        for (int nj = 0; nj < 4; nj++) {
            int c0 = n0 + wn * 32 + nj * 8 + tig * 2;
            float b0 = bias[c0], b1 = bias[c0 + 1];
            *(uint32_t*)(C + (size_t)r0 * DMODEL + c0) =
                pack_h2(acc[mi][nj][0] + b0, acc[mi][nj][1] + b1);
            *(uint32_t*)(C + (size_t)(r0 + 8) * DMODEL + c0) =
                pack_h2(acc[mi][nj][2] + b0, acc[mi][nj][3] + b1);
        }
    }
}

__global__ __launch_bounds__(256, 2) void wo_gemm(
    const __half* __restrict__ A, const __half* __restrict__ B,
    const float* __restrict__ bias, float* __restrict__ C)
{
    extern __shared__ uint32_t smg[];
    const int n0 = blockIdx.x * 128, m0 = blockIdx.y * 128;

    float acc[4][4][4];
    gemm_pipe(A, B, smg, n0, m0, acc);

    const int lid = threadIdx.x & 31;
    const int g = lid >> 2, tig = lid & 3;
    const int wm = (threadIdx.x >> 5) >> 2, wn = (threadIdx.x >> 5) & 3;
#pragma unroll
    for (int mi = 0; mi < 4; mi++) {
        int r0 = m0 + wm * 64 + mi * 16 + g;
#pragma unroll
        for (int nj = 0; nj < 4; nj++) {
            int c0 = n0 + wn * 32 + nj * 8 + tig * 2;
            float b0 = bias[c0], b1 = bias[c0 + 1];
            *(float2*)(C + (size_t)r0 * DMODEL + c0) =
                make_float2(acc[mi][nj][0] + b0, acc[mi][nj][1] + b1);
            *(float2*)(C + (size_t)(r0 + 8) * DMODEL + c0) =
                make_float2(acc[mi][nj][2] + b0, acc[mi][nj][3] + b1);
        }
    }
}

// ============ flash attention: ldmatrix fragments ============
#define FSH 36

__global__ __launch_bounds__(256, 2) void flash_attn_h(
    const __half* __restrict__ q, const __half* __restrict__ k,
    const __half* __restrict__ v, const float* __restrict__ amask,
    __half* __restrict__ z)
{
    extern __shared__ uint32_t sm[];
    uint32_t* Qs = sm;                   // 128 x FSH

    const int qt = (int)(gridDim.x - 1 - blockIdx.x);
    const int h  = blockIdx.y;
    const int b  = blockIdx.z;
    const int tid = threadIdx.x;
    const int lid = tid & 31;
    const int g   = lid >> 2;
    const int tig = lid & 3;
    const int r0  = (tid >> 5) * 16;

    const uint32_t smbase = smem_u32(sm);

    // ldmatrix lane mappings (same as GEMM, verified)
    const int m8    = lid >> 3;
    const int a_row = (lid & 7) + (m8 & 1) * 8;
    const int a_cw  = (m8 >> 1) * 4;
    const int b_row = (lid & 7) + (m8 >> 1) * 8;
    const int b_cw  = (m8 & 1) * 4;

    const size_t base = (size_t)b * S_LEN;
    const __half* qp = q + (base + qt * 128) * DMODEL + h * 64;

#pragma unroll
    for (int it = 0; it < 4; it++) {
        int i = tid + it * 256;
        int row = i >> 3, j = i & 7;
        *(uint4*)(Qs + row * FSH + j * 4) =
            *(const uint4*)((const char*)(qp + (size_t)row * DMODEL) + j * 16);
    }

    float o[8][4];
#pragma unroll
    for (int nj = 0; nj < 8; nj++)
#pragma unroll
        for (int f = 0; f < 4; f++) o[nj][f] = 0.0f;
    float mrow0 = -1e30f, mrow1 = -1e30f;
    float lrow0 = 0.0f,  lrow1 = 0.0f;

    const int qi0 = qt * 128 + r0 + g;
    const int qi1 = qi0 + 8;
    const int nkt = 2 * (qt + 1);

    const int krow0 = tid >> 3,         kj0 = tid & 7;
    const int krow1 = (tid + 256) >> 3, kj1 = tid & 7;
    const int vp_pair = tid & 31;
    const int vdq     = tid >> 5;

    uint4 kr0, kr1, vr0, vr1;
    auto load_regs = [&](int kt) {
        const __half* kp = k + (base + kt * 64) * DMODEL + h * 64;
        const __half* vp = v + (base + kt * 64) * DMODEL + h * 64;
        kr0 = *(const uint4*)((const char*)(kp + (size_t)krow0 * DMODEL) + kj0 * 16);
        kr1 = *(const uint4*)((const char*)(kp + (size_t)krow1 * DMODEL) + kj1 * 16);
        vr0 = *(const uint4*)(vp + (size_t)(2 * vp_pair) * DMODEL + vdq * 8);
        vr1 = *(const uint4*)(vp + (size_t)(2 * vp_pair + 1) * DMODEL + vdq * 8);
    };
    auto store_regs = [&](int buf) {
        uint32_t* Ksb = sm + (128 + buf * 128) * FSH;
        uint32_t* Vtb = Ksb + 64 * FSH;
        *(uint4*)(Ksb + krow0 * FSH + kj0 * 4) = kr0;
        *(uint4*)(Ksb + krow1 * FSH + kj1 * 4) = kr1;
        int dbase = vdq * 8;
        Vtb[(dbase + 0) * FSH + vp_pair] = prmt(vr0.x, vr1.x, 0x5410);
        Vtb[(dbase + 1) * FSH + vp_pair] = prmt(vr0.x, vr1.x, 0x7632);
        Vtb[(dbase + 2) * FSH + vp_pair] = prmt(vr0.y, vr1.y, 0x5410);
        Vtb[(dbase + 3) * FSH + vp_pair] = prmt(vr0.y, vr1.y, 0x7632);
        Vtb[(dbase + 4) * FSH + vp_pair] = prmt(vr0.z, vr1.z, 0x5410);
        Vtb[(dbase + 5) * FSH + vp_pair] = prmt(vr0.z, vr1.z, 0x7632);
        Vtb[(dbase + 6) * FSH + vp_pair] = prmt(vr0.w, vr1.w, 0x5410);
        Vtb[(dbase + 7) * FSH + vp_pair] = prmt(vr0.w, vr1.w, 0x7632);
    };

    load_regs(0);
    store_regs(0);
    if (nkt > 1) load_regs(1);

    for (int kt = 0; kt < nkt; kt++) {
        __syncthreads();
        const int buf = kt & 1;
        const uint32_t Ksb = smbase + (uint32_t)(((128 + buf * 128) * FSH) << 2);
        const uint32_t Vtb = Ksb + (uint32_t)((64 * FSH) << 2);

        if (kt + 1 < nkt) store_regs(buf ^ 1);
        if (kt + 2 < nkt) load_regs(kt + 2);

        // ---- S = Q K^T (ldmatrix fragments) ----
        float sacc[8][4];
#pragma unroll
        for (int nj = 0; nj < 8; nj++)
#pragma unroll
            for (int f = 0; f < 4; f++) sacc[nj][f] = 0.0f;

#pragma unroll
        for (int kk = 0; kk < 4; kk++) {
            uint32_t a[4];
            ldsm_x4(a[0], a[1], a[2], a[3],
                    smbase + (uint32_t)((((r0 + a_row) * FSH) + kk * 8 + a_cw) << 2));
#pragma unroll
            for (int njp = 0; njp < 4; njp++) {
                uint32_t b0, b1, b2, b3;
                ldsm_x4(b0, b1, b2, b3,
                        Ksb + (uint32_t)((((njp * 16 + b_row) * FSH) + kk * 8 + b_cw) << 2));
                uint32_t bb0[2] = { b0, b1 };
                uint32_t bb1[2] = { b2, b3 };
                mma_f16_16x8x16(sacc[2 * njp],     a, bb0, sacc[2 * njp]);
                mma_f16_16x8x16(sacc[2 * njp + 1], a, bb1, sacc[2 * njp + 1]);
            }
        }

        // ---- scale, causal, additive mask ----
        float tmax0 = -1e30f, tmax1 = -1e30f;
#pragma unroll
        for (int nj = 0; nj < 8; nj++) {
            int kj = kt * 64 + nj * 8 + tig * 2;
            float am0 = amask[b * S_LEN + kj];
            float am1 = amask[b * S_LEN + kj + 1];
            float s0 = ((kj     <= qi0) ? sacc[nj][0] * 0.125f : IGNORE_VAL) + am0;
            float s1 = ((kj + 1 <= qi0) ? sacc[nj][1] * 0.125f : IGNORE_VAL) + am1;
            float s2 = ((kj     <= qi1) ? sacc[nj][2] * 0.125f : IGNORE_VAL) + am0;
            float s3 = ((kj + 1 <= qi1) ? sacc[nj][3] * 0.125f : IGNORE_VAL) + am1;
            sacc[nj][0] = s0; sacc[nj][1] = s1; sacc[nj][2] = s2; sacc[nj][3] = s3;
            tmax0 = fmaxf(tmax0, fmaxf(s0, s1));
            tmax1 = fmaxf(tmax1, fmaxf(s2, s3));
        }
        tmax0 = fmaxf(tmax0, __shfl_xor_sync(0xffffffffu, tmax0, 1));
        tmax0 = fmaxf(tmax0, __shfl_xor_sync(0xffffffffu, tmax0, 2));
        tmax1 = fmaxf(tmax1, __shfl_xor_sync(0xffffffffu, tmax1, 1));
        tmax1 = fmaxf(tmax1, __shfl_xor_sync(0xffffffffu, tmax1, 2));

        float mn0 = fmaxf(mrow0, tmax0);
        float mn1 = fmaxf(mrow1, tmax1);
        float alpha0 = __expf(mrow0 - mn0);
        float alpha1 = __expf(mrow1 - mn1);
        mrow0 = mn0; mrow1 = mn1;

        float rs0 = 0.0f, rs1 = 0.0f;
#pragma unroll
        for (int nj = 0; nj < 8; nj++) {
            float p0 = __expf(sacc[nj][0] - mn0);
            float p1 = __expf(sacc[nj][1] - mn0);
            float p2 = __expf(sacc[nj][2] - mn1);
            float p3 = __expf(sacc[nj][3] - mn1);
            sacc[nj][0] = p0; sacc[nj][1] = p1; sacc[nj][2] = p2; sacc[nj][3] = p3;
            rs0 += p0 + p1;
            rs1 += p2 + p3;
        }
        rs0 += __shfl_xor_sync(0xffffffffu, rs0, 1);
        rs0 += __shfl_xor_sync(0xffffffffu, rs0, 2);
        rs1 += __shfl_xor_sync(0xffffffffu, rs1, 1);
        rs1 += __shfl_xor_sync(0xffffffffu, rs1, 2);
        lrow0 = lrow0 * alpha0 + rs0;
        lrow1 = lrow1 * alpha1 + rs1;

#pragma unroll
        for (int nj = 0; nj < 8; nj++) {
            o[nj][0] *= alpha0; o[nj][1] *= alpha0;
            o[nj][2] *= alpha1; o[nj][3] *= alpha1;
        }

        // ---- O += P V : P in registers, Vt via ldmatrix ----
#pragma unroll
        for (int kk = 0; kk < 4; kk++) {
            uint32_t a[4];
            a[0] = pack_h2(sacc[2 * kk][0],     sacc[2 * kk][1]);
            a[1] = pack_h2(sacc[2 * kk][2],     sacc[2 * kk][3]);
            a[2] = pack_h2(sacc[2 * kk + 1][0], sacc[2 * kk + 1][1]);
            a[3] = pack_h2(sacc[2 * kk + 1][2], sacc[2 * kk + 1][3]);
#pragma unroll
            for (int njp = 0; njp < 4; njp++) {
                uint32_t b0, b1, b2, b3;
                ldsm_x4(b0, b1, b2, b3,
                        Vtb + (uint32_t)((((njp * 16 + b_row) * FSH) + kk * 8 + b_cw) << 2));
                uint32_t bb0[2] = { b0, b1 };
                uint32_t bb1[2] = { b2, b3 };
                mma_f16_16x8x16(o[2 * njp],     a, bb0, o[2 * njp]);
                mma_f16_16x8x16(o[2 * njp + 1], a, bb1, o[2 * njp + 1]);
            }
        }
    }

    float inv0 = 1.0f / lrow0;
    float inv1 = 1.0f / lrow1;
    const size_t row0 = base + qt * 128 + r0 + g;
#pragma unroll
    for (int nj = 0; nj < 8; nj++) {
        int col = h * 64 + nj * 8 + tig * 2;
        *(uint32_t*)(z + row0 * DMODEL + col) =
            pack_h2(o[nj][0] * inv0, o[nj][1] * inv0);
        *(uint32_t*)(z + (row0 + 8) * DMODEL + col) =
            pack_h2(o[nj][2] * inv1, o[nj][3] * inv1);
    }
}

// ---------------- launch ----------------
extern "C" void kernel_launch(void* const* d_in, const int* in_sizes, int n_in,
                              void* d_out, int out_size)
{
    const float* x_q  = (const float*)d_in[0];
    const float* x_k  = (const float*)d_in[1];
    const float* x_v  = (const float*)d_in[2];
    const float* amsk = (const float*)d_in[3];
    const float* w_q  = (const float*)d_in[4];
    const float* w_k  = (const float*)d_in[5];
    const float* w_v  = (const float*)d_in[6];
    const float* w_o  = (const float*)d_in[7];
    const float* b_q  = (const float*)d_in[8];
    const float* b_k  = (const float*)d_in[9];
    const float* b_v  = (const float*)d_in[10];
    const float* b_o  = (const float*)d_in[11];
    float* out = (float*)d_out;

    __half *hxq, *hxk, *hxv, *hwq, *hwk, *hwv, *hwo, *hq, *hk, *hv, *hz;
    cudaGetSymbolAddress((void**)&hxq, g_hxq);
    cudaGetSymbolAddress((void**)&hxk, g_hxk);
    cudaGetSymbolAddress((void**)&hxv, g_hxv);
    cudaGetSymbolAddress((void**)&hwq, g_hwq);
    cudaGetSymbolAddress((void**)&hwk, g_hwk);
    cudaGetSymbolAddress((void**)&hwv, g_hwv);
    cudaGetSymbolAddress((void**)&hwo, g_hwo);
    cudaGetSymbolAddress((void**)&hq,  g_hq);
    cudaGetSymbolAddress((void**)&hk,  g_hk);
    cudaGetSymbolAddress((void**)&hv,  g_hv);
    cudaGetSymbolAddress((void**)&hz,  g_hz);

    int fl_smem = 384 * FSH * sizeof(uint32_t);   // 55,296 B
    cudaFuncSetAttribute(flash_attn_h, cudaFuncAttributeMaxDynamicSharedMemorySize, fl_smem);
    cudaFuncSetAttribute(qkv_gemm, cudaFuncAttributeMaxDynamicSharedMemorySize, GEMM_SMEM);
    cudaFuncSetAttribute(wo_gemm, cudaFuncAttributeMaxDynamicSharedMemorySize, GEMM_SMEM);

    // conversions
    dim3 cxg(MROWS * DMODEL / (256 * 4), 3);
    conv_x<<<cxg, 256>>>(x_q, x_k, x_v, hxq, hxk, hxv);
    dim3 cwg(DMODEL / 64, NHEADS, 3);
    conv_w<<<cwg, 256>>>(w_q, w_k, w_v, hwq, hwk, hwv);
    dim3 cog(DMODEL / 64, DMODEL / 64);
    conv_wo<<<cog, 256>>>(w_o, hwo);

    // QKV projections
    dim3 qgrid(DMODEL / 128, MROWS / 128, 3);
    qkv_gemm<<<qgrid, 256, GEMM_SMEM>>>(hxq, hxk, hxv, hwq, hwk, hwv,
                                        b_q, b_k, b_v, hq, hk, hv);

    // flash attention
    dim3 fgrid(S_LEN / 128, NHEADS, BATCH);
    flash_attn_h<<<fgrid, 256, fl_smem>>>(hq, hk, hv, amsk, hz);

    // output projection
    dim3 ogrid(DMODEL / 128, MROWS / 128);
    wo_gemm<<<ogrid, 256, GEMM_SMEM>>>(hz, hwo, b_o, out);

    (void)in_sizes; (void)n_in; (void)out_size;
}

// round 15
// speedup vs baseline: 2.5563x; 1.1019x over previous
#include <cuda_runtime.h>
#include <cuda_fp16.h>
#include <cstdint>
#include <math.h>

#define S_LEN   2048
#define BATCH   2
#define DMODEL  1024
#define NHEADS  16
#define DHEAD   64
#define MROWS   (BATCH * S_LEN)   // 4096
#define IGNORE_VAL (-100000.0f)

// ---------------- scratch (half everywhere) ----------------
__device__ __half g_hxq[MROWS * DMODEL];
__device__ __half g_hxk[MROWS * DMODEL];
__device__ __half g_hxv[MROWS * DMODEL];
__device__ __half g_hwq[DMODEL * DMODEL];   // [n][k]
__device__ __half g_hwk[DMODEL * DMODEL];
__device__ __half g_hwv[DMODEL * DMODEL];
__device__ __half g_hwo[DMODEL * DMODEL];   // [n][k]
__device__ __half g_hq[MROWS * DMODEL];
__device__ __half g_hk[MROWS * DMODEL];
__device__ __half g_hv[MROWS * DMODEL];
__device__ __half g_hz[MROWS * DMODEL];

// ---------------- helpers ----------------
__device__ __forceinline__ uint32_t smem_u32(const void* p) {
    uint32_t a;
    asm("{ .reg .u64 t; cvta.to.shared.u64 t, %1; cvt.u32.u64 %0, t; }" : "=r"(a) : "l"(p));
    return a;
}
__device__ __forceinline__ uint32_t pack_h2(float a, float b) {
    __half2 h = __float22half2_rn(make_float2(a, b));
    return *reinterpret_cast<uint32_t*>(&h);
}
__device__ __forceinline__ void cp_async16(uint32_t dst, const void* src) {
    asm volatile("cp.async.cg.shared.global [%0], [%1], 16;" :: "r"(dst), "l"(src));
}
__device__ __forceinline__ void cp_commit() {
    asm volatile("cp.async.commit_group;" ::: "memory");
}
template <int N>
__device__ __forceinline__ void cp_wait() {
    asm volatile("cp.async.wait_group %0;" :: "n"(N) : "memory");
}
__device__ __forceinline__ void ldsm_x4(uint32_t& r0, uint32_t& r1, uint32_t& r2, uint32_t& r3,
                                        uint32_t addr) {
    asm volatile("ldmatrix.sync.aligned.m8n8.x4.shared.b16 {%0,%1,%2,%3}, [%4];"
        : "=r"(r0), "=r"(r1), "=r"(r2), "=r"(r3) : "r"(addr));
}
__device__ __forceinline__ void ldsm_x4_trans(uint32_t& r0, uint32_t& r1, uint32_t& r2, uint32_t& r3,
                                              uint32_t addr) {
    asm volatile("ldmatrix.sync.aligned.m8n8.x4.trans.shared.b16 {%0,%1,%2,%3}, [%4];"
        : "=r"(r0), "=r"(r1), "=r"(r2), "=r"(r3) : "r"(addr));
}
__device__ __forceinline__ void mma_f16_16x8x16(
    float* d, const uint32_t* a, const uint32_t* b, const float* c)
{
    asm volatile(
        "mma.sync.aligned.m16n8k16.row.col.f32.f16.f16.f32 "
        "{%0,%1,%2,%3}, {%4,%5,%6,%7}, {%8,%9}, {%10,%11,%12,%13};\n"
        : "=f"(d[0]), "=f"(d[1]), "=f"(d[2]), "=f"(d[3])
        : "r"(a[0]), "r"(a[1]), "r"(a[2]), "r"(a[3]),
          "r"(b[0]), "r"(b[1]),
          "f"(c[0]), "f"(c[1]), "f"(c[2]), "f"(c[3]));
}

// ================= conversion kernels (unchanged) =================
__global__ void conv_x(const float* __restrict__ xq, const float* __restrict__ xk,
                       const float* __restrict__ xv,
                       __half* __restrict__ hq, __half* __restrict__ hk,
                       __half* __restrict__ hv)
{
    const float* src = (blockIdx.y == 0) ? xq : (blockIdx.y == 1) ? xk : xv;
    __half* dst = (blockIdx.y == 0) ? hq : (blockIdx.y == 1) ? hk : hv;
    int idx = blockIdx.x * 256 + threadIdx.x;
    float4 v = *(const float4*)(src + (size_t)idx * 4);
    uint32_t* d = (uint32_t*)(dst + (size_t)idx * 4);
    d[0] = pack_h2(v.x, v.y);
    d[1] = pack_h2(v.z, v.w);
}

__global__ void conv_w(const float* __restrict__ wq, const float* __restrict__ wk,
                       const float* __restrict__ wv,
                       __half* __restrict__ hwq, __half* __restrict__ hwk,
                       __half* __restrict__ hwv)
{
    __shared__ float s[64][65];
    const float* W = (blockIdx.z == 0) ? wq : (blockIdx.z == 1) ? wk : wv;
    __half* hw = (blockIdx.z == 0) ? hwq : (blockIdx.z == 1) ? hwk : hwv;
    const int k0 = blockIdx.x * 64;
    const int h  = blockIdx.y;
    const int tid = threadIdx.x;
#pragma unroll
    for (int it = 0; it < 4; it++) {
        int idx = tid + it * 256;
        int kk = idx >> 4, d4 = (idx & 15) * 4;
        float4 v = *(const float4*)(W + (size_t)h * DMODEL * DHEAD + (size_t)(k0 + kk) * DHEAD + d4);
        s[kk][d4 + 0] = v.x; s[kk][d4 + 1] = v.y;
        s[kk][d4 + 2] = v.z; s[kk][d4 + 3] = v.w;
    }
    __syncthreads();
    int d = tid >> 2, seg = (tid & 3) * 16;
    uint32_t* dst = (uint32_t*)(hw + (size_t)(h * 64 + d) * DMODEL + k0 + seg);
#pragma unroll
    for (int j = 0; j < 8; j++)
        dst[j] = pack_h2(s[seg + 2 * j][d], s[seg + 2 * j + 1][d]);
}

__global__ void conv_wo(const float* __restrict__ w, __half* __restrict__ hwo)
{
    __shared__ float s[64][65];
    const int k0 = blockIdx.x * 64;
    const int n0 = blockIdx.y * 64;
    const int tid = threadIdx.x;
#pragma unroll
    for (int it = 0; it < 4; it++) {
        int idx = tid + it * 256;
        int kk = idx >> 4, n4 = (idx & 15) * 4;
        float4 v = *(const float4*)(w + (size_t)(k0 + kk) * DMODEL + n0 + n4);
        s[kk][n4 + 0] = v.x; s[kk][n4 + 1] = v.y;
        s[kk][n4 + 2] = v.z; s[kk][n4 + 3] = v.w;
    }
    __syncthreads();
    int n = tid >> 2, seg = (tid & 3) * 16;
    uint32_t* dst = (uint32_t*)(hwo + (size_t)(n0 + n) * DMODEL + k0 + seg);
#pragma unroll
    for (int j = 0; j < 8; j++)
        dst[j] = pack_h2(s[seg + 2 * j][n], s[seg + 2 * j + 1][n]);
}

// ============ half GEMM: 3-stage cp.async ring + ldmatrix (unchanged R13/R14) ============
#define TSg 36
#define GEMM_SMEM (6 * 128 * TSg * 4)   // 110,592 B

__device__ __forceinline__ void gemm_pipe(
    const __half* __restrict__ A, const __half* __restrict__ B,
    uint32_t* smg, int n0, int m0, float acc[4][4][4])
{
    const int tid = threadIdx.x;
    const int wid = tid >> 5;
    const int lid = tid & 31;
    const int wm  = wid >> 2;
    const int wn  = wid & 3;

    uint32_t stA[3], stB[3];
#pragma unroll
    for (int s = 0; s < 3; s++) {
        stA[s] = smem_u32(smg + s * 256 * TSg);
        stB[s] = stA[s] + 128 * TSg * 4;
    }

#pragma unroll
    for (int i = 0; i < 4; i++)
#pragma unroll
        for (int j = 0; j < 4; j++)
#pragma unroll
            for (int f = 0; f < 4; f++) acc[i][j][f] = 0.0f;

    auto load_chunk = [&](int c, int s) {
        const int k0 = c * 64;
        const uint32_t aA = stA[s], aB = stB[s];
#pragma unroll
        for (int it = 0; it < 4; it++) {
            int i = tid + it * 256;
            int row = i >> 3, j = i & 7;
            cp_async16(aA + (uint32_t)((row * TSg + j * 4) << 2),
                       A + (size_t)(m0 + row) * DMODEL + k0 + j * 8);
            cp_async16(aB + (uint32_t)((row * TSg + j * 4) << 2),
                       B + (size_t)(n0 + row) * DMODEL + k0 + j * 8);
        }
        cp_commit();
    };

    const int m8   = lid >> 3;
    const int a_row = (lid & 7) + (m8 & 1) * 8;
    const int a_cw  = (m8 >> 1) * 4;
    const int b_row = (lid & 7) + (m8 >> 1) * 8;
    const int b_cw  = (m8 & 1) * 4;

    load_chunk(0, 0);
    load_chunk(1, 1);

    const int NCH = DMODEL / 64;   // 16
    for (int c = 0; c < NCH; c++) {
        cp_wait<1>();
        __syncthreads();
        if (c + 2 < NCH) load_chunk(c + 2, (c + 2) % 3);

        const int s = c % 3;
        const uint32_t aA = stA[s], aB = stB[s];
#pragma unroll
        for (int kk = 0; kk < 4; kk++) {
            uint32_t af[4][4], bf[4][2];
#pragma unroll
            for (int mi = 0; mi < 4; mi++) {
                uint32_t addr = aA + (uint32_t)((((wm * 64 + mi * 16 + a_row) * TSg)
                                                + kk * 8 + a_cw) << 2);
                ldsm_x4(af[mi][0], af[mi][1], af[mi][2], af[mi][3], addr);
            }
#pragma unroll
            for (int njp = 0; njp < 2; njp++) {
                uint32_t addr = aB + (uint32_t)((((wn * 32 + njp * 16 + b_row) * TSg)
                                                + kk * 8 + b_cw) << 2);
                ldsm_x4(bf[2 * njp][0], bf[2 * njp][1],
                        bf[2 * njp + 1][0], bf[2 * njp + 1][1], addr);
            }
#pragma unroll
            for (int mi = 0; mi < 4; mi++)
#pragma unroll
                for (int nj = 0; nj < 4; nj++)
                    mma_f16_16x8x16(acc[mi][nj], af[mi], bf[nj], acc[mi][nj]);
        }
    }
}

__global__ __launch_bounds__(256, 2) void qkv_gemm(
    const __half* __restrict__ xq, const __half* __restrict__ xk, const __half* __restrict__ xv,
    const __half* __restrict__ wq, const __half* __restrict__ wk, const __half* __restrict__ wv,
    const float* __restrict__ bq, const float* __restrict__ bk, const float* __restrict__ bv,
    __half* __restrict__ cq, __half* __restrict__ ck, __half* __restrict__ cv)
{
    extern __shared__ uint32_t smg[];
    const __half* A = (blockIdx.z == 0) ? xq : (blockIdx.z == 1) ? xk : xv;
    const __half* B = (blockIdx.z == 0) ? wq : (blockIdx.z == 1) ? wk : wv;
    const float* bias = (blockIdx.z == 0) ? bq : (blockIdx.z == 1) ? bk : bv;
    __half*      C = (blockIdx.z == 0) ? cq : (blockIdx.z == 1) ? ck : cv;
    const int n0 = blockIdx.x * 128, m0 = blockIdx.y * 128;

    float acc[4][4][4];
    gemm_pipe(A, B, smg, n0, m0, acc);

    const int lid = threadIdx.x & 31;
    const int g = lid >> 2, tig = lid & 3;
    const int wm = (threadIdx.x >> 5) >> 2, wn = (threadIdx.x >> 5) & 3;
#pragma unroll
    for (int mi = 0; mi < 4; mi++) {
        int r0 = m0 + wm * 64 + mi * 16 + g;
#pragma unroll
        for (int nj = 0; nj < 4; nj++) {
            int c0 = n0 + wn * 32 + nj * 8 + tig * 2;
            float b0 = bias[c0], b1 = bias[c0 + 1];
            *(uint32_t*)(C + (size_t)r0 * DMODEL + c0) =
                pack_h2(acc[mi][nj][0] + b0, acc[mi][nj][1] + b1);
            *(uint32_t*)(C + (size_t)(r0 + 8) * DMODEL + c0) =
                pack_h2(acc[mi][nj][2] + b0, acc[mi][nj][3] + b1);
        }
    }
}

__global__ __launch_bounds__(256, 2) void wo_gemm(
    const __half* __restrict__ A, const __half* __restrict__ B,
    const float* __restrict__ bias, float* __restrict__ C)
{
    extern __shared__ uint32_t smg[];
    const int n0 = blockIdx.x * 128, m0 = blockIdx.y * 128;

    float acc[4][4][4];
    gemm_pipe(A, B, smg, n0, m0, acc);

    const int lid = threadIdx.x & 31;
    const int g = lid >> 2, tig = lid & 3;
    const int wm = (threadIdx.x >> 5) >> 2, wn = (threadIdx.x >> 5) & 3;
#pragma unroll
    for (int mi = 0; mi < 4; mi++) {
        int r0 = m0 + wm * 64 + mi * 16 + g;
#pragma unroll
        for (int nj = 0; nj < 4; nj++) {
            int c0 = n0 + wn * 32 + nj * 8 + tig * 2;
            float b0 = bias[c0], b1 = bias[c0 + 1];
            *(float2*)(C + (size_t)r0 * DMODEL + c0) =
                make_float2(acc[mi][nj][0] + b0, acc[mi][nj][1] + b1);
            *(float2*)(C + (size_t)(r0 + 8) * DMODEL + c0) =
                make_float2(acc[mi][nj][2] + b0, acc[mi][nj][3] + b1);
        }
    }
}

// ============ flash attention: 128-thr CTAs, cp.async K/V, ldsm.trans V ============
// smem (words, stride FSH=36): Q[0,64) | K0[64,128) | V0[128,192) | K1[192,256) | V1[256,320)
// K and V both stored row-major [kpos][d].
#define FSH 36
#define FL_SMEM (320 * FSH * 4)   // 46,080 B

__global__ __launch_bounds__(128, 4) void flash_attn_h(
    const __half* __restrict__ q, const __half* __restrict__ k,
    const __half* __restrict__ v, const float* __restrict__ amask,
    __half* __restrict__ z)
{
    extern __shared__ uint32_t sm[];
    uint32_t* Qs = sm;                   // 64 x FSH

    const int qt = (int)(gridDim.x - 1 - blockIdx.x);   // longest first
    const int h  = blockIdx.y;
    const int b  = blockIdx.z;
    const int tid = threadIdx.x;
    const int lid = tid & 31;
    const int g   = lid >> 2;
    const int tig = lid & 3;
    const int r0  = (tid >> 5) * 16;     // warp 0..3 -> rows 0..63

    const uint32_t smbase = smem_u32(sm);

    // ldmatrix lane mappings
    const int m8    = lid >> 3;
    const int a_row = (lid & 7) + (m8 & 1) * 8;
    const int a_cw  = (m8 >> 1) * 4;
    const int b_row = (lid & 7) + (m8 >> 1) * 8;
    const int b_cw  = (m8 & 1) * 4;
    const int v_row = (lid & 7) + (m8 & 1) * 8;      // kpos within k16 block
    const int v_cb  = (m8 >> 1) * 16;                // byte offset in d

    const size_t base = (size_t)b * S_LEN;
    const __half* qp = q + (base + qt * 64) * DMODEL + h * 64;

    // cp.async K/V tile loader (64 rows x 64 halfs each)
    auto load_tile = [&](int kt, int buf) {
        const __half* kp = k + (base + kt * 64) * DMODEL + h * 64;
        const __half* vp = v + (base + kt * 64) * DMODEL + h * 64;
        const uint32_t Kb = smbase + (uint32_t)(((64 + buf * 128) * FSH) << 2);
        const uint32_t Vb = Kb + (uint32_t)((64 * FSH) << 2);
#pragma unroll
        for (int it = 0; it < 4; it++) {
            int i = tid + it * 128;
            int row = i >> 3, j = i & 7;
            cp_async16(Kb + (uint32_t)((row * FSH + j * 4) << 2),
                       kp + (size_t)row * DMODEL + j * 8);
            cp_async16(Vb + (uint32_t)((row * FSH + j * 4) << 2),
                       vp + (size_t)row * DMODEL + j * 8);
        }
        cp_commit();
    };

    load_tile(0, 0);

    // Q tile: 64 rows x 64 halfs = 512 uint4
#pragma unroll
    for (int it = 0; it < 4; it++) {
        int i = tid + it * 128;
        int row = i >> 3, j = i & 7;
        *(uint4*)(Qs + row * FSH + j * 4) =
            *(const uint4*)((const char*)(qp + (size_t)row * DMODEL) + j * 16);
    }

    float o[8][4];
#pragma unroll
    for (int nj = 0; nj < 8; nj++)
#pragma unroll
        for (int f = 0; f < 4; f++) o[nj][f] = 0.0f;
    float mrow0 = -1e30f, mrow1 = -1e30f;
    float lrow0 = 0.0f,  lrow1 = 0.0f;

    const int qi0 = qt * 64 + r0 + g;
    const int qi1 = qi0 + 8;
    const int nkt = qt + 1;

    for (int kt = 0; kt < nkt; kt++) {
        cp_wait<0>();      // K/V tile kt landed
        __syncthreads();   // visible to all; prior readers of other buffer done
        if (kt + 1 < nkt) load_tile(kt + 1, (kt + 1) & 1);

        const uint32_t Ksb = smbase + (uint32_t)(((64 + (kt & 1) * 128) * FSH) << 2);
        const uint32_t Vsb = Ksb + (uint32_t)((64 * FSH) << 2);

        // ---- S = Q K^T ----
        float sacc[8][4];
#pragma unroll
        for (int nj = 0; nj < 8; nj++)
#pragma unroll
            for (int f = 0; f < 4; f++) sacc[nj][f] = 0.0f;

#pragma unroll
        for (int kk = 0; kk < 4; kk++) {
            uint32_t a[4];
            ldsm_x4(a[0], a[1], a[2], a[3],
                    smbase + (uint32_t)((((r0 + a_row) * FSH) + kk * 8 + a_cw) << 2));
#pragma unroll
            for (int njp = 0; njp < 4; njp++) {
                uint32_t b0, b1, b2, b3;
                ldsm_x4(b0, b1, b2, b3,
                        Ksb + (uint32_t)((((njp * 16 + b_row) * FSH) + kk * 8 + b_cw) << 2));
                uint32_t bb0[2] = { b0, b1 };
                uint32_t bb1[2] = { b2, b3 };
                mma_f16_16x8x16(sacc[2 * njp],     a, bb0, sacc[2 * njp]);
                mma_f16_16x8x16(sacc[2 * njp + 1], a, bb1, sacc[2 * njp + 1]);
            }
        }

        // ---- scale, causal, additive mask ----
        float tmax0 = -1e30f, tmax1 = -1e30f;
#pragma unroll
        for (int nj = 0; nj < 8; nj++) {
            int kj = kt * 64 + nj * 8 + tig * 2;
            float am0 = amask[b * S_LEN + kj];
            float am1 = amask[b * S_LEN + kj + 1];
            float s0 = ((kj     <= qi0) ? sacc[nj][0] * 0.125f : IGNORE_VAL) + am0;
            float s1 = ((kj + 1 <= qi0) ? sacc[nj][1] * 0.125f : IGNORE_VAL) + am1;
            float s2 = ((kj     <= qi1) ? sacc[nj][2] * 0.125f : IGNORE_VAL) + am0;
            float s3 = ((kj + 1 <= qi1) ? sacc[nj][3] * 0.125f : IGNORE_VAL) + am1;
            sacc[nj][0] = s0; sacc[nj][1] = s1; sacc[nj][2] = s2; sacc[nj][3] = s3;
            tmax0 = fmaxf(tmax0, fmaxf(s0, s1));
            tmax1 = fmaxf(tmax1, fmaxf(s2, s3));
        }
        tmax0 = fmaxf(tmax0, __shfl_xor_sync(0xffffffffu, tmax0, 1));
        tmax0 = fmaxf(tmax0, __shfl_xor_sync(0xffffffffu, tmax0, 2));
        tmax1 = fmaxf(tmax1, __shfl_xor_sync(0xffffffffu, tmax1, 1));
        tmax1 = fmaxf(tmax1, __shfl_xor_sync(0xffffffffu, tmax1, 2));

        float mn0 = fmaxf(mrow0, tmax0);
        float mn1 = fmaxf(mrow1, tmax1);
        float alpha0 = __expf(mrow0 - mn0);
        float alpha1 = __expf(mrow1 - mn1);
        mrow0 = mn0; mrow1 = mn1;

        float rs0 = 0.0f, rs1 = 0.0f;
#pragma unroll
        for (int nj = 0; nj < 8; nj++) {
            float p0 = __expf(sacc[nj][0] - mn0);
            float p1 = __expf(sacc[nj][1] - mn0);
            float p2 = __expf(sacc[nj][2] - mn1);
            float p3 = __expf(sacc[nj][3] - mn1);
            sacc[nj][0] = p0; sacc[nj][1] = p1; sacc[nj][2] = p2; sacc[nj][3] = p3;
            rs0 += p0 + p1;
            rs1 += p2 + p3;
        }
        rs0 += __shfl_xor_sync(0xffffffffu, rs0, 1);
        rs0 += __shfl_xor_sync(0xffffffffu, rs0, 2);
        rs1 += __shfl_xor_sync(0xffffffffu, rs1, 1);
        rs1 += __shfl_xor_sync(0xffffffffu, rs1, 2);
        lrow0 = lrow0 * alpha0 + rs0;
        lrow1 = lrow1 * alpha1 + rs1;

#pragma unroll
        for (int nj = 0; nj < 8; nj++) {
            o[nj][0] *= alpha0; o[nj][1] *= alpha0;
            o[nj][2] *= alpha1; o[nj][3] *= alpha1;
        }

        // ---- O += P V : P in registers, V row-major via ldsm.trans ----
#pragma unroll
        for (int kk = 0; kk < 4; kk++) {
            uint32_t a[4];
            a[0] = pack_h2(sacc[2 * kk][0],     sacc[2 * kk][1]);
            a[1] = pack_h2(sacc[2 * kk][2],     sacc[2 * kk][3]);
            a[2] = pack_h2(sacc[2 * kk + 1][0], sacc[2 * kk + 1][1]);
            a[3] = pack_h2(sacc[2 * kk + 1][2], sacc[2 * kk + 1][3]);
#pragma unroll
            for (int njp = 0; njp < 4; njp++) {
                uint32_t b0, b1, b2, b3;
                ldsm_x4_trans(b0, b1, b2, b3,
                    Vsb + (uint32_t)((((kk * 16 + v_row) * FSH) << 2)
                                     + njp * 32 + v_cb));
                uint32_t bb0[2] = { b0, b1 };
                uint32_t bb1[2] = { b2, b3 };
                mma_f16_16x8x16(o[2 * njp],     a, bb0, o[2 * njp]);
                mma_f16_16x8x16(o[2 * njp + 1], a, bb1, o[2 * njp + 1]);
            }
        }
    }

    // ---- epilogue: write z as half ----
    float inv0 = 1.0f / lrow0;
    float inv1 = 1.0f / lrow1;
    const size_t row0 = base + qt * 64 + r0 + g;
#pragma unroll
    for (int nj = 0; nj < 8; nj++) {
        int col = h * 64 + nj * 8 + tig * 2;
        *(uint32_t*)(z + row0 * DMODEL + col) =
            pack_h2(o[nj][0] * inv0, o[nj][1] * inv0);
        *(uint32_t*)(z + (row0 + 8) * DMODEL + col) =
            pack_h2(o[nj][2] * inv1, o[nj][3] * inv1);
    }
}

// ---------------- launch ----------------
extern "C" void kernel_launch(void* const* d_in, const int* in_sizes, int n_in,
                              void* d_out, int out_size)
{
    const float* x_q  = (const float*)d_in[0];
    const float* x_k  = (const float*)d_in[1];
    const float* x_v  = (const float*)d_in[2];
    const float* amsk = (const float*)d_in[3];
    const float* w_q  = (const float*)d_in[4];
    const float* w_k  = (const float*)d_in[5];
    const float* w_v  = (const float*)d_in[6];
    const float* w_o  = (const float*)d_in[7];
    const float* b_q  = (const float*)d_in[8];
    const float* b_k  = (const float*)d_in[9];
    const float* b_v  = (const float*)d_in[10];
    const float* b_o  = (const float*)d_in[11];
    float* out = (float*)d_out;

    __half *hxq, *hxk, *hxv, *hwq, *hwk, *hwv, *hwo, *hq, *hk, *hv, *hz;
    cudaGetSymbolAddress((void**)&hxq, g_hxq);
    cudaGetSymbolAddress((void**)&hxk, g_hxk);
    cudaGetSymbolAddress((void**)&hxv, g_hxv);
    cudaGetSymbolAddress((void**)&hwq, g_hwq);
    cudaGetSymbolAddress((void**)&hwk, g_hwk);
    cudaGetSymbolAddress((void**)&hwv, g_hwv);
    cudaGetSymbolAddress((void**)&hwo, g_hwo);
    cudaGetSymbolAddress((void**)&hq,  g_hq);
    cudaGetSymbolAddress((void**)&hk,  g_hk);
    cudaGetSymbolAddress((void**)&hv,  g_hv);
    cudaGetSymbolAddress((void**)&hz,  g_hz);

    cudaFuncSetAttribute(flash_attn_h, cudaFuncAttributeMaxDynamicSharedMemorySize, FL_SMEM);
    cudaFuncSetAttribute(qkv_gemm, cudaFuncAttributeMaxDynamicSharedMemorySize, GEMM_SMEM);
    cudaFuncSetAttribute(wo_gemm, cudaFuncAttributeMaxDynamicSharedMemorySize, GEMM_SMEM);

    // conversions
    dim3 cxg(MROWS * DMODEL / (256 * 4), 3);
    conv_x<<<cxg, 256>>>(x_q, x_k, x_v, hxq, hxk, hxv);
    dim3 cwg(DMODEL / 64, NHEADS, 3);
    conv_w<<<cwg, 256>>>(w_q, w_k, w_v, hwq, hwk, hwv);
    dim3 cog(DMODEL / 64, DMODEL / 64);
    conv_wo<<<cog, 256>>>(w_o, hwo);

    // QKV projections
    dim3 qgrid(DMODEL / 128, MROWS / 128, 3);
    qkv_gemm<<<qgrid, 256, GEMM_SMEM>>>(hxq, hxk, hxv, hwq, hwk, hwv,
                                        b_q, b_k, b_v, hq, hk, hv);

    // flash attention (64-row Q tiles, 128-thread CTAs)
    dim3 fgrid(S_LEN / 64, NHEADS, BATCH);   // (32, 16, 2)
    flash_attn_h<<<fgrid, 128, FL_SMEM>>>(hq, hk, hv, amsk, hz);

    // output projection
    dim3 ogrid(DMODEL / 128, MROWS / 128);
    wo_gemm<<<ogrid, 256, GEMM_SMEM>>>(hz, hwo, b_o, out);

    (void)in_sizes; (void)n_in; (void)out_size;
}

// round 16
// speedup vs baseline: 2.5779x; 1.0085x over previous
#include <cuda_runtime.h>
#include <cuda_fp16.h>
#include <cstdint>
#include <math.h>

#define S_LEN   2048
#define BATCH   2
#define DMODEL  1024
#define NHEADS  16
#define DHEAD   64
#define MROWS   (BATCH * S_LEN)   // 4096
#define IGNORE_VAL (-100000.0f)

// ---------------- scratch (half everywhere) ----------------
__device__ __half g_hxq[MROWS * DMODEL];
__device__ __half g_hxk[MROWS * DMODEL];
__device__ __half g_hxv[MROWS * DMODEL];
__device__ __half g_hwq[DMODEL * DMODEL];   // [n][k]
__device__ __half g_hwk[DMODEL * DMODEL];
__device__ __half g_hwv[DMODEL * DMODEL];
__device__ __half g_hwo[DMODEL * DMODEL];   // [n][k]
__device__ __half g_hq[MROWS * DMODEL];
__device__ __half g_hk[MROWS * DMODEL];
__device__ __half g_hv[MROWS * DMODEL];
__device__ __half g_hz[MROWS * DMODEL];

// ---------------- helpers ----------------
__device__ __forceinline__ uint32_t smem_u32(const void* p) {
    uint32_t a;
    asm("{ .reg .u64 t; cvta.to.shared.u64 t, %1; cvt.u32.u64 %0, t; }" : "=r"(a) : "l"(p));
    return a;
}
__device__ __forceinline__ uint32_t pack_h2(float a, float b) {
    __half2 h = __float22half2_rn(make_float2(a, b));
    return *reinterpret_cast<uint32_t*>(&h);
}
__device__ __forceinline__ void cp_async16(uint32_t dst, const void* src) {
    asm volatile("cp.async.cg.shared.global [%0], [%1], 16;" :: "r"(dst), "l"(src));
}
__device__ __forceinline__ void cp_commit() {
    asm volatile("cp.async.commit_group;" ::: "memory");
}
template <int N>
__device__ __forceinline__ void cp_wait() {
    asm volatile("cp.async.wait_group %0;" :: "n"(N) : "memory");
}
__device__ __forceinline__ void ldsm_x4(uint32_t& r0, uint32_t& r1, uint32_t& r2, uint32_t& r3,
                                        uint32_t addr) {
    asm volatile("ldmatrix.sync.aligned.m8n8.x4.shared.b16 {%0,%1,%2,%3}, [%4];"
        : "=r"(r0), "=r"(r1), "=r"(r2), "=r"(r3) : "r"(addr));
}
__device__ __forceinline__ void ldsm_x4_trans(uint32_t& r0, uint32_t& r1, uint32_t& r2, uint32_t& r3,
                                              uint32_t addr) {
    asm volatile("ldmatrix.sync.aligned.m8n8.x4.trans.shared.b16 {%0,%1,%2,%3}, [%4];"
        : "=r"(r0), "=r"(r1), "=r"(r2), "=r"(r3) : "r"(addr));
}
__device__ __forceinline__ void mma_f16_16x8x16(
    float* d, const uint32_t* a, const uint32_t* b, const float* c)
{
    asm volatile(
        "mma.sync.aligned.m16n8k16.row.col.f32.f16.f16.f32 "
        "{%0,%1,%2,%3}, {%4,%5,%6,%7}, {%8,%9}, {%10,%11,%12,%13};\n"
        : "=f"(d[0]), "=f"(d[1]), "=f"(d[2]), "=f"(d[3])
        : "r"(a[0]), "r"(a[1]), "r"(a[2]), "r"(a[3]),
          "r"(b[0]), "r"(b[1]),
          "f"(c[0]), "f"(c[1]), "f"(c[2]), "f"(c[3]));
}

// ================= merged conversion kernel =================
// flat grid: [0, 12288)   : conv_x   (3 x 4096 blocks, 1 float4/thread)
//            [12288,13056): conv_w   (3 x 16h x 16ktile)
//            [13056,13312): conv_wo  (16n x 16k)
__global__ void conv_all(
    const float* __restrict__ xq, const float* __restrict__ xk, const float* __restrict__ xv,
    const float* __restrict__ wq, const float* __restrict__ wk, const float* __restrict__ wv,
    const float* __restrict__ wo,
    __half* __restrict__ hxq, __half* __restrict__ hxk, __half* __restrict__ hxv,
    __half* __restrict__ hwq, __half* __restrict__ hwk, __half* __restrict__ hwv,
    __half* __restrict__ hwo)
{
    __shared__ float s[64][65];
    const int bid = blockIdx.x;
    const int tid = threadIdx.x;

    if (bid < 12288) {
        // ---- x conversion ----
        const int which = bid >> 12;          // /4096
        const int xb    = bid & 4095;
        const float* src = (which == 0) ? xq : (which == 1) ? xk : xv;
        __half* dst = (which == 0) ? hxq : (which == 1) ? hxk : hxv;
        int idx = xb * 256 + tid;             // float4 index
        float4 v = *(const float4*)(src + (size_t)idx * 4);
        uint32_t* d = (uint32_t*)(dst + (size_t)idx * 4);
        d[0] = pack_h2(v.x, v.y);
        d[1] = pack_h2(v.z, v.w);
    } else if (bid < 13056) {
        // ---- QKV weight transpose: W[h][k][d] -> hw[(h*64+d)][k] ----
        const int j  = bid - 12288;
        const int z  = j >> 8;                // /256
        const int rem = j & 255;
        const int h  = rem >> 4;
        const int k0 = (rem & 15) * 64;
        const float* W = (z == 0) ? wq : (z == 1) ? wk : wv;
        __half* hw = (z == 0) ? hwq : (z == 1) ? hwk : hwv;
#pragma unroll
        for (int it = 0; it < 4; it++) {
            int idx = tid + it * 256;
            int kk = idx >> 4, d4 = (idx & 15) * 4;
            float4 v = *(const float4*)(W + (size_t)h * DMODEL * DHEAD + (size_t)(k0 + kk) * DHEAD + d4);
            s[kk][d4 + 0] = v.x; s[kk][d4 + 1] = v.y;
            s[kk][d4 + 2] = v.z; s[kk][d4 + 3] = v.w;
        }
        __syncthreads();
        int d = tid >> 2, seg = (tid & 3) * 16;
        uint32_t* dst = (uint32_t*)(hw + (size_t)(h * 64 + d) * DMODEL + k0 + seg);
#pragma unroll
        for (int jj = 0; jj < 8; jj++)
            dst[jj] = pack_h2(s[seg + 2 * jj][d], s[seg + 2 * jj + 1][d]);
    } else {
        // ---- W_O transpose: w[k][n] -> hwo[n][k] ----
        const int j  = bid - 13056;
        const int k0 = (j & 15) * 64;
        const int n0 = (j >> 4) * 64;
#pragma unroll
        for (int it = 0; it < 4; it++) {
            int idx = tid + it * 256;
            int kk = idx >> 4, n4 = (idx & 15) * 4;
            float4 v = *(const float4*)(wo + (size_t)(k0 + kk) * DMODEL + n0 + n4);
            s[kk][n4 + 0] = v.x; s[kk][n4 + 1] = v.y;
            s[kk][n4 + 2] = v.z; s[kk][n4 + 3] = v.w;
        }
        __syncthreads();
        int n = tid >> 2, seg = (tid & 3) * 16;
        uint32_t* dst = (uint32_t*)(hwo + (size_t)(n0 + n) * DMODEL + k0 + seg);
#pragma unroll
        for (int jj = 0; jj < 8; jj++)
            dst[jj] = pack_h2(s[seg + 2 * jj][n], s[seg + 2 * jj + 1][n]);
    }
}

// ============ half GEMM: 3-stage cp.async ring + ldmatrix (unchanged) ============
#define TSg 36
#define GEMM_SMEM (6 * 128 * TSg * 4)   // 110,592 B

__device__ __forceinline__ void gemm_pipe(
    const __half* __restrict__ A, const __half* __restrict__ B,
    uint32_t* smg, int n0, int m0, float acc[4][4][4])
{
    const int tid = threadIdx.x;
    const int wid = tid >> 5;
    const int lid = tid & 31;
    const int wm  = wid >> 2;
    const int wn  = wid & 3;

    uint32_t stA[3], stB[3];
#pragma unroll
    for (int s = 0; s < 3; s++) {
        stA[s] = smem_u32(smg + s * 256 * TSg);
        stB[s] = stA[s] + 128 * TSg * 4;
    }

#pragma unroll
    for (int i = 0; i < 4; i++)
#pragma unroll
        for (int j = 0; j < 4; j++)
#pragma unroll
            for (int f = 0; f < 4; f++) acc[i][j][f] = 0.0f;

    auto load_chunk = [&](int c, int s) {
        const int k0 = c * 64;
        const uint32_t aA = stA[s], aB = stB[s];
#pragma unroll
        for (int it = 0; it < 4; it++) {
            int i = tid + it * 256;
            int row = i >> 3, j = i & 7;
            cp_async16(aA + (uint32_t)((row * TSg + j * 4) << 2),
                       A + (size_t)(m0 + row) * DMODEL + k0 + j * 8);
            cp_async16(aB + (uint32_t)((row * TSg + j * 4) << 2),
                       B + (size_t)(n0 + row) * DMODEL + k0 + j * 8);
        }
        cp_commit();
    };

    const int m8   = lid >> 3;
    const int a_row = (lid & 7) + (m8 & 1) * 8;
    const int a_cw  = (m8 >> 1) * 4;
    const int b_row = (lid & 7) + (m8 >> 1) * 8;
    const int b_cw  = (m8 & 1) * 4;

    load_chunk(0, 0);
    load_chunk(1, 1);

    const int NCH = DMODEL / 64;   // 16
    for (int c = 0; c < NCH; c++) {
        cp_wait<1>();
        __syncthreads();
        if (c + 2 < NCH) load_chunk(c + 2, (c + 2) % 3);

        const int s = c % 3;
        const uint32_t aA = stA[s], aB = stB[s];
#pragma unroll
        for (int kk = 0; kk < 4; kk++) {
            uint32_t af[4][4], bf[4][2];
#pragma unroll
            for (int mi = 0; mi < 4; mi++) {
                uint32_t addr = aA + (uint32_t)((((wm * 64 + mi * 16 + a_row) * TSg)
                                                + kk * 8 + a_cw) << 2);
                ldsm_x4(af[mi][0], af[mi][1], af[mi][2], af[mi][3], addr);
            }
#pragma unroll
            for (int njp = 0; njp < 2; njp++) {
                uint32_t addr = aB + (uint32_t)((((wn * 32 + njp * 16 + b_row) * TSg)
                                                + kk * 8 + b_cw) << 2);
                ldsm_x4(bf[2 * njp][0], bf[2 * njp][1],
                        bf[2 * njp + 1][0], bf[2 * njp + 1][1], addr);
            }
#pragma unroll
            for (int mi = 0; mi < 4; mi++)
#pragma unroll
                for (int nj = 0; nj < 4; nj++)
                    mma_f16_16x8x16(acc[mi][nj], af[mi], bf[nj], acc[mi][nj]);
        }
    }
}

__global__ __launch_bounds__(256, 2) void qkv_gemm(
    const __half* __restrict__ xq, const __half* __restrict__ xk, const __half* __restrict__ xv,
    const __half* __restrict__ wq, const __half* __restrict__ wk, const __half* __restrict__ wv,
    const float* __restrict__ bq, const float* __restrict__ bk, const float* __restrict__ bv,
    __half* __restrict__ cq, __half* __restrict__ ck, __half* __restrict__ cv)
{
    extern __shared__ uint32_t smg[];
    const __half* A = (blockIdx.z == 0) ? xq : (blockIdx.z == 1) ? xk : xv;
    const __half* B = (blockIdx.z == 0) ? wq : (blockIdx.z == 1) ? wk : wv;
    const float* bias = (blockIdx.z == 0) ? bq : (blockIdx.z == 1) ? bk : bv;
    __half*      C = (blockIdx.z == 0) ? cq : (blockIdx.z == 1) ? ck : cv;
    const int n0 = blockIdx.x * 128, m0 = blockIdx.y * 128;

    float acc[4][4][4];
    gemm_pipe(A, B, smg, n0, m0, acc);

    const int lid = threadIdx.x & 31;
    const int g = lid >> 2, tig = lid & 3;
    const int wm = (threadIdx.x >> 5) >> 2, wn = (threadIdx.x >> 5) & 3;
#pragma unroll
    for (int mi = 0; mi < 4; mi++) {
        int r0 = m0 + wm * 64 + mi * 16 + g;
#pragma unroll
        for (int nj = 0; nj < 4; nj++) {
            int c0 = n0 + wn * 32 + nj * 8 + tig * 2;
            float b0 = bias[c0], b1 = bias[c0 + 1];
            *(uint32_t*)(C + (size_t)r0 * DMODEL + c0) =
                pack_h2(acc[mi][nj][0] + b0, acc[mi][nj][1] + b1);
            *(uint32_t*)(C + (size_t)(r0 + 8) * DMODEL + c0) =
                pack_h2(acc[mi][nj][2] + b0, acc[mi][nj][3] + b1);
        }
    }
}

__global__ __launch_bounds__(256, 2) void wo_gemm(
    const __half* __restrict__ A, const __half* __restrict__ B,
    const float* __restrict__ bias, float* __restrict__ C)
{
    extern __shared__ uint32_t smg[];
    const int n0 = blockIdx.x * 128, m0 = blockIdx.y * 128;

    float acc[4][4][4];
    gemm_pipe(A, B, smg, n0, m0, acc);

    const int lid = threadIdx.x & 31;
    const int g = lid >> 2, tig = lid & 3;
    const int wm = (threadIdx.x >> 5) >> 2, wn = (threadIdx.x >> 5) & 3;
#pragma unroll
    for (int mi = 0; mi < 4; mi++) {
        int r0 = m0 + wm * 64 + mi * 16 + g;
#pragma unroll
        for (int nj = 0; nj < 4; nj++) {
            int c0 = n0 + wn * 32 + nj * 8 + tig * 2;
            float b0 = bias[c0], b1 = bias[c0 + 1];
            *(float2*)(C + (size_t)r0 * DMODEL + c0) =
                make_float2(acc[mi][nj][0] + b0, acc[mi][nj][1] + b1);
            *(float2*)(C + (size_t)(r0 + 8) * DMODEL + c0) =
                make_float2(acc[mi][nj][2] + b0, acc[mi][nj][3] + b1);
        }
    }
}

// ============ flash attention: Q frags hoisted to registers ============
// smem (words, stride FSH=36): Q[0,64) | K0[64,128) | V0[128,192) | K1[192,256) | V1[256,320)
#define FSH 36
#define FL_SMEM (320 * FSH * 4)   // 46,080 B

__global__ __launch_bounds__(128, 4) void flash_attn_h(
    const __half* __restrict__ q, const __half* __restrict__ k,
    const __half* __restrict__ v, const float* __restrict__ amask,
    __half* __restrict__ z)
{
    extern __shared__ uint32_t sm[];
    uint32_t* Qs = sm;                   // 64 x FSH

    const int qt = (int)(gridDim.x - 1 - blockIdx.x);   // longest first
    const int h  = blockIdx.y;
    const int b  = blockIdx.z;
    const int tid = threadIdx.x;
    const int lid = tid & 31;
    const int g   = lid >> 2;
    const int tig = lid & 3;
    const int r0  = (tid >> 5) * 16;

    const uint32_t smbase = smem_u32(sm);

    const int m8    = lid >> 3;
    const int a_row = (lid & 7) + (m8 & 1) * 8;
    const int a_cw  = (m8 >> 1) * 4;
    const int b_row = (lid & 7) + (m8 >> 1) * 8;
    const int b_cw  = (m8 & 1) * 4;
    const int v_row = (lid & 7) + (m8 & 1) * 8;
    const int v_cb  = (m8 >> 1) * 16;

    const size_t base = (size_t)b * S_LEN;
    const __half* qp = q + (base + qt * 64) * DMODEL + h * 64;

    auto load_tile = [&](int kt, int buf) {
        const __half* kp = k + (base + kt * 64) * DMODEL + h * 64;
        const __half* vp = v + (base + kt * 64) * DMODEL + h * 64;
        const uint32_t Kb = smbase + (uint32_t)(((64 + buf * 128) * FSH) << 2);
        const uint32_t Vb = Kb + (uint32_t)((64 * FSH) << 2);
#pragma unroll
        for (int it = 0; it < 4; it++) {
            int i = tid + it * 128;
            int row = i >> 3, j = i & 7;
            cp_async16(Kb + (uint32_t)((row * FSH + j * 4) << 2),
                       kp + (size_t)row * DMODEL + j * 8);
            cp_async16(Vb + (uint32_t)((row * FSH + j * 4) << 2),
                       vp + (size_t)row * DMODEL + j * 8);
        }
        cp_commit();
    };

    load_tile(0, 0);

    // Q tile: 64 rows x 64 halfs
#pragma unroll
    for (int it = 0; it < 4; it++) {
        int i = tid + it * 128;
        int row = i >> 3, j = i & 7;
        *(uint4*)(Qs + row * FSH + j * 4) =
            *(const uint4*)((const char*)(qp + (size_t)row * DMODEL) + j * 16);
    }
    __syncthreads();   // Q visible to all warps

    // hoist Q fragments to registers (invariant over kt)
    uint32_t qf[4][4];
#pragma unroll
    for (int kk = 0; kk < 4; kk++)
        ldsm_x4(qf[kk][0], qf[kk][1], qf[kk][2], qf[kk][3],
                smbase + (uint32_t)((((r0 + a_row) * FSH) + kk * 8 + a_cw) << 2));

    float o[8][4];
#pragma unroll
    for (int nj = 0; nj < 8; nj++)
#pragma unroll
        for (int f = 0; f < 4; f++) o[nj][f] = 0.0f;
    float mrow0 = -1e30f, mrow1 = -1e30f;
    float lrow0 = 0.0f,  lrow1 = 0.0f;

    const int qi0 = qt * 64 + r0 + g;
    const int qi1 = qi0 + 8;
    const int nkt = qt + 1;

    for (int kt = 0; kt < nkt; kt++) {
        cp_wait<0>();
        __syncthreads();
        if (kt + 1 < nkt) load_tile(kt + 1, (kt + 1) & 1);

        const uint32_t Ksb = smbase + (uint32_t)(((64 + (kt & 1) * 128) * FSH) << 2);
        const uint32_t Vsb = Ksb + (uint32_t)((64 * FSH) << 2);

        // ---- S = Q K^T ----
        float sacc[8][4];
#pragma unroll
        for (int nj = 0; nj < 8; nj++)
#pragma unroll
            for (int f = 0; f < 4; f++) sacc[nj][f] = 0.0f;

#pragma unroll
        for (int kk = 0; kk < 4; kk++) {
#pragma unroll
            for (int njp = 0; njp < 4; njp++) {
                uint32_t b0, b1, b2, b3;
                ldsm_x4(b0, b1, b2, b3,
                        Ksb + (uint32_t)((((njp * 16 + b_row) * FSH) + kk * 8 + b_cw) << 2));
                uint32_t bb0[2] = { b0, b1 };
                uint32_t bb1[2] = { b2, b3 };
                mma_f16_16x8x16(sacc[2 * njp],     qf[kk], bb0, sacc[2 * njp]);
                mma_f16_16x8x16(sacc[2 * njp + 1], qf[kk], bb1, sacc[2 * njp + 1]);
            }
        }

        // ---- scale, causal, additive mask ----
        float tmax0 = -1e30f, tmax1 = -1e30f;
#pragma unroll
        for (int nj = 0; nj < 8; nj++) {
            int kj = kt * 64 + nj * 8 + tig * 2;
            float am0 = amask[b * S_LEN + kj];
            float am1 = amask[b * S_LEN + kj + 1];
            float s0 = ((kj     <= qi0) ? sacc[nj][0] * 0.125f : IGNORE_VAL) + am0;
            float s1 = ((kj + 1 <= qi0) ? sacc[nj][1] * 0.125f : IGNORE_VAL) + am1;
            float s2 = ((kj     <= qi1) ? sacc[nj][2] * 0.125f : IGNORE_VAL) + am0;
            float s3 = ((kj + 1 <= qi1) ? sacc[nj][3] * 0.125f : IGNORE_VAL) + am1;
            sacc[nj][0] = s0; sacc[nj][1] = s1; sacc[nj][2] = s2; sacc[nj][3] = s3;
            tmax0 = fmaxf(tmax0, fmaxf(s0, s1));
            tmax1 = fmaxf(tmax1, fmaxf(s2, s3));
        }
        tmax0 = fmaxf(tmax0, __shfl_xor_sync(0xffffffffu, tmax0, 1));
        tmax0 = fmaxf(tmax0, __shfl_xor_sync(0xffffffffu, tmax0, 2));
        tmax1 = fmaxf(tmax1, __shfl_xor_sync(0xffffffffu, tmax1, 1));
        tmax1 = fmaxf(tmax1, __shfl_xor_sync(0xffffffffu, tmax1, 2));

        float mn0 = fmaxf(mrow0, tmax0);
        float mn1 = fmaxf(mrow1, tmax1);
        float alpha0 = __expf(mrow0 - mn0);
        float alpha1 = __expf(mrow1 - mn1);
        mrow0 = mn0; mrow1 = mn1;

        float rs0 = 0.0f, rs1 = 0.0f;
#pragma unroll
        for (int nj = 0; nj < 8; nj++) {
            float p0 = __expf(sacc[nj][0] - mn0);
            float p1 = __expf(sacc[nj][1] - mn0);
            float p2 = __expf(sacc[nj][2] - mn1);
            float p3 = __expf(sacc[nj][3] - mn1);
            sacc[nj][0] = p0; sacc[nj][1] = p1; sacc[nj][2] = p2; sacc[nj][3] = p3;
            rs0 += p0 + p1;
            rs1 += p2 + p3;
        }
        rs0 += __shfl_xor_sync(0xffffffffu, rs0, 1);
        rs0 += __shfl_xor_sync(0xffffffffu, rs0, 2);
        rs1 += __shfl_xor_sync(0xffffffffu, rs1, 1);
        rs1 += __shfl_xor_sync(0xffffffffu, rs1, 2);
        lrow0 = lrow0 * alpha0 + rs0;
        lrow1 = lrow1 * alpha1 + rs1;

#pragma unroll
        for (int nj = 0; nj < 8; nj++) {
            o[nj][0] *= alpha0; o[nj][1] *= alpha0;
            o[nj][2] *= alpha1; o[nj][3] *= alpha1;
        }

        // ---- O += P V ----
#pragma unroll
        for (int kk = 0; kk < 4; kk++) {
            uint32_t a[4];
            a[0] = pack_h2(sacc[2 * kk][0],     sacc[2 * kk][1]);
            a[1] = pack_h2(sacc[2 * kk][2],     sacc[2 * kk][3]);
            a[2] = pack_h2(sacc[2 * kk + 1][0], sacc[2 * kk + 1][1]);
            a[3] = pack_h2(sacc[2 * kk + 1][2], sacc[2 * kk + 1][3]);
#pragma unroll
            for (int njp = 0; njp < 4; njp++) {
                uint32_t b0, b1, b2, b3;
                ldsm_x4_trans(b0, b1, b2, b3,
                    Vsb + (uint32_t)((((kk * 16 + v_row) * FSH) << 2)
                                     + njp * 32 + v_cb));
                uint32_t bb0[2] = { b0, b1 };
                uint32_t bb1[2] = { b2, b3 };
                mma_f16_16x8x16(o[2 * njp],     a, bb0, o[2 * njp]);
                mma_f16_16x8x16(o[2 * njp + 1], a, bb1, o[2 * njp + 1]);
            }
        }
    }

    // ---- epilogue ----
    float inv0 = 1.0f / lrow0;
    float inv1 = 1.0f / lrow1;
    const size_t row0 = base + qt * 64 + r0 + g;
#pragma unroll
    for (int nj = 0; nj < 8; nj++) {
        int col = h * 64 + nj * 8 + tig * 2;
        *(uint32_t*)(z + row0 * DMODEL + col) =
            pack_h2(o[nj][0] * inv0, o[nj][1] * inv0);
        *(uint32_t*)(z + (row0 + 8) * DMODEL + col) =
            pack_h2(o[nj][2] * inv1, o[nj][3] * inv1);
    }
}

// ---------------- launch ----------------
extern "C" void kernel_launch(void* const* d_in, const int* in_sizes, int n_in,
                              void* d_out, int out_size)
{
    const float* x_q  = (const float*)d_in[0];
    const float* x_k  = (const float*)d_in[1];
    const float* x_v  = (const float*)d_in[2];
    const float* amsk = (const float*)d_in[3];
    const float* w_q  = (const float*)d_in[4];
    const float* w_k  = (const float*)d_in[5];
    const float* w_v  = (const float*)d_in[6];
    const float* w_o  = (const float*)d_in[7];
    const float* b_q  = (const float*)d_in[8];
    const float* b_k  = (const float*)d_in[9];
    const float* b_v  = (const float*)d_in[10];
    const float* b_o  = (const float*)d_in[11];
    float* out = (float*)d_out;

    __half *hxq, *hxk, *hxv, *hwq, *hwk, *hwv, *hwo, *hq, *hk, *hv, *hz;
    cudaGetSymbolAddress((void**)&hxq, g_hxq);
    cudaGetSymbolAddress((void**)&hxk, g_hxk);
    cudaGetSymbolAddress((void**)&hxv, g_hxv);
    cudaGetSymbolAddress((void**)&hwq, g_hwq);
    cudaGetSymbolAddress((void**)&hwk, g_hwk);
    cudaGetSymbolAddress((void**)&hwv, g_hwv);
    cudaGetSymbolAddress((void**)&hwo, g_hwo);
    cudaGetSymbolAddress((void**)&hq,  g_hq);
    cudaGetSymbolAddress((void**)&hk,  g_hk);
    cudaGetSymbolAddress((void**)&hv,  g_hv);
    cudaGetSymbolAddress((void**)&hz,  g_hz);

    cudaFuncSetAttribute(flash_attn_h, cudaFuncAttributeMaxDynamicSharedMemorySize, FL_SMEM);
    cudaFuncSetAttribute(qkv_gemm, cudaFuncAttributeMaxDynamicSharedMemorySize, GEMM_SMEM);
    cudaFuncSetAttribute(wo_gemm, cudaFuncAttributeMaxDynamicSharedMemorySize, GEMM_SMEM);

    // merged conversions: 12288 + 768 + 256 = 13312 blocks
    conv_all<<<13312, 256>>>(x_q, x_k, x_v, w_q, w_k, w_v, w_o,
                             hxq, hxk, hxv, hwq, hwk, hwv, hwo);

    // QKV projections
    dim3 qgrid(DMODEL / 128, MROWS / 128, 3);
    qkv_gemm<<<qgrid, 256, GEMM_SMEM>>>(hxq, hxk, hxv, hwq, hwk, hwv,
                                        b_q, b_k, b_v, hq, hk, hv);

    // flash attention
    dim3 fgrid(S_LEN / 64, NHEADS, BATCH);   // (32, 16, 2)
    flash_attn_h<<<fgrid, 128, FL_SMEM>>>(hq, hk, hv, amsk, hz);

    // output projection
    dim3 ogrid(DMODEL / 128, MROWS / 128);
    wo_gemm<<<ogrid, 256, GEMM_SMEM>>>(hz, hwo, b_o, out);

    (void)in_sizes; (void)n_in; (void)out_size;
}

// round 17
// speedup vs baseline: 2.6849x; 1.0415x over previous
#include <cuda_runtime.h>
#include <cuda_fp16.h>
#include <cstdint>
#include <math.h>

#define S_LEN   2048
#define BATCH   2
#define DMODEL  1024
#define NHEADS  16
#define DHEAD   64
#define MROWS   (BATCH * S_LEN)   // 4096
#define IGNORE_VAL (-100000.0f)

// ---------------- scratch (half everywhere) ----------------
__device__ __half g_hxq[MROWS * DMODEL];
__device__ __half g_hxk[MROWS * DMODEL];
__device__ __half g_hxv[MROWS * DMODEL];
__device__ __half g_hwq[DMODEL * DMODEL];   // [n][k]
__device__ __half g_hwk[DMODEL * DMODEL];
__device__ __half g_hwv[DMODEL * DMODEL];
__device__ __half g_hwo[DMODEL * DMODEL];   // [n][k]
__device__ __half g_hq[MROWS * DMODEL];
__device__ __half g_hk[MROWS * DMODEL];
__device__ __half g_hv[MROWS * DMODEL];
__device__ __half g_hz[MROWS * DMODEL];

// ---------------- helpers ----------------
__device__ __forceinline__ uint32_t smem_u32(const void* p) {
    uint32_t a;
    asm("{ .reg .u64 t; cvta.to.shared.u64 t, %1; cvt.u32.u64 %0, t; }" : "=r"(a) : "l"(p));
    return a;
}
__device__ __forceinline__ uint32_t pack_h2(float a, float b) {
    __half2 h = __float22half2_rn(make_float2(a, b));
    return *reinterpret_cast<uint32_t*>(&h);
}
__device__ __forceinline__ void cp_async16(uint32_t dst, const void* src) {
    asm volatile("cp.async.cg.shared.global [%0], [%1], 16;" :: "r"(dst), "l"(src));
}
__device__ __forceinline__ void cp_commit() {
    asm volatile("cp.async.commit_group;" ::: "memory");
}
template <int N>
__device__ __forceinline__ void cp_wait() {
    asm volatile("cp.async.wait_group %0;" :: "n"(N) : "memory");
}
__device__ __forceinline__ void ldsm_x4(uint32_t& r0, uint32_t& r1, uint32_t& r2, uint32_t& r3,
                                        uint32_t addr) {
    asm volatile("ldmatrix.sync.aligned.m8n8.x4.shared.b16 {%0,%1,%2,%3}, [%4];"
        : "=r"(r0), "=r"(r1), "=r"(r2), "=r"(r3) : "r"(addr));
}
__device__ __forceinline__ void ldsm_x4_trans(uint32_t& r0, uint32_t& r1, uint32_t& r2, uint32_t& r3,
                                              uint32_t addr) {
    asm volatile("ldmatrix.sync.aligned.m8n8.x4.trans.shared.b16 {%0,%1,%2,%3}, [%4];"
        : "=r"(r0), "=r"(r1), "=r"(r2), "=r"(r3) : "r"(addr));
}
__device__ __forceinline__ void mma_f16_16x8x16(
    float* d, const uint32_t* a, const uint32_t* b, const float* c)
{
    asm volatile(
        "mma.sync.aligned.m16n8k16.row.col.f32.f16.f16.f32 "
        "{%0,%1,%2,%3}, {%4,%5,%6,%7}, {%8,%9}, {%10,%11,%12,%13};\n"
        : "=f"(d[0]), "=f"(d[1]), "=f"(d[2]), "=f"(d[3])
        : "r"(a[0]), "r"(a[1]), "r"(a[2]), "r"(a[3]),
          "r"(b[0]), "r"(b[1]),
          "f"(c[0]), "f"(c[1]), "f"(c[2]), "f"(c[3]));
}

// ================= merged conversion kernel (unchanged R16) =================
__global__ void conv_all(
    const float* __restrict__ xq, const float* __restrict__ xk, const float* __restrict__ xv,
    const float* __restrict__ wq, const float* __restrict__ wk, const float* __restrict__ wv,
    const float* __restrict__ wo,
    __half* __restrict__ hxq, __half* __restrict__ hxk, __half* __restrict__ hxv,
    __half* __restrict__ hwq, __half* __restrict__ hwk, __half* __restrict__ hwv,
    __half* __restrict__ hwo)
{
    __shared__ float s[64][65];
    const int bid = blockIdx.x;
    const int tid = threadIdx.x;

    if (bid < 12288) {
        const int which = bid >> 12;
        const int xb    = bid & 4095;
        const float* src = (which == 0) ? xq : (which == 1) ? xk : xv;
        __half* dst = (which == 0) ? hxq : (which == 1) ? hxk : hxv;
        int idx = xb * 256 + tid;
        float4 v = *(const float4*)(src + (size_t)idx * 4);
        uint32_t* d = (uint32_t*)(dst + (size_t)idx * 4);
        d[0] = pack_h2(v.x, v.y);
        d[1] = pack_h2(v.z, v.w);
    } else if (bid < 13056) {
        const int j  = bid - 12288;
        const int z  = j >> 8;
        const int rem = j & 255;
        const int h  = rem >> 4;
        const int k0 = (rem & 15) * 64;
        const float* W = (z == 0) ? wq : (z == 1) ? wk : wv;
        __half* hw = (z == 0) ? hwq : (z == 1) ? hwk : hwv;
#pragma unroll
        for (int it = 0; it < 4; it++) {
            int idx = tid + it * 256;
            int kk = idx >> 4, d4 = (idx & 15) * 4;
            float4 v = *(const float4*)(W + (size_t)h * DMODEL * DHEAD + (size_t)(k0 + kk) * DHEAD + d4);
            s[kk][d4 + 0] = v.x; s[kk][d4 + 1] = v.y;
            s[kk][d4 + 2] = v.z; s[kk][d4 + 3] = v.w;
        }
        __syncthreads();
        int d = tid >> 2, seg = (tid & 3) * 16;
        uint32_t* dst = (uint32_t*)(hw + (size_t)(h * 64 + d) * DMODEL + k0 + seg);
#pragma unroll
        for (int jj = 0; jj < 8; jj++)
            dst[jj] = pack_h2(s[seg + 2 * jj][d], s[seg + 2 * jj + 1][d]);
    } else {
        const int j  = bid - 13056;
        const int k0 = (j & 15) * 64;
        const int n0 = (j >> 4) * 64;
#pragma unroll
        for (int it = 0; it < 4; it++) {
            int idx = tid + it * 256;
            int kk = idx >> 4, n4 = (idx & 15) * 4;
            float4 v = *(const float4*)(wo + (size_t)(k0 + kk) * DMODEL + n0 + n4);
            s[kk][n4 + 0] = v.x; s[kk][n4 + 1] = v.y;
            s[kk][n4 + 2] = v.z; s[kk][n4 + 3] = v.w;
        }
        __syncthreads();
        int n = tid >> 2, seg = (tid & 3) * 16;
        uint32_t* dst = (uint32_t*)(hwo + (size_t)(n0 + n) * DMODEL + k0 + seg);
#pragma unroll
        for (int jj = 0; jj < 8; jj++)
            dst[jj] = pack_h2(s[seg + 2 * jj][n], s[seg + 2 * jj + 1][n]);
    }
}

// ============ half GEMM: 3-stage cp.async ring + ldmatrix (unchanged) ============
#define TSg 36
#define GEMM_SMEM (6 * 128 * TSg * 4)   // 110,592 B

__device__ __forceinline__ void gemm_pipe(
    const __half* __restrict__ A, const __half* __restrict__ B,
    uint32_t* smg, int n0, int m0, float acc[4][4][4])
{
    const int tid = threadIdx.x;
    const int wid = tid >> 5;
    const int lid = tid & 31;
    const int wm  = wid >> 2;
    const int wn  = wid & 3;

    uint32_t stA[3], stB[3];
#pragma unroll
    for (int s = 0; s < 3; s++) {
        stA[s] = smem_u32(smg + s * 256 * TSg);
        stB[s] = stA[s] + 128 * TSg * 4;
    }

#pragma unroll
    for (int i = 0; i < 4; i++)
#pragma unroll
        for (int j = 0; j < 4; j++)
#pragma unroll
            for (int f = 0; f < 4; f++) acc[i][j][f] = 0.0f;

    auto load_chunk = [&](int c, int s) {
        const int k0 = c * 64;
        const uint32_t aA = stA[s], aB = stB[s];
#pragma unroll
        for (int it = 0; it < 4; it++) {
            int i = tid + it * 256;
            int row = i >> 3, j = i & 7;
            cp_async16(aA + (uint32_t)((row * TSg + j * 4) << 2),
                       A + (size_t)(m0 + row) * DMODEL + k0 + j * 8);
            cp_async16(aB + (uint32_t)((row * TSg + j * 4) << 2),
                       B + (size_t)(n0 + row) * DMODEL + k0 + j * 8);
        }
        cp_commit();
    };

    const int m8   = lid >> 3;
    const int a_row = (lid & 7) + (m8 & 1) * 8;
    const int a_cw  = (m8 >> 1) * 4;
    const int b_row = (lid & 7) + (m8 >> 1) * 8;
    const int b_cw  = (m8 & 1) * 4;

    load_chunk(0, 0);
    load_chunk(1, 1);

    const int NCH = DMODEL / 64;   // 16
    for (int c = 0; c < NCH; c++) {
        cp_wait<1>();
        __syncthreads();
        if (c + 2 < NCH) load_chunk(c + 2, (c + 2) % 3);

        const int s = c % 3;
        const uint32_t aA = stA[s], aB = stB[s];
#pragma unroll
        for (int kk = 0; kk < 4; kk++) {
            uint32_t af[4][4], bf[4][2];
#pragma unroll
            for (int mi = 0; mi < 4; mi++) {
                uint32_t addr = aA + (uint32_t)((((wm * 64 + mi * 16 + a_row) * TSg)
                                                + kk * 8 + a_cw) << 2);
                ldsm_x4(af[mi][0], af[mi][1], af[mi][2], af[mi][3], addr);
            }
#pragma unroll
            for (int njp = 0; njp < 2; njp++) {
                uint32_t addr = aB + (uint32_t)((((wn * 32 + njp * 16 + b_row) * TSg)
                                                + kk * 8 + b_cw) << 2);
                ldsm_x4(bf[2 * njp][0], bf[2 * njp][1],
                        bf[2 * njp + 1][0], bf[2 * njp + 1][1], addr);
            }
#pragma unroll
            for (int mi = 0; mi < 4; mi++)
#pragma unroll
                for (int nj = 0; nj < 4; nj++)
                    mma_f16_16x8x16(acc[mi][nj], af[mi], bf[nj], acc[mi][nj]);
        }
    }
}

__global__ __launch_bounds__(256, 2) void qkv_gemm(
    const __half* __restrict__ xq, const __half* __restrict__ xk, const __half* __restrict__ xv,
    const __half* __restrict__ wq, const __half* __restrict__ wk, const __half* __restrict__ wv,
    const float* __restrict__ bq, const float* __restrict__ bk, const float* __restrict__ bv,
    __half* __restrict__ cq, __half* __restrict__ ck, __half* __restrict__ cv)
{
    extern __shared__ uint32_t smg[];
    const __half* A = (blockIdx.z == 0) ? xq : (blockIdx.z == 1) ? xk : xv;
    const __half* B = (blockIdx.z == 0) ? wq : (blockIdx.z == 1) ? wk : wv;
    const float* bias = (blockIdx.z == 0) ? bq : (blockIdx.z == 1) ? bk : bv;
    __half*      C = (blockIdx.z == 0) ? cq : (blockIdx.z == 1) ? ck : cv;
    const int n0 = blockIdx.x * 128, m0 = blockIdx.y * 128;

    float acc[4][4][4];
    gemm_pipe(A, B, smg, n0, m0, acc);

    const int lid = threadIdx.x & 31;
    const int g = lid >> 2, tig = lid & 3;
    const int wm = (threadIdx.x >> 5) >> 2, wn = (threadIdx.x >> 5) & 3;
#pragma unroll
    for (int mi = 0; mi < 4; mi++) {
        int r0 = m0 + wm * 64 + mi * 16 + g;
#pragma unroll
        for (int nj = 0; nj < 4; nj++) {
            int c0 = n0 + wn * 32 + nj * 8 + tig * 2;
            float b0 = bias[c0], b1 = bias[c0 + 1];
            *(uint32_t*)(C + (size_t)r0 * DMODEL + c0) =
                pack_h2(acc[mi][nj][0] + b0, acc[mi][nj][1] + b1);
            *(uint32_t*)(C + (size_t)(r0 + 8) * DMODEL + c0) =
                pack_h2(acc[mi][nj][2] + b0, acc[mi][nj][3] + b1);
        }
    }
}

__global__ __launch_bounds__(256, 2) void wo_gemm(
    const __half* __restrict__ A, const __half* __restrict__ B,
    const float* __restrict__ bias, float* __restrict__ C)
{
    extern __shared__ uint32_t smg[];
    const int n0 = blockIdx.x * 128, m0 = blockIdx.y * 128;

    float acc[4][4][4];
    gemm_pipe(A, B, smg, n0, m0, acc);

    const int lid = threadIdx.x & 31;
    const int g = lid >> 2, tig = lid & 3;
    const int wm = (threadIdx.x >> 5) >> 2, wn = (threadIdx.x >> 5) & 3;
#pragma unroll
    for (int mi = 0; mi < 4; mi++) {
        int r0 = m0 + wm * 64 + mi * 16 + g;
#pragma unroll
        for (int nj = 0; nj < 4; nj++) {
            int c0 = n0 + wn * 32 + nj * 8 + tig * 2;
            float b0 = bias[c0], b1 = bias[c0 + 1];
            *(float2*)(C + (size_t)r0 * DMODEL + c0) =
                make_float2(acc[mi][nj][0] + b0, acc[mi][nj][1] + b1);
            *(float2*)(C + (size_t)(r0 + 8) * DMODEL + c0) =
                make_float2(acc[mi][nj][2] + b0, acc[mi][nj][3] + b1);
        }
    }
}

// ============ flash attention: paired Q-tiles (perfect load balance) ============
// Grid (16, 16, 2): CTA bx processes Q-tile 31-bx then bx -> every CTA = 33 iters.
// smem (words, stride FSH=36): Q[0,64) | K0[64,128) | V0[128,192) | K1[192,256) | V1[256,320)
#define FSH 36
#define FL_SMEM (320 * FSH * 4)   // 46,080 B

__global__ __launch_bounds__(128, 4) void flash_attn_h(
    const __half* __restrict__ q, const __half* __restrict__ k,
    const __half* __restrict__ v, const float* __restrict__ amask,
    __half* __restrict__ z)
{
    extern __shared__ uint32_t sm[];
    uint32_t* Qs = sm;                   // 64 x FSH

    const int h  = blockIdx.y;
    const int b  = blockIdx.z;
    const int tid = threadIdx.x;
    const int lid = tid & 31;
    const int g   = lid >> 2;
    const int tig = lid & 3;
    const int r0  = (tid >> 5) * 16;

    const uint32_t smbase = smem_u32(sm);

    const int m8    = lid >> 3;
    const int a_row = (lid & 7) + (m8 & 1) * 8;
    const int a_cw  = (m8 >> 1) * 4;
    const int b_row = (lid & 7) + (m8 >> 1) * 8;
    const int b_cw  = (m8 & 1) * 4;
    const int v_row = (lid & 7) + (m8 & 1) * 8;
    const int v_cb  = (m8 >> 1) * 16;

    const size_t base = (size_t)b * S_LEN;
    const int NT = (int)gridDim.x * 2;   // 32 q-tiles total

    auto load_tile = [&](int kt, int buf) {
        const __half* kp = k + (base + kt * 64) * DMODEL + h * 64;
        const __half* vp = v + (base + kt * 64) * DMODEL + h * 64;
        const uint32_t Kb = smbase + (uint32_t)(((64 + buf * 128) * FSH) << 2);
        const uint32_t Vb = Kb + (uint32_t)((64 * FSH) << 2);
#pragma unroll
        for (int it = 0; it < 4; it++) {
            int i = tid + it * 128;
            int row = i >> 3, j = i & 7;
            cp_async16(Kb + (uint32_t)((row * FSH + j * 4) << 2),
                       kp + (size_t)row * DMODEL + j * 8);
            cp_async16(Vb + (uint32_t)((row * FSH + j * 4) << 2),
                       vp + (size_t)row * DMODEL + j * 8);
        }
        cp_commit();
    };

#pragma unroll 1
    for (int pass = 0; pass < 2; pass++) {
        const int qt = (pass == 0) ? (NT - 1 - (int)blockIdx.x) : (int)blockIdx.x;

        __syncthreads();   // all readers of K/V buffers from prior pass done
        load_tile(0, 0);

        // Q tile: 64 rows x 64 halfs
        const __half* qp = q + (base + qt * 64) * DMODEL + h * 64;
#pragma unroll
        for (int it = 0; it < 4; it++) {
            int i = tid + it * 128;
            int row = i >> 3, j = i & 7;
            *(uint4*)(Qs + row * FSH + j * 4) =
                *(const uint4*)((const char*)(qp + (size_t)row * DMODEL) + j * 16);
        }
        __syncthreads();   // Q visible

        uint32_t qf[4][4];
#pragma unroll
        for (int kk = 0; kk < 4; kk++)
            ldsm_x4(qf[kk][0], qf[kk][1], qf[kk][2], qf[kk][3],
                    smbase + (uint32_t)((((r0 + a_row) * FSH) + kk * 8 + a_cw) << 2));

        float o[8][4];
#pragma unroll
        for (int nj = 0; nj < 8; nj++)
#pragma unroll
            for (int f = 0; f < 4; f++) o[nj][f] = 0.0f;
        float mrow0 = -1e30f, mrow1 = -1e30f;
        float lrow0 = 0.0f,  lrow1 = 0.0f;

        const int qi0 = qt * 64 + r0 + g;
        const int qi1 = qi0 + 8;
        const int nkt = qt + 1;

        for (int kt = 0; kt < nkt; kt++) {
            cp_wait<0>();
            __syncthreads();
            if (kt + 1 < nkt) load_tile(kt + 1, (kt + 1) & 1);

            const uint32_t Ksb = smbase + (uint32_t)(((64 + (kt & 1) * 128) * FSH) << 2);
            const uint32_t Vsb = Ksb + (uint32_t)((64 * FSH) << 2);

            // ---- S = Q K^T ----
            float sacc[8][4];
#pragma unroll
            for (int nj = 0; nj < 8; nj++)
#pragma unroll
                for (int f = 0; f < 4; f++) sacc[nj][f] = 0.0f;

#pragma unroll
            for (int kk = 0; kk < 4; kk++) {
#pragma unroll
                for (int njp = 0; njp < 4; njp++) {
                    uint32_t b0, b1, b2, b3;
                    ldsm_x4(b0, b1, b2, b3,
                            Ksb + (uint32_t)((((njp * 16 + b_row) * FSH) + kk * 8 + b_cw) << 2));
                    uint32_t bb0[2] = { b0, b1 };
                    uint32_t bb1[2] = { b2, b3 };
                    mma_f16_16x8x16(sacc[2 * njp],     qf[kk], bb0, sacc[2 * njp]);
                    mma_f16_16x8x16(sacc[2 * njp + 1], qf[kk], bb1, sacc[2 * njp + 1]);
                }
            }

            // ---- scale, causal, additive mask ----
            float tmax0 = -1e30f, tmax1 = -1e30f;
#pragma unroll
            for (int nj = 0; nj < 8; nj++) {
                int kj = kt * 64 + nj * 8 + tig * 2;
                float am0 = amask[b * S_LEN + kj];
                float am1 = amask[b * S_LEN + kj + 1];
                float s0 = ((kj     <= qi0) ? sacc[nj][0] * 0.125f : IGNORE_VAL) + am0;
                float s1 = ((kj + 1 <= qi0) ? sacc[nj][1] * 0.125f : IGNORE_VAL) + am1;
                float s2 = ((kj     <= qi1) ? sacc[nj][2] * 0.125f : IGNORE_VAL) + am0;
                float s3 = ((kj + 1 <= qi1) ? sacc[nj][3] * 0.125f : IGNORE_VAL) + am1;
                sacc[nj][0] = s0; sacc[nj][1] = s1; sacc[nj][2] = s2; sacc[nj][3] = s3;
                tmax0 = fmaxf(tmax0, fmaxf(s0, s1));
                tmax1 = fmaxf(tmax1, fmaxf(s2, s3));
            }
            tmax0 = fmaxf(tmax0, __shfl_xor_sync(0xffffffffu, tmax0, 1));
            tmax0 = fmaxf(tmax0, __shfl_xor_sync(0xffffffffu, tmax0, 2));
            tmax1 = fmaxf(tmax1, __shfl_xor_sync(0xffffffffu, tmax1, 1));
            tmax1 = fmaxf(tmax1, __shfl_xor_sync(0xffffffffu, tmax1, 2));

            float mn0 = fmaxf(mrow0, tmax0);
            float mn1 = fmaxf(mrow1, tmax1);
            float alpha0 = __expf(mrow0 - mn0);
            float alpha1 = __expf(mrow1 - mn1);
            mrow0 = mn0; mrow1 = mn1;

            float rs0 = 0.0f, rs1 = 0.0f;
#pragma unroll
            for (int nj = 0; nj < 8; nj++) {
                float p0 = __expf(sacc[nj][0] - mn0);
                float p1 = __expf(sacc[nj][1] - mn0);
                float p2 = __expf(sacc[nj][2] - mn1);
                float p3 = __expf(sacc[nj][3] - mn1);
                sacc[nj][0] = p0; sacc[nj][1] = p1; sacc[nj][2] = p2; sacc[nj][3] = p3;
                rs0 += p0 + p1;
                rs1 += p2 + p3;
            }
            rs0 += __shfl_xor_sync(0xffffffffu, rs0, 1);
            rs0 += __shfl_xor_sync(0xffffffffu, rs0, 2);
            rs1 += __shfl_xor_sync(0xffffffffu, rs1, 1);
            rs1 += __shfl_xor_sync(0xffffffffu, rs1, 2);
            lrow0 = lrow0 * alpha0 + rs0;
            lrow1 = lrow1 * alpha1 + rs1;

#pragma unroll
            for (int nj = 0; nj < 8; nj++) {
                o[nj][0] *= alpha0; o[nj][1] *= alpha0;
                o[nj][2] *= alpha1; o[nj][3] *= alpha1;
            }

            // ---- O += P V ----
#pragma unroll
            for (int kk = 0; kk < 4; kk++) {
                uint32_t a[4];
                a[0] = pack_h2(sacc[2 * kk][0],     sacc[2 * kk][1]);
                a[1] = pack_h2(sacc[2 * kk][2],     sacc[2 * kk][3]);
                a[2] = pack_h2(sacc[2 * kk + 1][0], sacc[2 * kk + 1][1]);
                a[3] = pack_h2(sacc[2 * kk + 1][2], sacc[2 * kk + 1][3]);
#pragma unroll
                for (int njp = 0; njp < 4; njp++) {
                    uint32_t b0, b1, b2, b3;
                    ldsm_x4_trans(b0, b1, b2, b3,
                        Vsb + (uint32_t)((((kk * 16 + v_row) * FSH) << 2)
                                         + njp * 32 + v_cb));
                    uint32_t bb0[2] = { b0, b1 };
                    uint32_t bb1[2] = { b2, b3 };
                    mma_f16_16x8x16(o[2 * njp],     a, bb0, o[2 * njp]);
                    mma_f16_16x8x16(o[2 * njp + 1], a, bb1, o[2 * njp + 1]);
                }
            }
        }

        // ---- epilogue ----
        float inv0 = 1.0f / lrow0;
        float inv1 = 1.0f / lrow1;
        const size_t row0 = base + qt * 64 + r0 + g;
#pragma unroll
        for (int nj = 0; nj < 8; nj++) {
            int col = h * 64 + nj * 8 + tig * 2;
            *(uint32_t*)(z + row0 * DMODEL + col) =
                pack_h2(o[nj][0] * inv0, o[nj][1] * inv0);
            *(uint32_t*)(z + (row0 + 8) * DMODEL + col) =
                pack_h2(o[nj][2] * inv1, o[nj][3] * inv1);
        }
    }
}

// ---------------- launch ----------------
extern "C" void kernel_launch(void* const* d_in, const int* in_sizes, int n_in,
                              void* d_out, int out_size)
{
    const float* x_q  = (const float*)d_in[0];
    const float* x_k  = (const float*)d_in[1];
    const float* x_v  = (const float*)d_in[2];
    const float* amsk = (const float*)d_in[3];
    const float* w_q  = (const float*)d_in[4];
    const float* w_k  = (const float*)d_in[5];
    const float* w_v  = (const float*)d_in[6];
    const float* w_o  = (const float*)d_in[7];
    const float* b_q  = (const float*)d_in[8];
    const float* b_k  = (const float*)d_in[9];
    const float* b_v  = (const float*)d_in[10];
    const float* b_o  = (const float*)d_in[11];
    float* out = (float*)d_out;

    __half *hxq, *hxk, *hxv, *hwq, *hwk, *hwv, *hwo, *hq, *hk, *hv, *hz;
    cudaGetSymbolAddress((void**)&hxq, g_hxq);
    cudaGetSymbolAddress((void**)&hxk, g_hxk);
    cudaGetSymbolAddress((void**)&hxv, g_hxv);
    cudaGetSymbolAddress((void**)&hwq, g_hwq);
    cudaGetSymbolAddress((void**)&hwk, g_hwk);
    cudaGetSymbolAddress((void**)&hwv, g_hwv);
    cudaGetSymbolAddress((void**)&hwo, g_hwo);
    cudaGetSymbolAddress((void**)&hq,  g_hq);
    cudaGetSymbolAddress((void**)&hk,  g_hk);
    cudaGetSymbolAddress((void**)&hv,  g_hv);
    cudaGetSymbolAddress((void**)&hz,  g_hz);

    cudaFuncSetAttribute(flash_attn_h, cudaFuncAttributeMaxDynamicSharedMemorySize, FL_SMEM);
    cudaFuncSetAttribute(qkv_gemm, cudaFuncAttributeMaxDynamicSharedMemorySize, GEMM_SMEM);
    cudaFuncSetAttribute(wo_gemm, cudaFuncAttributeMaxDynamicSharedMemorySize, GEMM_SMEM);

    // merged conversions
    conv_all<<<13312, 256>>>(x_q, x_k, x_v, w_q, w_k, w_v, w_o,
                             hxq, hxk, hxv, hwq, hwk, hwv, hwo);

    // QKV projections
    dim3 qgrid(DMODEL / 128, MROWS / 128, 3);
    qkv_gemm<<<qgrid, 256, GEMM_SMEM>>>(hxq, hxk, hxv, hwq, hwk, hwv,
                                        b_q, b_k, b_v, hq, hk, hv);

    // flash attention: paired tiles, one balanced wave
    dim3 fgrid(S_LEN / 128, NHEADS, BATCH);   // (16, 16, 2) = 512 CTAs
    flash_attn_h<<<fgrid, 128, FL_SMEM>>>(hq, hk, hv, amsk, hz);

    // output projection
    dim3 ogrid(DMODEL / 128, MROWS / 128);
    wo_gemm<<<ogrid, 256, GEMM_SMEM>>>(hz, hwo, b_o, out);

    (void)in_sizes; (void)n_in; (void)out_size;
}